// round 1
// baseline (speedup 1.0000x reference)
#include <cuda_runtime.h>
#include <cuda_bf16.h>
#include <math.h>

// ---------------------------------------------------------------------------
// Problem constants
// ---------------------------------------------------------------------------
#define NB   4        // batch
#define C1   256      // input / output channels
#define CM   128      // cv1 output channels
#define C2   256      // main width
#define HW   4096     // 64*64
#define HH   64
#define WW   64
#define NPIX (NB*HW)  // 16384
#define PP   9        // K*K
#define BN_EPS 1e-5f
#define LN_EPS 1e-6f

// ---------------------------------------------------------------------------
// Scratch (single __device__ global, offsets in floats)
// ---------------------------------------------------------------------------
#define OFF_Y1     0                        // (4,128,64,64) NCHW   2,097,152
#define OFF_Y2     (OFF_Y1 + NB*CM*HW)      // (16384,256)   NHWC   4,194,304
#define OFF_X1     (OFF_Y2 + NPIX*C2)       // (16384,256)          4,194,304
#define OFF_XPROJ  (OFF_X1 + NPIX*C2)       // (16384,256)          4,194,304
#define OFF_OM     (OFF_XPROJ + NPIX*C2)    // (16384,27)             442,368
#define OFF_CORE   (OFF_OM + NPIX*27)       // (16384,256)          4,194,304
#define SCRATCH_FLOATS (OFF_CORE + NPIX*C2)

__device__ __align__(16) float g_scratch[SCRATCH_FLOATS];

__device__ __forceinline__ float silu(float v) { return v / (1.0f + expf(-v)); }

// ---------------------------------------------------------------------------
// Kernel 1: cv1 = 3x3 conv (C1=256 -> CM=128), pad 1, fused BN+SiLU.
// One block per (c_out, n), block computes the full 64x64 plane.
// 256 threads, 4x4 outputs per thread. Input plane staged in SMEM per ci.
// ---------------------------------------------------------------------------
__global__ __launch_bounds__(256) void conv3x3_bnsilu_k(
    const float* __restrict__ x,     // (NB, C1, 64, 64)
    const float* __restrict__ w,     // (CM, C1, 3, 3)
    const float* __restrict__ g,
    const float* __restrict__ b,
    float* __restrict__ out)         // (NB, CM, 64, 64)
{
    __shared__ __align__(16) float xs[66 * 68];  // rows -1..64 (66), stride 68
    __shared__ float ws[9];

    const int c   = blockIdx.x;           // 0..127
    const int n   = blockIdx.y;           // 0..3
    const int tid = threadIdx.x;
    const int tx  = tid & 15;             // column group
    const int ty  = tid >> 4;             // row group

    float acc[16];
#pragma unroll
    for (int i = 0; i < 16; i++) acc[i] = 0.0f;

    for (int ci = 0; ci < C1; ci++) {
        if (tid < 9) ws[tid] = w[((size_t)c * C1 + ci) * 9 + tid];
        const float* xp = x + ((size_t)n * C1 + ci) * HW;
        // stage padded 66x66 plane
        for (int idx = tid; idx < 66 * 66; idx += 256) {
            int r  = idx / 66, cc = idx - r * 66;
            int gr = r - 1,    gc = cc - 1;
            float v = 0.0f;
            if ((unsigned)gr < 64u && (unsigned)gc < 64u) v = xp[gr * 64 + gc];
            xs[r * 68 + cc] = v;
        }
        __syncthreads();

        float xv[6][8];
#pragma unroll
        for (int r = 0; r < 6; r++) {
            float4 a  = *(const float4*)&xs[(ty * 4 + r) * 68 + tx * 4];
            float4 b4 = *(const float4*)&xs[(ty * 4 + r) * 68 + tx * 4 + 4];
            xv[r][0] = a.x;  xv[r][1] = a.y;  xv[r][2] = a.z;  xv[r][3] = a.w;
            xv[r][4] = b4.x; xv[r][5] = b4.y; xv[r][6] = b4.z; xv[r][7] = b4.w;
        }
        float wr[9];
#pragma unroll
        for (int k = 0; k < 9; k++) wr[k] = ws[k];

#pragma unroll
        for (int kh = 0; kh < 3; kh++)
#pragma unroll
            for (int kw = 0; kw < 3; kw++) {
                float wv = wr[kh * 3 + kw];
#pragma unroll
                for (int i = 0; i < 4; i++)
#pragma unroll
                    for (int j = 0; j < 4; j++)
                        acc[i * 4 + j] = fmaf(wv, xv[i + kh][j + kw], acc[i * 4 + j]);
            }
        __syncthreads();
    }

    const float scale = g[c] * rsqrtf(1.0f + BN_EPS);
    const float bias  = b[c];
    float* op = out + ((size_t)n * CM + c) * HW;
#pragma unroll
    for (int i = 0; i < 4; i++)
#pragma unroll
        for (int j = 0; j < 4; j++) {
            float v = fmaf(acc[i * 4 + j], scale, bias);
            op[(ty * 4 + i) * 64 + tx * 4 + j] = silu(v);
        }
}

// ---------------------------------------------------------------------------
// Generic tiled SGEMM: C[M,N] = A * W^T (+bias) with fused epilogues.
//   W is [N][K] row-major (torch Linear weight layout).
//   TRANSA=0: A row-major [M][K] (lda = K).
//   TRANSA=1: A col-major [K][M] (lda = M)   -> used for pw 1x1 conv on NCHW.
// MODE 0: C[(z*M+m)*N + n] = acc + bias[n]
// MODE 1: bn(gamma,beta)+SiLU, write NHWC C[(z*M+m)*N + n]
// MODE 2: +bias, bn(gamma,beta)+SiLU, +residual(NCHW), write NCHW to C
// Tiles: BM=BN=64, BK=16, 256 threads, 4x4 per thread. M,N,K divisible.
// ---------------------------------------------------------------------------
template<int TRANSA, int MODE>
__global__ __launch_bounds__(256) void gemm_k(
    const float* __restrict__ A, const float* __restrict__ W,
    const float* __restrict__ bias,
    const float* __restrict__ gamma, const float* __restrict__ beta,
    const float* __restrict__ res,
    float* __restrict__ C,
    int M, int N, int K, int lda)
{
    __shared__ __align__(16) float As[16][68];
    __shared__ __align__(16) float Bs[16][68];

    const int m0 = blockIdx.x * 64;
    const int n0 = blockIdx.y * 64;
    const int z  = blockIdx.z;
    const float* Ab = A + (TRANSA ? (size_t)z * K * lda : (size_t)z * M * K);

    const int tid = threadIdx.x;
    const int tx  = tid & 15;
    const int ty  = tid >> 4;

    float acc[4][4];
#pragma unroll
    for (int i = 0; i < 4; i++)
#pragma unroll
        for (int j = 0; j < 4; j++) acc[i][j] = 0.0f;

    for (int k0 = 0; k0 < K; k0 += 16) {
        if (TRANSA) {
            int k  = tid >> 4;          // 0..15
            int mm = (tid & 15) * 4;    // 0..60
            float4 a4 = *(const float4*)&Ab[(size_t)(k0 + k) * lda + m0 + mm];
            *(float4*)&As[k][mm] = a4;
        } else {
            int row = tid >> 2;         // 0..63
            int c4  = (tid & 3) * 4;    // 0..12
            float4 a4 = *(const float4*)&Ab[(size_t)(m0 + row) * K + k0 + c4];
            As[c4 + 0][row] = a4.x; As[c4 + 1][row] = a4.y;
            As[c4 + 2][row] = a4.z; As[c4 + 3][row] = a4.w;
        }
        {
            int row = tid >> 2;
            int c4  = (tid & 3) * 4;
            float4 b4 = *(const float4*)&W[(size_t)(n0 + row) * K + k0 + c4];
            Bs[c4 + 0][row] = b4.x; Bs[c4 + 1][row] = b4.y;
            Bs[c4 + 2][row] = b4.z; Bs[c4 + 3][row] = b4.w;
        }
        __syncthreads();

#pragma unroll
        for (int kk = 0; kk < 16; kk++) {
            float4 a = *(const float4*)&As[kk][ty * 4];
            float4 b = *(const float4*)&Bs[kk][tx * 4];
            float av[4] = {a.x, a.y, a.z, a.w};
            float bv[4] = {b.x, b.y, b.z, b.w};
#pragma unroll
            for (int i = 0; i < 4; i++)
#pragma unroll
                for (int j = 0; j < 4; j++)
                    acc[i][j] = fmaf(av[i], bv[j], acc[i][j]);
        }
        __syncthreads();
    }

#pragma unroll
    for (int i = 0; i < 4; i++)
#pragma unroll
        for (int j = 0; j < 4; j++) {
            int m = m0 + ty * 4 + i;
            int n = n0 + tx * 4 + j;
            float v = acc[i][j];
            if (MODE == 0) {
                if (bias) v += bias[n];
                C[((size_t)z * M + m) * N + n] = v;
            } else if (MODE == 1) {
                float s = gamma[n] * rsqrtf(1.0f + BN_EPS);
                v = fmaf(v, s, beta[n]);
                C[((size_t)z * M + m) * N + n] = silu(v);
            } else { // MODE 2: out_proj -> bias -> bn2 -> silu -> +x -> NCHW
                v += bias[n];
                float s = gamma[n] * rsqrtf(1.0f + BN_EPS);
                v = fmaf(v, s, beta[n]);
                v = silu(v);
                int mg   = (int)((size_t)z * M + m);
                int nimg = mg >> 12;
                int hw   = mg & 4095;
                size_t idx = ((size_t)nimg * C2 + n) * HW + hw;
                C[idx] = res[idx] + v;
            }
        }
}

// ---------------------------------------------------------------------------
// Kernel: depthwise 3x3 (on NHWC y2) + bias + LayerNorm(C) + exact GELU.
// One block per pixel, one thread per channel (256).
// ---------------------------------------------------------------------------
__global__ __launch_bounds__(256) void dw_ln_gelu_k(
    const float* __restrict__ y2,    // (NPIX, 256) NHWC
    const float* __restrict__ dww,   // (256,1,3,3)
    const float* __restrict__ dwb,
    const float* __restrict__ lg,
    const float* __restrict__ lb,
    float* __restrict__ x1)          // (NPIX, 256)
{
    const int pix = blockIdx.x;
    const int n = pix >> 12, hw = pix & 4095, h = hw >> 6, w = hw & 63;
    const int c = threadIdx.x;

    float v = dwb[c];
#pragma unroll
    for (int kh = 0; kh < 3; kh++)
#pragma unroll
        for (int kw = 0; kw < 3; kw++) {
            int hh = h + kh - 1, wk = w + kw - 1;
            if ((unsigned)hh < 64u && (unsigned)wk < 64u)
                v = fmaf(y2[(((size_t)n * HW) + hh * 64 + wk) * C2 + c],
                         dww[c * 9 + kh * 3 + kw], v);
        }

    __shared__ float s1[256];
    __shared__ float s2[256];
    s1[c] = v; s2[c] = v * v;
    __syncthreads();
#pragma unroll
    for (int off = 128; off > 0; off >>= 1) {
        if (c < off) { s1[c] += s1[c + off]; s2[c] += s2[c + off]; }
        __syncthreads();
    }
    float mean = s1[0] * (1.0f / 256.0f);
    float var  = s2[0] * (1.0f / 256.0f) - mean * mean;

    float t = fmaf((v - mean) * rsqrtf(var + LN_EPS), lg[c], lb[c]);
    float gelu = 0.5f * t * (1.0f + erff(t * 0.70710678118654752f));
    x1[(size_t)pix * C2 + c] = gelu;
}

// ---------------------------------------------------------------------------
// Kernel: offset (18) + mask (9, softmaxed) heads: small matvec per pixel.
// One block (256 thr = 8 warps) per pixel; warp w handles outputs w, w+8, ...
// ---------------------------------------------------------------------------
__global__ __launch_bounds__(256) void offmask_k(
    const float* __restrict__ x1,
    const float* __restrict__ offw, const float* __restrict__ offb,
    const float* __restrict__ mskw, const float* __restrict__ mskb,
    float* __restrict__ om)          // (NPIX, 27): [0..17]=offset, [18..26]=mask
{
    const int pix = blockIdx.x;
    const int tid = threadIdx.x;
    const int lane = tid & 31, wp = tid >> 5;

    __shared__ float xr[256];
    __shared__ float logits[32];
    xr[tid] = x1[(size_t)pix * C2 + tid];
    __syncthreads();

    for (int j = wp; j < 27; j += 8) {
        const float* wrow = (j < 18) ? (offw + (size_t)j * C2)
                                     : (mskw + (size_t)(j - 18) * C2);
        float s = 0.0f;
#pragma unroll
        for (int t = lane; t < C2; t += 32) s = fmaf(xr[t], wrow[t], s);
#pragma unroll
        for (int o = 16; o > 0; o >>= 1) s += __shfl_down_sync(0xffffffffu, s, o);
        if (lane == 0) logits[j] = s + ((j < 18) ? offb[j] : mskb[j - 18]);
    }
    __syncthreads();

    if (tid < 18) om[(size_t)pix * 27 + tid] = logits[tid];
    if (tid == 0) {
        float mx = -1e30f;
#pragma unroll
        for (int q = 0; q < 9; q++) mx = fmaxf(mx, logits[18 + q]);
        float e[9], sum = 0.0f;
#pragma unroll
        for (int q = 0; q < 9; q++) { e[q] = expf(logits[18 + q] - mx); sum += e[q]; }
        float inv = 1.0f / sum;
#pragma unroll
        for (int q = 0; q < 9; q++) om[(size_t)pix * 27 + 18 + q] = e[q] * inv;
    }
}

// ---------------------------------------------------------------------------
// Kernel: DCNv3 core. One block per pixel, one thread per channel.
// Sampling coords derived analytically (pad=1, stride=1, scale=1, G=1):
//   px = w + (p/3) + off_x(p),  py = h + (p%3) + off_y(p)   [padded 66x66 frame]
// Padded border is zero -> only interior taps (1..64) contribute.
// ---------------------------------------------------------------------------
__global__ __launch_bounds__(256) void dcnv3_k(
    const float* __restrict__ xproj,   // (NPIX, 256) NHWC
    const float* __restrict__ om,      // (NPIX, 27)
    float* __restrict__ core)          // (NPIX, 256)
{
    const int pix = blockIdx.x;
    const int n = pix >> 12, hw = pix & 4095, h = hw >> 6, w = hw & 63;
    const int c = threadIdx.x;

    __shared__ float o[32];
    if (c < 27) o[c] = om[(size_t)pix * 27 + c];
    __syncthreads();

    const float* base = xproj + (size_t)n * HW * C2;
    float acc = 0.0f;

#pragma unroll
    for (int p = 0; p < PP; p++) {
        float px = (float)(w + (p / 3)) + o[2 * p];
        float py = (float)(h + (p % 3)) + o[2 * p + 1];
        float x0f = floorf(px), y0f = floorf(py);
        float fx = px - x0f, fy = py - y0f;
        int x0 = (int)x0f, y0 = (int)y0f;
        float mk = o[18 + p];
        float s = 0.0f;
#pragma unroll
        for (int dy = 0; dy < 2; dy++)
#pragma unroll
            for (int dx = 0; dx < 2; dx++) {
                int xi = x0 + dx, yi = y0 + dy;
                if (xi >= 1 && xi <= 64 && yi >= 1 && yi <= 64) {
                    float wgt = (dx ? fx : 1.0f - fx) * (dy ? fy : 1.0f - fy);
                    s = fmaf(wgt, base[((size_t)(yi - 1) * 64 + (xi - 1)) * C2 + c], s);
                }
            }
        acc = fmaf(mk, s, acc);
    }
    core[(size_t)pix * C2 + c] = acc;
}

// ---------------------------------------------------------------------------
// Launch
// ---------------------------------------------------------------------------
extern "C" void kernel_launch(void* const* d_in, const int* in_sizes, int n_in,
                              void* d_out, int out_size) {
    const float* x     = (const float*)d_in[0];
    const float* cv1_w = (const float*)d_in[1];
    const float* cv1_g = (const float*)d_in[2];
    const float* cv1_b = (const float*)d_in[3];
    const float* pw_w  = (const float*)d_in[4];
    const float* pw_g  = (const float*)d_in[5];
    const float* pw_b  = (const float*)d_in[6];
    const float* dw_w  = (const float*)d_in[7];
    const float* dw_b  = (const float*)d_in[8];
    const float* ln_g  = (const float*)d_in[9];
    const float* ln_b  = (const float*)d_in[10];
    const float* off_w = (const float*)d_in[11];
    const float* off_b = (const float*)d_in[12];
    const float* msk_w = (const float*)d_in[13];
    const float* msk_b = (const float*)d_in[14];
    const float* inp_w = (const float*)d_in[15];
    const float* inp_b = (const float*)d_in[16];
    const float* out_w = (const float*)d_in[17];
    const float* out_b = (const float*)d_in[18];
    const float* bn2_g = (const float*)d_in[19];
    const float* bn2_b = (const float*)d_in[20];

    float* scratch = nullptr;
    cudaGetSymbolAddress((void**)&scratch, g_scratch);
    float* y1    = scratch + OFF_Y1;
    float* y2    = scratch + OFF_Y2;
    float* x1    = scratch + OFF_X1;
    float* xproj = scratch + OFF_XPROJ;
    float* om    = scratch + OFF_OM;
    float* core  = scratch + OFF_CORE;
    float* outp  = (float*)d_out;

    // 1) cv1: 3x3 conv + BN + SiLU -> y1 (NCHW)
    conv3x3_bnsilu_k<<<dim3(CM, NB), 256>>>(x, cv1_w, cv1_g, cv1_b, y1);

    // 2) pw: 1x1 conv + BN + SiLU -> y2 (NHWC).  A = y1 col-major per image.
    gemm_k<1, 1><<<dim3(HW / 64, C2 / 64, NB), 256>>>(
        y1, pw_w, nullptr, pw_g, pw_b, nullptr, y2, HW, C2, CM, HW);

    // 3) input_proj: xproj = y2 @ inp_w^T + inp_b
    gemm_k<0, 0><<<dim3(NPIX / 64, C2 / 64, 1), 256>>>(
        y2, inp_w, inp_b, nullptr, nullptr, nullptr, xproj, NPIX, C2, C2, 0);

    // 4) depthwise 3x3 + LN + GELU -> x1
    dw_ln_gelu_k<<<NPIX, 256>>>(y2, dw_w, dw_b, ln_g, ln_b, x1);

    // 5) offset + softmax(mask) heads -> om
    offmask_k<<<NPIX, 256>>>(x1, off_w, off_b, msk_w, msk_b, om);

    // 6) DCNv3 bilinear core -> core
    dcnv3_k<<<NPIX, 256>>>(xproj, om, core);

    // 7) output_proj + bias + BN2 + SiLU + residual -> d_out (NCHW)
    gemm_k<0, 2><<<dim3(NPIX / 64, C2 / 64, 1), 256>>>(
        core, out_w, out_b, bn2_g, bn2_b, x, outp, NPIX, C2, C2, 0);
}

// round 3
// speedup vs baseline: 2.0035x; 2.0035x over previous
#include <cuda_runtime.h>
#include <cuda_bf16.h>
#include <math.h>

// ---------------------------------------------------------------------------
// Problem constants
// ---------------------------------------------------------------------------
#define NB   4
#define C1   256
#define CM   128
#define C2   256
#define HW   4096
#define NPIX (NB*HW)
#define PP   9
#define BN_EPS 1e-5f
#define LN_EPS 1e-6f

// ---------------------------------------------------------------------------
// Scratch
// ---------------------------------------------------------------------------
#define OFF_Y1     0                        // (4,128,64,64) NCHW
#define OFF_Y2     (OFF_Y1 + NB*CM*HW)      // (16384,256) NHWC
#define OFF_ONHWC  (OFF_Y2 + NPIX*C2)       // (16384,256) out_proj result NHWC
#define OFF_XPROJ  (OFF_ONHWC + NPIX*C2)    // (16384,256)
#define OFF_OM     (OFF_XPROJ + NPIX*C2)    // (16384,27)
#define OFF_CORE   (OFF_OM + NPIX*27)       // (16384,256)
#define SCRATCH_FLOATS (OFF_CORE + NPIX*C2)

__device__ __align__(16) float g_scratch[SCRATCH_FLOATS];

__device__ __forceinline__ float silu(float v) { return v / (1.0f + expf(-v)); }

// ---------------------------------------------------------------------------
// Packed fp32x2 helpers (Blackwell FFMA2 — exact fp32, 2 MACs/inst)
// ---------------------------------------------------------------------------
typedef unsigned long long u64;
__device__ __forceinline__ u64 packdup(float v) {
    u64 r; asm("mov.b64 %0, {%1, %1};" : "=l"(r) : "f"(v)); return r;
}
__device__ __forceinline__ void ffma2(u64& d, u64 a, u64 b) {
    asm("fma.rn.f32x2 %0, %1, %2, %0;" : "+l"(d) : "l"(a), "l"(b));
}
__device__ __forceinline__ float2 unpack2(u64 v) {
    float2 f; asm("mov.b64 {%0, %1}, %2;" : "=f"(f.x), "=f"(f.y) : "l"(v)); return f;
}

// ---------------------------------------------------------------------------
// cv1: 3x3 conv (256->128) + BN + SiLU.
// Block: 32x32 spatial tile x 8 c_out. 256 threads (16x16), each 2x2 spatial.
// Input staged in SMEM in 4-ci chunks, shared by all 8 c_out.
// Inner loop: f32x2 FMA over c_out pairs.
// ---------------------------------------------------------------------------
__global__ __launch_bounds__(256, 2) void conv3x3_bnsilu_k(
    const float* __restrict__ x,     // (NB, 256, 64, 64)
    const float* __restrict__ w,     // (128, 256, 3, 3)
    const float* __restrict__ g,
    const float* __restrict__ b,
    float* __restrict__ out)         // (NB, 128, 64, 64)
{
    __shared__ __align__(16) float xs[4][34 * 36];  // 4 ci planes, 34x34 padded, stride 36
    __shared__ __align__(16) float ws[4][9][8];     // [ci][tap][co]

    const int co0  = blockIdx.x * 8;              // 0..120
    const int tile = blockIdx.y;                  // 0..3
    const int n    = blockIdx.z;
    const int th0  = (tile >> 1) * 32;
    const int tw0  = (tile & 1) * 32;

    const int tid = threadIdx.x;
    const int tx  = tid & 15;    // col group (2 cols)
    const int ty  = tid >> 4;    // row group (2 rows)

    // precompute staging coords
    int rr[5], cc[5];
#pragma unroll
    for (int s = 0; s < 5; s++) {
        int k = tid + s * 256;
        rr[s] = k / 34; cc[s] = k - rr[s] * 34;
    }

    u64 acc[4][4];   // [co_pair][spatial i*2+j]
#pragma unroll
    for (int p = 0; p < 4; p++)
#pragma unroll
        for (int sSp = 0; sSp < 4; sSp++) acc[p][sSp] = 0ULL;

    for (int ci0 = 0; ci0 < C1; ci0 += 4) {
        // ---- stage 4 input planes ----
#pragma unroll
        for (int cis = 0; cis < 4; cis++) {
            const float* xp = x + ((size_t)n * C1 + ci0 + cis) * HW;
#pragma unroll
            for (int s = 0; s < 5; s++) {
                int k = tid + s * 256;
                if (k < 34 * 34) {
                    int gh = th0 + rr[s] - 1;
                    int gw = tw0 + cc[s] - 1;
                    float v = 0.0f;
                    if ((unsigned)gh < 64u && (unsigned)gw < 64u) v = xp[gh * 64 + gw];
                    xs[cis][rr[s] * 36 + cc[s]] = v;
                }
            }
        }
        // ---- stage weights: 4 ci x 9 taps x 8 co = 288 entries (strided) ----
        for (int k = tid; k < 288; k += 256) {
            int cis = k / 72;
            int rem = k - cis * 72;
            int tap = rem >> 3;
            int co  = rem & 7;
            ws[cis][tap][co] = w[((size_t)(co0 + co) * C1 + ci0 + cis) * 9 + tap];
        }
        __syncthreads();

#pragma unroll
        for (int cis = 0; cis < 4; cis++) {
            // load 4x4 input patch, duplicate-pack
            u64 xd[4][4];
#pragma unroll
            for (int r = 0; r < 4; r++) {
                const float* row = &xs[cis][(ty * 2 + r) * 36 + tx * 2];
                float2 a = *(const float2*)(row);
                float2 c2v = *(const float2*)(row + 2);
                xd[r][0] = packdup(a.x);   xd[r][1] = packdup(a.y);
                xd[r][2] = packdup(c2v.x); xd[r][3] = packdup(c2v.y);
            }
#pragma unroll
            for (int kh = 0; kh < 3; kh++)
#pragma unroll
                for (int kw = 0; kw < 3; kw++) {
                    int tap = kh * 3 + kw;
                    u64 w01 = *(const u64*)&ws[cis][tap][0];
                    u64 w23 = *(const u64*)&ws[cis][tap][2];
                    u64 w45 = *(const u64*)&ws[cis][tap][4];
                    u64 w67 = *(const u64*)&ws[cis][tap][6];
#pragma unroll
                    for (int i = 0; i < 2; i++)
#pragma unroll
                        for (int j = 0; j < 2; j++) {
                            u64 xv = xd[i + kh][j + kw];
                            ffma2(acc[0][i * 2 + j], w01, xv);
                            ffma2(acc[1][i * 2 + j], w23, xv);
                            ffma2(acc[2][i * 2 + j], w45, xv);
                            ffma2(acc[3][i * 2 + j], w67, xv);
                        }
                }
        }
        __syncthreads();
    }

    // ---- epilogue: BN + SiLU, write NCHW ----
#pragma unroll
    for (int p = 0; p < 4; p++) {
        int coA = co0 + p * 2, coB = coA + 1;
        float sA = g[coA] * rsqrtf(1.0f + BN_EPS), bA = b[coA];
        float sB = g[coB] * rsqrtf(1.0f + BN_EPS), bB = b[coB];
        float* opA = out + ((size_t)n * CM + coA) * HW;
        float* opB = out + ((size_t)n * CM + coB) * HW;
#pragma unroll
        for (int i = 0; i < 2; i++) {
            int gh = th0 + ty * 2 + i;
            int gw = tw0 + tx * 2;
            float2 v0 = unpack2(acc[p][i * 2 + 0]);
            float2 v1 = unpack2(acc[p][i * 2 + 1]);
            float2 oa, ob;
            oa.x = silu(fmaf(v0.x, sA, bA)); oa.y = silu(fmaf(v1.x, sA, bA));
            ob.x = silu(fmaf(v0.y, sB, bB)); ob.y = silu(fmaf(v1.y, sB, bB));
            *(float2*)&opA[gh * 64 + gw] = oa;
            *(float2*)&opB[gh * 64 + gw] = ob;
        }
    }
}

// ---------------------------------------------------------------------------
// Tiled SGEMM with f32x2 inner loop: C[M,N] = A * W^T (+epilogue)
//   W is [N][K] row-major. TRANSA=0: A row-major [M][K]. TRANSA=1: A [K][M].
// MODE 0: +bias, row-major out. MODE 1: BN+SiLU, row-major out.
// ---------------------------------------------------------------------------
template<int TRANSA, int MODE>
__global__ __launch_bounds__(256) void gemm_k(
    const float* __restrict__ A, const float* __restrict__ W,
    const float* __restrict__ bias,
    const float* __restrict__ gamma, const float* __restrict__ beta,
    float* __restrict__ C,
    int M, int N, int K, int lda)
{
    __shared__ __align__(16) float As[16][68];
    __shared__ __align__(16) float Bs[16][68];

    const int m0 = blockIdx.x * 64;
    const int n0 = blockIdx.y * 64;
    const int z  = blockIdx.z;
    const float* Ab = A + (TRANSA ? (size_t)z * K * lda : (size_t)z * M * K);

    const int tid = threadIdx.x;
    const int tx  = tid & 15;
    const int ty  = tid >> 4;

    u64 acc2[4][2];
#pragma unroll
    for (int i = 0; i < 4; i++) { acc2[i][0] = 0ULL; acc2[i][1] = 0ULL; }

    for (int k0 = 0; k0 < K; k0 += 16) {
        if (TRANSA) {
            int k  = tid >> 4;
            int mm = (tid & 15) * 4;
            float4 a4 = *(const float4*)&Ab[(size_t)(k0 + k) * lda + m0 + mm];
            *(float4*)&As[k][mm] = a4;
        } else {
            int row = tid >> 2;
            int c4  = (tid & 3) * 4;
            float4 a4 = *(const float4*)&Ab[(size_t)(m0 + row) * K + k0 + c4];
            As[c4 + 0][row] = a4.x; As[c4 + 1][row] = a4.y;
            As[c4 + 2][row] = a4.z; As[c4 + 3][row] = a4.w;
        }
        {
            int row = tid >> 2;
            int c4  = (tid & 3) * 4;
            float4 b4 = *(const float4*)&W[(size_t)(n0 + row) * K + k0 + c4];
            Bs[c4 + 0][row] = b4.x; Bs[c4 + 1][row] = b4.y;
            Bs[c4 + 2][row] = b4.z; Bs[c4 + 3][row] = b4.w;
        }
        __syncthreads();

#pragma unroll
        for (int kk = 0; kk < 16; kk++) {
            float4 a = *(const float4*)&As[kk][ty * 4];
            ulonglong2 bb = *(const ulonglong2*)&Bs[kk][tx * 4];
            u64 a0 = packdup(a.x), a1 = packdup(a.y), a2 = packdup(a.z), a3 = packdup(a.w);
            ffma2(acc2[0][0], a0, bb.x); ffma2(acc2[0][1], a0, bb.y);
            ffma2(acc2[1][0], a1, bb.x); ffma2(acc2[1][1], a1, bb.y);
            ffma2(acc2[2][0], a2, bb.x); ffma2(acc2[2][1], a2, bb.y);
            ffma2(acc2[3][0], a3, bb.x); ffma2(acc2[3][1], a3, bb.y);
        }
        __syncthreads();
    }

#pragma unroll
    for (int i = 0; i < 4; i++) {
        float2 v01 = unpack2(acc2[i][0]);
        float2 v23 = unpack2(acc2[i][1]);
        float vv[4] = {v01.x, v01.y, v23.x, v23.y};
#pragma unroll
        for (int j = 0; j < 4; j++) {
            int m = m0 + ty * 4 + i;
            int n = n0 + tx * 4 + j;
            float v = vv[j];
            if (MODE == 0) {
                if (bias) v += bias[n];
                C[((size_t)z * M + m) * N + n] = v;
            } else {
                float s = gamma[n] * rsqrtf(1.0f + BN_EPS);
                v = fmaf(v, s, beta[n]);
                C[((size_t)z * M + m) * N + n] = silu(v);
            }
        }
    }
}

// ---------------------------------------------------------------------------
// Fused: depthwise 3x3 + bias + LayerNorm(C) + GELU + offset/mask heads
// One block per pixel, one thread per channel (256). x1 never materialized.
// ---------------------------------------------------------------------------
__global__ __launch_bounds__(256) void dw_ln_gelu_offmask_k(
    const float* __restrict__ y2,    // (NPIX, 256) NHWC
    const float* __restrict__ dww,   // (256,1,3,3)
    const float* __restrict__ dwb,
    const float* __restrict__ lg,
    const float* __restrict__ lb,
    const float* __restrict__ offw, const float* __restrict__ offb,
    const float* __restrict__ mskw, const float* __restrict__ mskb,
    float* __restrict__ om)          // (NPIX, 27)
{
    const int pix = blockIdx.x;
    const int n = pix >> 12, hw = pix & 4095, h = hw >> 6, w = hw & 63;
    const int c = threadIdx.x;

    float v = dwb[c];
#pragma unroll
    for (int kh = 0; kh < 3; kh++)
#pragma unroll
        for (int kw = 0; kw < 3; kw++) {
            int hh = h + kh - 1, wk = w + kw - 1;
            if ((unsigned)hh < 64u && (unsigned)wk < 64u)
                v = fmaf(y2[(((size_t)n * HW) + hh * 64 + wk) * C2 + c],
                         dww[c * 9 + kh * 3 + kw], v);
        }

    __shared__ float s1[256];
    __shared__ float s2[256];
    __shared__ float logits[32];
    s1[c] = v; s2[c] = v * v;
    __syncthreads();
#pragma unroll
    for (int off = 128; off > 32; off >>= 1) {
        if (c < off) { s1[c] += s1[c + off]; s2[c] += s2[c + off]; }
        __syncthreads();
    }
    float mean, var;
    {
        if (c < 32) {
            float a1 = s1[c] + s1[c + 32];
            float a2 = s2[c] + s2[c + 32];
#pragma unroll
            for (int o = 16; o > 0; o >>= 1) {
                a1 += __shfl_down_sync(0xffffffffu, a1, o);
                a2 += __shfl_down_sync(0xffffffffu, a2, o);
            }
            if (c == 0) { s1[0] = a1; s2[0] = a2; }
        }
        __syncthreads();
        mean = s1[0] * (1.0f / 256.0f);
        var  = s2[0] * (1.0f / 256.0f) - mean * mean;
    }

    float t = fmaf((v - mean) * rsqrtf(var + LN_EPS), lg[c], lb[c]);
    float gelu = 0.5f * t * (1.0f + erff(t * 0.70710678118654752f));

    __syncthreads();          // s1 reuse
    s1[c] = gelu;
    __syncthreads();

    const int lane = c & 31, wp = c >> 5;
#pragma unroll
    for (int j0 = 0; j0 < 32; j0 += 8) {
        int j = j0 + wp;
        if (j < 27) {
            const float* wrow = (j < 18) ? (offw + (size_t)j * C2)
                                         : (mskw + (size_t)(j - 18) * C2);
            float s = 0.0f;
#pragma unroll
            for (int tci = lane; tci < C2; tci += 32) s = fmaf(s1[tci], wrow[tci], s);
#pragma unroll
            for (int o = 16; o > 0; o >>= 1) s += __shfl_down_sync(0xffffffffu, s, o);
            if (lane == 0) logits[j] = s + ((j < 18) ? offb[j] : mskb[j - 18]);
        }
    }
    __syncthreads();

    if (c < 18) om[(size_t)pix * 27 + c] = logits[c];
    if (c == 0) {
        float mx = -1e30f;
#pragma unroll
        for (int q = 0; q < 9; q++) mx = fmaxf(mx, logits[18 + q]);
        float e[9], sum = 0.0f;
#pragma unroll
        for (int q = 0; q < 9; q++) { e[q] = expf(logits[18 + q] - mx); sum += e[q]; }
        float inv = 1.0f / sum;
#pragma unroll
        for (int q = 0; q < 9; q++) om[(size_t)pix * 27 + 18 + q] = e[q] * inv;
    }
}

// ---------------------------------------------------------------------------
// DCNv3 core. One block per pixel, one thread per channel.
// ---------------------------------------------------------------------------
__global__ __launch_bounds__(256) void dcnv3_k(
    const float* __restrict__ xproj,   // (NPIX, 256) NHWC
    const float* __restrict__ om,      // (NPIX, 27)
    float* __restrict__ core)          // (NPIX, 256)
{
    const int pix = blockIdx.x;
    const int n = pix >> 12, hw = pix & 4095, h = hw >> 6, w = hw & 63;
    const int c = threadIdx.x;

    __shared__ float o[32];
    if (c < 27) o[c] = om[(size_t)pix * 27 + c];
    __syncthreads();

    const float* base = xproj + (size_t)n * HW * C2;
    float acc = 0.0f;

#pragma unroll
    for (int p = 0; p < PP; p++) {
        float px = (float)(w + (p / 3)) + o[2 * p];
        float py = (float)(h + (p % 3)) + o[2 * p + 1];
        float x0f = floorf(px), y0f = floorf(py);
        float fx = px - x0f, fy = py - y0f;
        int x0 = (int)x0f, y0 = (int)y0f;
        float mk = o[18 + p];
        float s = 0.0f;
#pragma unroll
        for (int dy = 0; dy < 2; dy++)
#pragma unroll
            for (int dx = 0; dx < 2; dx++) {
                int xi = x0 + dx, yi = y0 + dy;
                if (xi >= 1 && xi <= 64 && yi >= 1 && yi <= 64) {
                    float wgt = (dx ? fx : 1.0f - fx) * (dy ? fy : 1.0f - fy);
                    s = fmaf(wgt, base[((size_t)(yi - 1) * 64 + (xi - 1)) * C2 + c], s);
                }
            }
        acc = fmaf(mk, s, acc);
    }
    core[(size_t)pix * C2 + c] = acc;
}

// ---------------------------------------------------------------------------
// Transpose NHWC->NCHW with fused BN2 + SiLU + residual (coalesced both ways)
// ---------------------------------------------------------------------------
__global__ __launch_bounds__(256) void bn2_res_transpose_k(
    const float* __restrict__ o,     // (NPIX, 256) NHWC (includes out_b)
    const float* __restrict__ xres,  // (NB, 256, 64, 64)
    const float* __restrict__ g, const float* __restrict__ b,
    float* __restrict__ out)         // (NB, 256, 64, 64)
{
    __shared__ float t[32][33];
    const int n   = blockIdx.z;
    const int hw0 = blockIdx.x * 32;
    const int c0  = blockIdx.y * 32;
    const int tx  = threadIdx.x & 31;
    const int ty  = threadIdx.x >> 5;   // 0..7

#pragma unroll
    for (int i = ty; i < 32; i += 8)
        t[i][tx] = o[((size_t)n * HW + hw0 + i) * C2 + c0 + tx];
    __syncthreads();

#pragma unroll
    for (int i = ty; i < 32; i += 8) {
        int c  = c0 + i;
        int hw = hw0 + tx;
        float v = t[tx][i];
        float s = g[c] * rsqrtf(1.0f + BN_EPS);
        v = silu(fmaf(v, s, b[c]));
        size_t idx = ((size_t)n * C2 + c) * HW + hw;
        out[idx] = xres[idx] + v;
    }
}

// ---------------------------------------------------------------------------
// Launch
// ---------------------------------------------------------------------------
extern "C" void kernel_launch(void* const* d_in, const int* in_sizes, int n_in,
                              void* d_out, int out_size) {
    const float* x     = (const float*)d_in[0];
    const float* cv1_w = (const float*)d_in[1];
    const float* cv1_g = (const float*)d_in[2];
    const float* cv1_b = (const float*)d_in[3];
    const float* pw_w  = (const float*)d_in[4];
    const float* pw_g  = (const float*)d_in[5];
    const float* pw_b  = (const float*)d_in[6];
    const float* dw_w  = (const float*)d_in[7];
    const float* dw_b  = (const float*)d_in[8];
    const float* ln_g  = (const float*)d_in[9];
    const float* ln_b  = (const float*)d_in[10];
    const float* off_w = (const float*)d_in[11];
    const float* off_b = (const float*)d_in[12];
    const float* msk_w = (const float*)d_in[13];
    const float* msk_b = (const float*)d_in[14];
    const float* inp_w = (const float*)d_in[15];
    const float* inp_b = (const float*)d_in[16];
    const float* out_w = (const float*)d_in[17];
    const float* out_b = (const float*)d_in[18];
    const float* bn2_g = (const float*)d_in[19];
    const float* bn2_b = (const float*)d_in[20];

    float* scratch = nullptr;
    cudaGetSymbolAddress((void**)&scratch, g_scratch);
    float* y1    = scratch + OFF_Y1;
    float* y2    = scratch + OFF_Y2;
    float* onhwc = scratch + OFF_ONHWC;
    float* xproj = scratch + OFF_XPROJ;
    float* om    = scratch + OFF_OM;
    float* core  = scratch + OFF_CORE;
    float* outp  = (float*)d_out;

    // 1) cv1: 3x3 conv + BN + SiLU -> y1 (NCHW)
    conv3x3_bnsilu_k<<<dim3(CM / 8, 4, NB), 256>>>(x, cv1_w, cv1_g, cv1_b, y1);

    // 2) pw: 1x1 conv + BN + SiLU -> y2 (NHWC)
    gemm_k<1, 1><<<dim3(HW / 64, C2 / 64, NB), 256>>>(
        y1, pw_w, nullptr, pw_g, pw_b, y2, HW, C2, CM, HW);

    // 3) input_proj: xproj = y2 @ inp_w^T + inp_b
    gemm_k<0, 0><<<dim3(NPIX / 64, C2 / 64, 1), 256>>>(
        y2, inp_w, inp_b, nullptr, nullptr, xproj, NPIX, C2, C2, 0);

    // 4) fused depthwise + LN + GELU + offset/mask heads -> om
    dw_ln_gelu_offmask_k<<<NPIX, 256>>>(y2, dw_w, dw_b, ln_g, ln_b,
                                        off_w, off_b, msk_w, msk_b, om);

    // 5) DCNv3 bilinear core -> core
    dcnv3_k<<<NPIX, 256>>>(xproj, om, core);

    // 6) output_proj (+bias) -> onhwc
    gemm_k<0, 0><<<dim3(NPIX / 64, C2 / 64, 1), 256>>>(
        core, out_w, out_b, nullptr, nullptr, onhwc, NPIX, C2, C2, 0);

    // 7) BN2 + SiLU + residual + NHWC->NCHW -> d_out
    bn2_res_transpose_k<<<dim3(HW / 32, C2 / 32, NB), 256>>>(
        onhwc, x, bn2_g, bn2_b, outp);
}

// round 5
// speedup vs baseline: 3.2623x; 1.6283x over previous
#include <cuda_runtime.h>
#include <cuda_bf16.h>
#include <math.h>
#include <stdint.h>

// ---------------------------------------------------------------------------
// Problem constants
// ---------------------------------------------------------------------------
#define NB   4
#define C1   256
#define CM   128
#define C2   256
#define HW   4096
#define NPIX (NB*HW)
#define PP   9
#define BN_EPS 1e-5f
#define LN_EPS 1e-6f

typedef __nv_bfloat16 bf16;

// ---------------------------------------------------------------------------
// Scratch (offsets in floats)
// ---------------------------------------------------------------------------
#define OFF_XHI   0                         // NPIX*C1 bf16
#define OFF_XLO   (OFF_XHI  + NPIX*C1/2)
#define OFF_Y1HI  (OFF_XLO  + NPIX*C1/2)    // NPIX*CM bf16
#define OFF_Y1LO  (OFF_Y1HI + NPIX*CM/2)
#define OFF_Y2F   (OFF_Y1LO + NPIX*CM/2)    // NPIX*C2 f32
#define OFF_Y2HI  (OFF_Y2F  + NPIX*C2)
#define OFF_Y2LO  (OFF_Y2HI + NPIX*C2/2)
#define OFF_XPROJ (OFF_Y2LO + NPIX*C2/2)    // f32
#define OFF_OM    (OFF_XPROJ+ NPIX*C2)      // NPIX*27 f32
#define OFF_CHI   (OFF_OM   + NPIX*27)
#define OFF_CLO   (OFF_CHI  + NPIX*C2/2)
#define OFF_ONH   (OFF_CLO  + NPIX*C2/2)    // f32
#define OFF_WT9H  (OFF_ONH  + NPIX*C2)      // 9*128*256 bf16, [tap][co][ci]
#define OFF_WT9L  (OFF_WT9H + 9*CM*C1/2)
#define OFF_PWH   (OFF_WT9L + 9*CM*C1/2)    // 256*128 bf16
#define OFF_PWL   (OFF_PWH  + C2*CM/2)
#define OFF_INH   (OFF_PWL  + C2*CM/2)      // 256*256 bf16
#define OFF_INL   (OFF_INH  + C2*C2/2)
#define OFF_OUH   (OFF_INL  + C2*C2/2)
#define OFF_OUL   (OFF_OUH  + C2*C2/2)
#define SCRATCH_FLOATS (OFF_OUL + C2*C2/2)

__device__ __align__(16) float g_scratch[SCRATCH_FLOATS];

__device__ __forceinline__ float silu(float v) { return v / (1.0f + expf(-v)); }

__device__ __forceinline__ void split_bf(float v, bf16& h, bf16& l) {
    h = __float2bfloat16_rn(v);
    l = __float2bfloat16_rn(v - __bfloat162float(h));
}
__device__ __forceinline__ uint32_t pack_pair(float a, float b, bool lo) {
    bf16 ha, la, hb, lbv;
    split_bf(a, ha, la); split_bf(b, hb, lbv);
    if (!lo) return ((uint32_t)*(uint16_t*)&hb << 16) | *(uint16_t*)&ha;
    else     return ((uint32_t)*(uint16_t*)&lbv << 16) | *(uint16_t*)&la;
}

// ---------------------------------------------------------------------------
// mma.sync m16n8k16 bf16 (portable PTX, sm_80+ -> HMMA on sm_103)
// ---------------------------------------------------------------------------
__device__ __forceinline__ void mma16816(float* d, const uint32_t* a, const uint32_t* b) {
    asm volatile("mma.sync.aligned.m16n8k16.row.col.f32.bf16.bf16.f32 "
        "{%0,%1,%2,%3}, {%4,%5,%6,%7}, {%8,%9}, {%0,%1,%2,%3};"
        : "+f"(d[0]), "+f"(d[1]), "+f"(d[2]), "+f"(d[3])
        : "r"(a[0]), "r"(a[1]), "r"(a[2]), "r"(a[3]), "r"(b[0]), "r"(b[1]));
}

// SMEM tile: 128 rows x 32 bf16, row stride 20 words (bank-conflict-free)
#define TS 20

// ---------------------------------------------------------------------------
// prep_x: NCHW f32 -> NHWC bf16 hi/lo
// ---------------------------------------------------------------------------
__global__ __launch_bounds__(256) void prep_x_k(
    const float* __restrict__ x, bf16* __restrict__ xhi, bf16* __restrict__ xlo)
{
    __shared__ float t[32][33];
    const int n = blockIdx.z, hw0 = blockIdx.x * 32, c0 = blockIdx.y * 32;
    const int tx = threadIdx.x & 31, ty = threadIdx.x >> 5;
#pragma unroll
    for (int i = ty; i < 32; i += 8)
        t[i][tx] = x[((size_t)n * C1 + c0 + i) * HW + hw0 + tx];
    __syncthreads();
#pragma unroll
    for (int i = ty; i < 32; i += 8) {
        float v = t[tx][i];
        bf16 h, l; split_bf(v, h, l);
        size_t idx = ((size_t)n * HW + hw0 + i) * C1 + c0 + tx;
        xhi[idx] = h; xlo[idx] = l;
    }
}

// ---------------------------------------------------------------------------
// prep_w: split weights to bf16 hi/lo; cv1 -> [tap][co][ci]
// ---------------------------------------------------------------------------
__global__ __launch_bounds__(256) void prep_w_k(
    const float* __restrict__ cv1w, const float* __restrict__ pww,
    const float* __restrict__ inpw, const float* __restrict__ outw,
    bf16* __restrict__ wt9h, bf16* __restrict__ wt9l,
    bf16* __restrict__ pwh,  bf16* __restrict__ pwl,
    bf16* __restrict__ inh,  bf16* __restrict__ inl,
    bf16* __restrict__ ouh,  bf16* __restrict__ oul)
{
    int idx = blockIdx.x * 256 + threadIdx.x;
    const int N1 = 9 * CM * C1;
    if (idx < N1) {
        int tap = idx / (CM * C1);
        int rem = idx - tap * CM * C1;
        int co = rem >> 8, ci = rem & 255;
        float v = cv1w[(size_t)co * (C1 * 9) + ci * 9 + tap];
        bf16 h, l; split_bf(v, h, l);
        wt9h[idx] = h; wt9l[idx] = l;
        return;
    }
    idx -= N1;
    if (idx < C2 * CM) {
        float v = pww[idx]; bf16 h, l; split_bf(v, h, l);
        pwh[idx] = h; pwl[idx] = l; return;
    }
    idx -= C2 * CM;
    if (idx < C2 * C2) {
        float v = inpw[idx]; bf16 h, l; split_bf(v, h, l);
        inh[idx] = h; inl[idx] = l; return;
    }
    idx -= C2 * C2;
    if (idx < C2 * C2) {
        float v = outw[idx]; bf16 h, l; split_bf(v, h, l);
        ouh[idx] = h; oul[idx] = l;
    }
}

// ---------------------------------------------------------------------------
// Shared inner MMA step over a staged 128x32 (A) x 128x32 (B) tile pair.
// acc[mt][nt][4]. Warp layout 2x4: wm in {0,1} (64 rows), wn in {0..3} (32 cols).
// ---------------------------------------------------------------------------
__device__ __forceinline__ void mma_tile_step(
    const uint32_t* AsHi, const uint32_t* AsLo,
    const uint32_t* BsHi, const uint32_t* BsLo,
    int wm, int wn, int qr, int qc, float acc[4][4][4])
{
#pragma unroll
    for (int ks = 0; ks < 2; ks++) {
        const int k8 = ks * 8;
        uint32_t ahi[4][4], alo[4][4], bhi[4][2], blo[4][2];
#pragma unroll
        for (int mt = 0; mt < 4; mt++) {
            int br = wm * 64 + mt * 16 + qr;
            ahi[mt][0] = AsHi[br * TS + k8 + qc];
            ahi[mt][1] = AsHi[(br + 8) * TS + k8 + qc];
            ahi[mt][2] = AsHi[br * TS + k8 + 4 + qc];
            ahi[mt][3] = AsHi[(br + 8) * TS + k8 + 4 + qc];
            alo[mt][0] = AsLo[br * TS + k8 + qc];
            alo[mt][1] = AsLo[(br + 8) * TS + k8 + qc];
            alo[mt][2] = AsLo[br * TS + k8 + 4 + qc];
            alo[mt][3] = AsLo[(br + 8) * TS + k8 + 4 + qc];
        }
#pragma unroll
        for (int nt = 0; nt < 4; nt++) {
            int bn_ = wn * 32 + nt * 8 + qr;
            bhi[nt][0] = BsHi[bn_ * TS + k8 + qc];
            bhi[nt][1] = BsHi[bn_ * TS + k8 + 4 + qc];
            blo[nt][0] = BsLo[bn_ * TS + k8 + qc];
            blo[nt][1] = BsLo[bn_ * TS + k8 + 4 + qc];
        }
#pragma unroll
        for (int mt = 0; mt < 4; mt++)
#pragma unroll
            for (int nt = 0; nt < 4; nt++) {
                mma16816(acc[mt][nt], ahi[mt], bhi[nt]);
                mma16816(acc[mt][nt], ahi[mt], blo[nt]);
                mma16816(acc[mt][nt], alo[mt], bhi[nt]);
            }
    }
}

// ---------------------------------------------------------------------------
// mma_conv: cv1 3x3 conv (256->128) + BN + SiLU, implicit GEMM over 9 taps.
// Block = 128 pixels x 128 co. Output: y1 hi/lo NHWC bf16.
// ---------------------------------------------------------------------------
__global__ __launch_bounds__(256) void mma_conv_k(
    const bf16* __restrict__ xhi, const bf16* __restrict__ xlo,
    const bf16* __restrict__ wth, const bf16* __restrict__ wtl,
    const float* __restrict__ g, const float* __restrict__ b,
    bf16* __restrict__ y1hi, bf16* __restrict__ y1lo)
{
    __shared__ __align__(16) uint32_t AsHi[128 * TS], AsLo[128 * TS];
    __shared__ __align__(16) uint32_t BsHi[128 * TS], BsLo[128 * TS];

    const int tid = threadIdx.x, wid = tid >> 5, lane = tid & 31;
    const int wm = wid >> 2, wn = wid & 3, qr = lane >> 2, qc = lane & 3;
    const int pix0 = blockIdx.x * 128;
    const int n = pix0 >> 12, h0 = (pix0 & 4095) >> 6;

    float acc[4][4][4];
#pragma unroll
    for (int mt = 0; mt < 4; mt++)
#pragma unroll
        for (int nt = 0; nt < 4; nt++)
#pragma unroll
            for (int q = 0; q < 4; q++) acc[mt][nt][q] = 0.0f;

    const int r0 = tid >> 2, ch0 = tid & 3;   // staging: row r0/r0+64, 16B chunk ch0

    for (int iter = 0; iter < 72; iter++) {
        const int tap = iter / 8, kc = iter & 7;
        const int dh = tap / 3 - 1, dw = tap % 3 - 1;
        // ---- stage A (shifted pixels, ci chunk kc*32) ----
#pragma unroll
        for (int i = 0; i < 2; i++) {
            int r = r0 + i * 64;
            int hh = h0 + (r >> 6) + dh, ww = (r & 63) + dw;
            bool val = ((unsigned)hh < 64u) && ((unsigned)ww < 64u);
            uint4 vh = make_uint4(0, 0, 0, 0), vl = make_uint4(0, 0, 0, 0);
            if (val) {
                size_t u4 = (size_t)(n * HW + hh * 64 + ww) * 32 + kc * 4 + ch0;
                vh = ((const uint4*)xhi)[u4];
                vl = ((const uint4*)xlo)[u4];
            }
            *(uint4*)&AsHi[r * TS + ch0 * 4] = vh;
            *(uint4*)&AsLo[r * TS + ch0 * 4] = vl;
        }
        // ---- stage B (weights [tap][co][ci]) ----
#pragma unroll
        for (int i = 0; i < 2; i++) {
            int r = r0 + i * 64;
            size_t u4 = (size_t)(tap * CM + r) * 32 + kc * 4 + ch0;
            *(uint4*)&BsHi[r * TS + ch0 * 4] = ((const uint4*)wth)[u4];
            *(uint4*)&BsLo[r * TS + ch0 * 4] = ((const uint4*)wtl)[u4];
        }
        __syncthreads();
        mma_tile_step(AsHi, AsLo, BsHi, BsLo, wm, wn, qr, qc, acc);
        __syncthreads();
    }

    // ---- epilogue: BN + SiLU -> split hi/lo, NHWC [pix][128] ----
#pragma unroll
    for (int nt = 0; nt < 4; nt++) {
        int c = wn * 32 + nt * 8 + qc * 2;
        float s0 = g[c] * rsqrtf(1.0f + BN_EPS),     b0 = b[c];
        float s1 = g[c + 1] * rsqrtf(1.0f + BN_EPS), b1 = b[c + 1];
#pragma unroll
        for (int mt = 0; mt < 4; mt++) {
            int row = wm * 64 + mt * 16 + qr;
#pragma unroll
            for (int half = 0; half < 2; half++) {
                int pix = pix0 + row + half * 8;
                float v0 = silu(fmaf(acc[mt][nt][half * 2 + 0], s0, b0));
                float v1 = silu(fmaf(acc[mt][nt][half * 2 + 1], s1, b1));
                *(uint32_t*)&y1hi[(size_t)pix * CM + c] = pack_pair(v0, v1, false);
                *(uint32_t*)&y1lo[(size_t)pix * CM + c] = pack_pair(v0, v1, true);
            }
        }
    }
}

// ---------------------------------------------------------------------------
// mma_gemm: C[M,N=256] = A[M,K] @ W[N,K]^T.
// MODE 0: BN+SiLU -> f32 + hi/lo split.  MODE 1: +bias -> f32.
// Grid: (M/128, N/128)
// ---------------------------------------------------------------------------
template<int K, int MODE>
__global__ __launch_bounds__(256) void mma_gemm_k(
    const bf16* __restrict__ Ahi, const bf16* __restrict__ Alo,
    const bf16* __restrict__ Whi, const bf16* __restrict__ Wlo,
    const float* __restrict__ p0, const float* __restrict__ p1,
    float* __restrict__ outf, bf16* __restrict__ outhi, bf16* __restrict__ outlo)
{
    __shared__ __align__(16) uint32_t AsHi[128 * TS], AsLo[128 * TS];
    __shared__ __align__(16) uint32_t BsHi[128 * TS], BsLo[128 * TS];

    const int tid = threadIdx.x, wid = tid >> 5, lane = tid & 31;
    const int wm = wid >> 2, wn = wid & 3, qr = lane >> 2, qc = lane & 3;
    const int pix0 = blockIdx.x * 128;
    const int n0 = blockIdx.y * 128;

    float acc[4][4][4];
#pragma unroll
    for (int mt = 0; mt < 4; mt++)
#pragma unroll
        for (int nt = 0; nt < 4; nt++)
#pragma unroll
            for (int q = 0; q < 4; q++) acc[mt][nt][q] = 0.0f;

    const int r0 = tid >> 2, ch0 = tid & 3;

#pragma unroll
    for (int kc = 0; kc < K / 32; kc++) {
#pragma unroll
        for (int i = 0; i < 2; i++) {
            int r = r0 + i * 64;
            size_t au4 = (size_t)(pix0 + r) * (K / 8) + kc * 4 + ch0;
            *(uint4*)&AsHi[r * TS + ch0 * 4] = ((const uint4*)Ahi)[au4];
            *(uint4*)&AsLo[r * TS + ch0 * 4] = ((const uint4*)Alo)[au4];
            size_t bu4 = (size_t)(n0 + r) * (K / 8) + kc * 4 + ch0;
            *(uint4*)&BsHi[r * TS + ch0 * 4] = ((const uint4*)Whi)[bu4];
            *(uint4*)&BsLo[r * TS + ch0 * 4] = ((const uint4*)Wlo)[bu4];
        }
        __syncthreads();
        mma_tile_step(AsHi, AsLo, BsHi, BsLo, wm, wn, qr, qc, acc);
        __syncthreads();
    }

#pragma unroll
    for (int nt = 0; nt < 4; nt++) {
        int c = n0 + wn * 32 + nt * 8 + qc * 2;
        float s0, b0, s1, b1;
        if (MODE == 0) {
            s0 = p0[c] * rsqrtf(1.0f + BN_EPS);     b0 = p1[c];
            s1 = p0[c + 1] * rsqrtf(1.0f + BN_EPS); b1 = p1[c + 1];
        } else {
            b0 = p0[c]; b1 = p0[c + 1]; s0 = s1 = 1.0f;
        }
#pragma unroll
        for (int mt = 0; mt < 4; mt++) {
            int row = wm * 64 + mt * 16 + qr;
#pragma unroll
            for (int half = 0; half < 2; half++) {
                int pix = pix0 + row + half * 8;
                float v0, v1;
                if (MODE == 0) {
                    v0 = silu(fmaf(acc[mt][nt][half * 2 + 0], s0, b0));
                    v1 = silu(fmaf(acc[mt][nt][half * 2 + 1], s1, b1));
                } else {
                    v0 = acc[mt][nt][half * 2 + 0] + b0;
                    v1 = acc[mt][nt][half * 2 + 1] + b1;
                }
                *(float2*)&outf[(size_t)pix * C2 + c] = make_float2(v0, v1);
                if (MODE == 0) {
                    *(uint32_t*)&outhi[(size_t)pix * C2 + c] = pack_pair(v0, v1, false);
                    *(uint32_t*)&outlo[(size_t)pix * C2 + c] = pack_pair(v0, v1, true);
                }
            }
        }
    }
}

// ---------------------------------------------------------------------------
// Fused: depthwise 3x3 + LN + GELU + offset/mask heads
// ---------------------------------------------------------------------------
__global__ __launch_bounds__(256) void dw_ln_gelu_offmask_k(
    const float* __restrict__ y2,
    const float* __restrict__ dww, const float* __restrict__ dwb,
    const float* __restrict__ lg,  const float* __restrict__ lb,
    const float* __restrict__ offw, const float* __restrict__ offb,
    const float* __restrict__ mskw, const float* __restrict__ mskb,
    float* __restrict__ om)
{
    const int pix = blockIdx.x;
    const int n = pix >> 12, hw = pix & 4095, h = hw >> 6, w = hw & 63;
    const int c = threadIdx.x;

    float v = dwb[c];
#pragma unroll
    for (int kh = 0; kh < 3; kh++)
#pragma unroll
        for (int kw = 0; kw < 3; kw++) {
            int hh = h + kh - 1, wk = w + kw - 1;
            if ((unsigned)hh < 64u && (unsigned)wk < 64u)
                v = fmaf(y2[(((size_t)n * HW) + hh * 64 + wk) * C2 + c],
                         dww[c * 9 + kh * 3 + kw], v);
        }

    __shared__ float s1[256];
    __shared__ float s2[256];
    __shared__ float logits[32];
    s1[c] = v; s2[c] = v * v;
    __syncthreads();
#pragma unroll
    for (int off = 128; off > 32; off >>= 1) {
        if (c < off) { s1[c] += s1[c + off]; s2[c] += s2[c + off]; }
        __syncthreads();
    }
    if (c < 32) {
        float a1 = s1[c] + s1[c + 32];
        float a2 = s2[c] + s2[c + 32];
#pragma unroll
        for (int o = 16; o > 0; o >>= 1) {
            a1 += __shfl_down_sync(0xffffffffu, a1, o);
            a2 += __shfl_down_sync(0xffffffffu, a2, o);
        }
        if (c == 0) { s1[0] = a1; s2[0] = a2; }
    }
    __syncthreads();
    float mean = s1[0] * (1.0f / 256.0f);
    float var  = s2[0] * (1.0f / 256.0f) - mean * mean;

    float t = fmaf((v - mean) * rsqrtf(var + LN_EPS), lg[c], lb[c]);
    float gelu = 0.5f * t * (1.0f + erff(t * 0.70710678118654752f));

    __syncthreads();
    s1[c] = gelu;
    __syncthreads();

    const int lane = c & 31, wp = c >> 5;
#pragma unroll
    for (int j0 = 0; j0 < 32; j0 += 8) {
        int j = j0 + wp;
        if (j < 27) {
            const float* wrow = (j < 18) ? (offw + (size_t)j * C2)
                                         : (mskw + (size_t)(j - 18) * C2);
            float s = 0.0f;
#pragma unroll
            for (int tci = lane; tci < C2; tci += 32) s = fmaf(s1[tci], wrow[tci], s);
#pragma unroll
            for (int o = 16; o > 0; o >>= 1) s += __shfl_down_sync(0xffffffffu, s, o);
            if (lane == 0) logits[j] = s + ((j < 18) ? offb[j] : mskb[j - 18]);
        }
    }
    __syncthreads();

    if (c < 18) om[(size_t)pix * 27 + c] = logits[c];
    if (c == 0) {
        float mx = -1e30f;
#pragma unroll
        for (int q = 0; q < 9; q++) mx = fmaxf(mx, logits[18 + q]);
        float e[9], sum = 0.0f;
#pragma unroll
        for (int q = 0; q < 9; q++) { e[q] = expf(logits[18 + q] - mx); sum += e[q]; }
        float inv = 1.0f / sum;
#pragma unroll
        for (int q = 0; q < 9; q++) om[(size_t)pix * 27 + 18 + q] = e[q] * inv;
    }
}

// ---------------------------------------------------------------------------
// DCNv3 core -> split hi/lo bf16
// ---------------------------------------------------------------------------
__global__ __launch_bounds__(256) void dcnv3_k(
    const float* __restrict__ xproj, const float* __restrict__ om,
    bf16* __restrict__ chi, bf16* __restrict__ clo)
{
    const int pix = blockIdx.x;
    const int n = pix >> 12, hw = pix & 4095, h = hw >> 6, w = hw & 63;
    const int c = threadIdx.x;

    __shared__ float o[32];
    if (c < 27) o[c] = om[(size_t)pix * 27 + c];
    __syncthreads();

    const float* base = xproj + (size_t)n * HW * C2;
    float acc = 0.0f;

#pragma unroll
    for (int p = 0; p < PP; p++) {
        float px = (float)(w + (p / 3)) + o[2 * p];
        float py = (float)(h + (p % 3)) + o[2 * p + 1];
        float x0f = floorf(px), y0f = floorf(py);
        float fx = px - x0f, fy = py - y0f;
        int x0 = (int)x0f, y0 = (int)y0f;
        float mk = o[18 + p];
        float s = 0.0f;
#pragma unroll
        for (int dy = 0; dy < 2; dy++)
#pragma unroll
            for (int dx = 0; dx < 2; dx++) {
                int xi = x0 + dx, yi = y0 + dy;
                if (xi >= 1 && xi <= 64 && yi >= 1 && yi <= 64) {
                    float wgt = (dx ? fx : 1.0f - fx) * (dy ? fy : 1.0f - fy);
                    s = fmaf(wgt, base[((size_t)(yi - 1) * 64 + (xi - 1)) * C2 + c], s);
                }
            }
        acc = fmaf(mk, s, acc);
    }
    bf16 hb, lb2; split_bf(acc, hb, lb2);
    chi[(size_t)pix * C2 + c] = hb;
    clo[(size_t)pix * C2 + c] = lb2;
}

// ---------------------------------------------------------------------------
// NHWC->NCHW + BN2 + SiLU + residual
// ---------------------------------------------------------------------------
__global__ __launch_bounds__(256) void bn2_res_transpose_k(
    const float* __restrict__ o, const float* __restrict__ xres,
    const float* __restrict__ g, const float* __restrict__ b,
    float* __restrict__ out)
{
    __shared__ float t[32][33];
    const int n = blockIdx.z, hw0 = blockIdx.x * 32, c0 = blockIdx.y * 32;
    const int tx = threadIdx.x & 31, ty = threadIdx.x >> 5;
#pragma unroll
    for (int i = ty; i < 32; i += 8)
        t[i][tx] = o[((size_t)n * HW + hw0 + i) * C2 + c0 + tx];
    __syncthreads();
#pragma unroll
    for (int i = ty; i < 32; i += 8) {
        int c = c0 + i, hw = hw0 + tx;
        float v = t[tx][i];
        float s = g[c] * rsqrtf(1.0f + BN_EPS);
        v = silu(fmaf(v, s, b[c]));
        size_t idx = ((size_t)n * C2 + c) * HW + hw;
        out[idx] = xres[idx] + v;
    }
}

// ---------------------------------------------------------------------------
// Launch
// ---------------------------------------------------------------------------
extern "C" void kernel_launch(void* const* d_in, const int* in_sizes, int n_in,
                              void* d_out, int out_size) {
    const float* x     = (const float*)d_in[0];
    const float* cv1_w = (const float*)d_in[1];
    const float* cv1_g = (const float*)d_in[2];
    const float* cv1_b = (const float*)d_in[3];
    const float* pw_w  = (const float*)d_in[4];
    const float* pw_g  = (const float*)d_in[5];
    const float* pw_b  = (const float*)d_in[6];
    const float* dw_w  = (const float*)d_in[7];
    const float* dw_b  = (const float*)d_in[8];
    const float* ln_g  = (const float*)d_in[9];
    const float* ln_b  = (const float*)d_in[10];
    const float* off_w = (const float*)d_in[11];
    const float* off_b = (const float*)d_in[12];
    const float* msk_w = (const float*)d_in[13];
    const float* msk_b = (const float*)d_in[14];
    const float* inp_w = (const float*)d_in[15];
    const float* inp_b = (const float*)d_in[16];
    const float* out_w = (const float*)d_in[17];
    const float* out_b = (const float*)d_in[18];
    const float* bn2_g = (const float*)d_in[19];
    const float* bn2_b = (const float*)d_in[20];

    float* sc = nullptr;
    cudaGetSymbolAddress((void**)&sc, g_scratch);
    bf16* xhi  = (bf16*)(sc + OFF_XHI);
    bf16* xlo  = (bf16*)(sc + OFF_XLO);
    bf16* y1hi = (bf16*)(sc + OFF_Y1HI);
    bf16* y1lo = (bf16*)(sc + OFF_Y1LO);
    float* y2f = sc + OFF_Y2F;
    bf16* y2hi = (bf16*)(sc + OFF_Y2HI);
    bf16* y2lo = (bf16*)(sc + OFF_Y2LO);
    float* xproj = sc + OFF_XPROJ;
    float* om    = sc + OFF_OM;
    bf16* chi  = (bf16*)(sc + OFF_CHI);
    bf16* clo  = (bf16*)(sc + OFF_CLO);
    float* onh = sc + OFF_ONH;
    bf16* wt9h = (bf16*)(sc + OFF_WT9H);
    bf16* wt9l = (bf16*)(sc + OFF_WT9L);
    bf16* pwh  = (bf16*)(sc + OFF_PWH);
    bf16* pwl  = (bf16*)(sc + OFF_PWL);
    bf16* inh  = (bf16*)(sc + OFF_INH);
    bf16* inl  = (bf16*)(sc + OFF_INL);
    bf16* ouh  = (bf16*)(sc + OFF_OUH);
    bf16* oul  = (bf16*)(sc + OFF_OUL);
    float* outp = (float*)d_out;

    // 0) preprocessing
    prep_x_k<<<dim3(HW / 32, C1 / 32, NB), 256>>>(x, xhi, xlo);
    prep_w_k<<<(9 * CM * C1 + C2 * CM + 2 * C2 * C2 + 255) / 256, 256>>>(
        cv1_w, pw_w, inp_w, out_w, wt9h, wt9l, pwh, pwl, inh, inl, ouh, oul);

    // 1) cv1 (mma) -> y1 hi/lo (NHWC bf16)
    mma_conv_k<<<NPIX / 128, 256>>>(xhi, xlo, wt9h, wt9l, cv1_g, cv1_b, y1hi, y1lo);

    // 2) pw (mma) -> y2 f32 + hi/lo
    mma_gemm_k<128, 0><<<dim3(NPIX / 128, 2), 256>>>(
        y1hi, y1lo, pwh, pwl, pw_g, pw_b, y2f, y2hi, y2lo);

    // 3) fused dw + LN + GELU + heads -> om
    dw_ln_gelu_offmask_k<<<NPIX, 256>>>(y2f, dw_w, dw_b, ln_g, ln_b,
                                        off_w, off_b, msk_w, msk_b, om);

    // 4) input_proj (mma) -> xproj f32
    mma_gemm_k<256, 1><<<dim3(NPIX / 128, 2), 256>>>(
        y2hi, y2lo, inh, inl, inp_b, nullptr, xproj, nullptr, nullptr);

    // 5) DCNv3 core -> hi/lo
    dcnv3_k<<<NPIX, 256>>>(xproj, om, chi, clo);

    // 6) output_proj (mma) -> onh f32
    mma_gemm_k<256, 1><<<dim3(NPIX / 128, 2), 256>>>(
        chi, clo, ouh, oul, out_b, nullptr, onh, nullptr, nullptr);

    // 7) BN2 + SiLU + residual + transpose -> d_out
    bn2_res_transpose_k<<<dim3(HW / 32, C2 / 32, NB), 256>>>(onh, x, bn2_g, bn2_b, outp);
}

// round 6
// speedup vs baseline: 3.5456x; 1.0868x over previous
#include <cuda_runtime.h>
#include <cuda_bf16.h>
#include <math.h>
#include <stdint.h>

// ---------------------------------------------------------------------------
// Problem constants
// ---------------------------------------------------------------------------
#define NB   4
#define C1   256
#define CM   128
#define C2   256
#define HW   4096
#define NPIX (NB*HW)
#define PP   9
#define BN_EPS 1e-5f
#define LN_EPS 1e-6f

typedef __nv_bfloat16 bf16;

// ---------------------------------------------------------------------------
// Scratch (offsets in floats)
// ---------------------------------------------------------------------------
#define OFF_XHI   0                         // NPIX*C1 bf16
#define OFF_XLO   (OFF_XHI  + NPIX*C1/2)
#define OFF_Y1HI  (OFF_XLO  + NPIX*C1/2)    // NPIX*CM bf16
#define OFF_Y1LO  (OFF_Y1HI + NPIX*CM/2)
#define OFF_Y2F   (OFF_Y1LO + NPIX*CM/2)    // NPIX*C2 f32
#define OFF_Y2HI  (OFF_Y2F  + NPIX*C2)
#define OFF_Y2LO  (OFF_Y2HI + NPIX*C2/2)
#define OFF_XPROJ (OFF_Y2LO + NPIX*C2/2)    // f32
#define OFF_OM    (OFF_XPROJ+ NPIX*C2)      // NPIX*27 f32
#define OFF_CHI   (OFF_OM   + NPIX*27)
#define OFF_CLO   (OFF_CHI  + NPIX*C2/2)
#define OFF_ONH   (OFF_CLO  + NPIX*C2/2)    // f32
#define OFF_WT9H  (OFF_ONH  + NPIX*C2)      // 9*128*256 bf16, [tap][co][ci]
#define OFF_WT9L  (OFF_WT9H + 9*CM*C1/2)
#define OFF_PWH   (OFF_WT9L + 9*CM*C1/2)    // 256*128 bf16
#define OFF_PWL   (OFF_PWH  + C2*CM/2)
#define OFF_INH   (OFF_PWL  + C2*CM/2)      // 256*256 bf16
#define OFF_INL   (OFF_INH  + C2*C2/2)
#define OFF_OUH   (OFF_INL  + C2*C2/2)
#define OFF_OUL   (OFF_OUH  + C2*C2/2)
#define SCRATCH_FLOATS (OFF_OUL + C2*C2/2)

__device__ __align__(16) float g_scratch[SCRATCH_FLOATS];

__device__ __forceinline__ float silu(float v) { return v / (1.0f + expf(-v)); }

__device__ __forceinline__ void split_bf(float v, bf16& h, bf16& l) {
    h = __float2bfloat16_rn(v);
    l = __float2bfloat16_rn(v - __bfloat162float(h));
}
__device__ __forceinline__ uint32_t pack_pair(float a, float b, bool lo) {
    bf16 ha, la, hb, lbv;
    split_bf(a, ha, la); split_bf(b, hb, lbv);
    if (!lo) return ((uint32_t)*(uint16_t*)&hb << 16) | *(uint16_t*)&ha;
    else     return ((uint32_t)*(uint16_t*)&lbv << 16) | *(uint16_t*)&la;
}

// ---------------------------------------------------------------------------
// mma.sync m16n8k16 bf16 + cp.async (portable sm_80 PTX)
// ---------------------------------------------------------------------------
__device__ __forceinline__ void mma16816(float* d, const uint32_t* a, const uint32_t* b) {
    asm volatile("mma.sync.aligned.m16n8k16.row.col.f32.bf16.bf16.f32 "
        "{%0,%1,%2,%3}, {%4,%5,%6,%7}, {%8,%9}, {%0,%1,%2,%3};"
        : "+f"(d[0]), "+f"(d[1]), "+f"(d[2]), "+f"(d[3])
        : "r"(a[0]), "r"(a[1]), "r"(a[2]), "r"(a[3]), "r"(b[0]), "r"(b[1]));
}
__device__ __forceinline__ void cp16(uint32_t dst, const void* src) {
    asm volatile("cp.async.cg.shared.global [%0], [%1], 16;" :: "r"(dst), "l"(src));
}
__device__ __forceinline__ void cp16z(uint32_t dst, const void* src, int srcsize) {
    asm volatile("cp.async.cg.shared.global [%0], [%1], 16, %2;"
                 :: "r"(dst), "l"(src), "r"(srcsize));
}
#define CP_COMMIT() asm volatile("cp.async.commit_group;" ::: "memory")
#define CP_WAIT2()  asm volatile("cp.async.wait_group 2;" ::: "memory")

// SMEM tile row stride: 32 bf16 -> 20 words (bank-conflict-free)
#define TS 20
#define ARRW (128 * TS)          // words per 128x32 array
#define STW  (4 * ARRW)          // words per pipeline stage (AHi,ALo,BHi,BLo)
#define SMEM_PIPE_BYTES (4 * STW * 4)   // 4 stages = 163840 B

// ---------------------------------------------------------------------------
// prep_x: NCHW f32 -> NHWC bf16 hi/lo
// ---------------------------------------------------------------------------
__global__ __launch_bounds__(256) void prep_x_k(
    const float* __restrict__ x, bf16* __restrict__ xhi, bf16* __restrict__ xlo)
{
    __shared__ float t[32][33];
    const int n = blockIdx.z, hw0 = blockIdx.x * 32, c0 = blockIdx.y * 32;
    const int tx = threadIdx.x & 31, ty = threadIdx.x >> 5;
#pragma unroll
    for (int i = ty; i < 32; i += 8)
        t[i][tx] = x[((size_t)n * C1 + c0 + i) * HW + hw0 + tx];
    __syncthreads();
#pragma unroll
    for (int i = ty; i < 32; i += 8) {
        float v = t[tx][i];
        bf16 h, l; split_bf(v, h, l);
        size_t idx = ((size_t)n * HW + hw0 + i) * C1 + c0 + tx;
        xhi[idx] = h; xlo[idx] = l;
    }
}

// ---------------------------------------------------------------------------
// prep_w: split weights to bf16 hi/lo; cv1 -> [tap][co][ci]
// ---------------------------------------------------------------------------
__global__ __launch_bounds__(256) void prep_w_k(
    const float* __restrict__ cv1w, const float* __restrict__ pww,
    const float* __restrict__ inpw, const float* __restrict__ outw,
    bf16* __restrict__ wt9h, bf16* __restrict__ wt9l,
    bf16* __restrict__ pwh,  bf16* __restrict__ pwl,
    bf16* __restrict__ inh,  bf16* __restrict__ inl,
    bf16* __restrict__ ouh,  bf16* __restrict__ oul)
{
    int idx = blockIdx.x * 256 + threadIdx.x;
    const int N1 = 9 * CM * C1;
    if (idx < N1) {
        int tap = idx / (CM * C1);
        int rem = idx - tap * CM * C1;
        int co = rem >> 8, ci = rem & 255;
        float v = cv1w[(size_t)co * (C1 * 9) + ci * 9 + tap];
        bf16 h, l; split_bf(v, h, l);
        wt9h[idx] = h; wt9l[idx] = l;
        return;
    }
    idx -= N1;
    if (idx < C2 * CM) {
        float v = pww[idx]; bf16 h, l; split_bf(v, h, l);
        pwh[idx] = h; pwl[idx] = l; return;
    }
    idx -= C2 * CM;
    if (idx < C2 * C2) {
        float v = inpw[idx]; bf16 h, l; split_bf(v, h, l);
        inh[idx] = h; inl[idx] = l; return;
    }
    idx -= C2 * C2;
    if (idx < C2 * C2) {
        float v = outw[idx]; bf16 h, l; split_bf(v, h, l);
        ouh[idx] = h; oul[idx] = l;
    }
}

// ---------------------------------------------------------------------------
// Inner MMA over a staged 128x32 (A) x 128x32 (B) pair. Warp grid 2x4.
// ---------------------------------------------------------------------------
__device__ __forceinline__ void mma_tile_step(
    const uint32_t* __restrict__ st, int wm, int wn, int qr, int qc, float acc[4][4][4])
{
    const uint32_t* AsHi = st;
    const uint32_t* AsLo = st + ARRW;
    const uint32_t* BsHi = st + 2 * ARRW;
    const uint32_t* BsLo = st + 3 * ARRW;
#pragma unroll
    for (int ks = 0; ks < 2; ks++) {
        const int k8 = ks * 8;
        uint32_t ahi[4][4], alo[4][4], bhi[4][2], blo[4][2];
#pragma unroll
        for (int mt = 0; mt < 4; mt++) {
            int br = wm * 64 + mt * 16 + qr;
            ahi[mt][0] = AsHi[br * TS + k8 + qc];
            ahi[mt][1] = AsHi[(br + 8) * TS + k8 + qc];
            ahi[mt][2] = AsHi[br * TS + k8 + 4 + qc];
            ahi[mt][3] = AsHi[(br + 8) * TS + k8 + 4 + qc];
            alo[mt][0] = AsLo[br * TS + k8 + qc];
            alo[mt][1] = AsLo[(br + 8) * TS + k8 + qc];
            alo[mt][2] = AsLo[br * TS + k8 + 4 + qc];
            alo[mt][3] = AsLo[(br + 8) * TS + k8 + 4 + qc];
        }
#pragma unroll
        for (int nt = 0; nt < 4; nt++) {
            int bn_ = wn * 32 + nt * 8 + qr;
            bhi[nt][0] = BsHi[bn_ * TS + k8 + qc];
            bhi[nt][1] = BsHi[bn_ * TS + k8 + 4 + qc];
            blo[nt][0] = BsLo[bn_ * TS + k8 + qc];
            blo[nt][1] = BsLo[bn_ * TS + k8 + 4 + qc];
        }
#pragma unroll
        for (int mt = 0; mt < 4; mt++)
#pragma unroll
            for (int nt = 0; nt < 4; nt++) {
                mma16816(acc[mt][nt], ahi[mt], bhi[nt]);
                mma16816(acc[mt][nt], ahi[mt], blo[nt]);
                mma16816(acc[mt][nt], alo[mt], bhi[nt]);
            }
    }
}

// ---------------------------------------------------------------------------
// mma_conv: cv1 3x3 conv (256->128) + BN + SiLU, implicit GEMM over 9 taps,
// 4-stage cp.async pipeline. Block = 128 pixels x 128 co.
// ---------------------------------------------------------------------------
__global__ __launch_bounds__(256) void mma_conv_k(
    const bf16* __restrict__ xhi, const bf16* __restrict__ xlo,
    const bf16* __restrict__ wth, const bf16* __restrict__ wtl,
    const float* __restrict__ g, const float* __restrict__ b,
    bf16* __restrict__ y1hi, bf16* __restrict__ y1lo)
{
    extern __shared__ __align__(16) uint32_t dsm[];
    const uint32_t sbase = (uint32_t)__cvta_generic_to_shared(dsm);

    const int tid = threadIdx.x, wid = tid >> 5, lane = tid & 31;
    const int wm = wid >> 2, wn = wid & 3, qr = lane >> 2, qc = lane & 3;
    const int pix0 = blockIdx.x * 128;
    const int n = pix0 >> 12, h0 = (pix0 & 4095) >> 6;
    const int r0 = tid >> 2, ch0 = tid & 3;

    float acc[4][4][4];
#pragma unroll
    for (int mt = 0; mt < 4; mt++)
#pragma unroll
        for (int nt = 0; nt < 4; nt++)
#pragma unroll
            for (int q = 0; q < 4; q++) acc[mt][nt][q] = 0.0f;

    const int TOT = 72;
    auto stage = [&](int it) {
        const int tap = it / 8, kc = it & 7;
        const int dh = tap / 3 - 1, dw = tap % 3 - 1;
        const uint32_t sb = sbase + (uint32_t)(it & 3) * (STW * 4);
#pragma unroll
        for (int i = 0; i < 2; i++) {
            int r = r0 + i * 64;
            uint32_t rowoff = (uint32_t)(r * TS + ch0 * 4) * 4;
            int hh = h0 + (r >> 6) + dh, ww = (r & 63) + dw;
            bool val = ((unsigned)hh < 64u) && ((unsigned)ww < 64u);
            size_t u4 = val ? ((size_t)(n * HW + hh * 64 + ww) * 32 + kc * 4 + ch0) : 0;
            int sz = val ? 16 : 0;
            cp16z(sb + rowoff,            (const char*)xhi + u4 * 16, sz);
            cp16z(sb + ARRW * 4 + rowoff, (const char*)xlo + u4 * 16, sz);
            size_t w4 = (size_t)(tap * CM + r) * 32 + kc * 4 + ch0;
            cp16(sb + 2 * ARRW * 4 + rowoff, (const char*)wth + w4 * 16);
            cp16(sb + 3 * ARRW * 4 + rowoff, (const char*)wtl + w4 * 16);
        }
    };

    stage(0); CP_COMMIT();
    stage(1); CP_COMMIT();
    for (int it = 0; it < TOT; it++) {
        if (it + 2 < TOT) stage(it + 2);
        CP_COMMIT();
        CP_WAIT2();
        __syncthreads();
        mma_tile_step(dsm + (it & 3) * STW, wm, wn, qr, qc, acc);
    }

    // ---- epilogue: BN + SiLU -> split hi/lo, NHWC [pix][128] ----
#pragma unroll
    for (int nt = 0; nt < 4; nt++) {
        int c = wn * 32 + nt * 8 + qc * 2;
        float s0 = g[c] * rsqrtf(1.0f + BN_EPS),     b0 = b[c];
        float s1 = g[c + 1] * rsqrtf(1.0f + BN_EPS), b1 = b[c + 1];
#pragma unroll
        for (int mt = 0; mt < 4; mt++) {
            int row = wm * 64 + mt * 16 + qr;
#pragma unroll
            for (int half = 0; half < 2; half++) {
                int pix = pix0 + row + half * 8;
                float v0 = silu(fmaf(acc[mt][nt][half * 2 + 0], s0, b0));
                float v1 = silu(fmaf(acc[mt][nt][half * 2 + 1], s1, b1));
                *(uint32_t*)&y1hi[(size_t)pix * CM + c] = pack_pair(v0, v1, false);
                *(uint32_t*)&y1lo[(size_t)pix * CM + c] = pack_pair(v0, v1, true);
            }
        }
    }
}

// ---------------------------------------------------------------------------
// mma_gemm: C[M,256] = A[M,K] @ W[256,K]^T, 4-stage cp.async pipeline.
// One block covers 128 pixels x full N=256 via two N-halves (grid = M/128).
// MODE 0: BN+SiLU -> f32 + hi/lo split.  MODE 1: +bias -> f32.
// ---------------------------------------------------------------------------
template<int K, int MODE>
__global__ __launch_bounds__(256) void mma_gemm_k(
    const bf16* __restrict__ Ahi, const bf16* __restrict__ Alo,
    const bf16* __restrict__ Whi, const bf16* __restrict__ Wlo,
    const float* __restrict__ p0, const float* __restrict__ p1,
    float* __restrict__ outf, bf16* __restrict__ outhi, bf16* __restrict__ outlo)
{
    extern __shared__ __align__(16) uint32_t dsm[];
    const uint32_t sbase = (uint32_t)__cvta_generic_to_shared(dsm);

    const int tid = threadIdx.x, wid = tid >> 5, lane = tid & 31;
    const int wm = wid >> 2, wn = wid & 3, qr = lane >> 2, qc = lane & 3;
    const int pix0 = blockIdx.x * 128;
    const int r0 = tid >> 2, ch0 = tid & 3;

    constexpr int NIT = K / 32;
    constexpr int TOT = 2 * NIT;          // two N-halves

    float acc[4][4][4];
#pragma unroll
    for (int mt = 0; mt < 4; mt++)
#pragma unroll
        for (int nt = 0; nt < 4; nt++)
#pragma unroll
            for (int q = 0; q < 4; q++) acc[mt][nt][q] = 0.0f;

    auto stage = [&](int it) {
        const int nh = it / NIT, kc = it % NIT;
        const uint32_t sb = sbase + (uint32_t)(it & 3) * (STW * 4);
#pragma unroll
        for (int i = 0; i < 2; i++) {
            int r = r0 + i * 64;
            uint32_t rowoff = (uint32_t)(r * TS + ch0 * 4) * 4;
            size_t a4 = (size_t)(pix0 + r) * (K / 8) + kc * 4 + ch0;
            cp16(sb + rowoff,            (const char*)Ahi + a4 * 16);
            cp16(sb + ARRW * 4 + rowoff, (const char*)Alo + a4 * 16);
            size_t b4 = (size_t)(nh * 128 + r) * (K / 8) + kc * 4 + ch0;
            cp16(sb + 2 * ARRW * 4 + rowoff, (const char*)Whi + b4 * 16);
            cp16(sb + 3 * ARRW * 4 + rowoff, (const char*)Wlo + b4 * 16);
        }
    };

    stage(0); CP_COMMIT();
    stage(1); CP_COMMIT();
    for (int it = 0; it < TOT; it++) {
        if (it + 2 < TOT) stage(it + 2);
        CP_COMMIT();
        CP_WAIT2();
        __syncthreads();
        mma_tile_step(dsm + (it & 3) * STW, wm, wn, qr, qc, acc);

        if ((it + 1) % NIT == 0) {
            // ---- epilogue for N-half nh ----
            const int nh = it / NIT;
#pragma unroll
            for (int nt = 0; nt < 4; nt++) {
                int c = nh * 128 + wn * 32 + nt * 8 + qc * 2;
                float s0, b0, s1, b1;
                if (MODE == 0) {
                    s0 = p0[c] * rsqrtf(1.0f + BN_EPS);     b0 = p1[c];
                    s1 = p0[c + 1] * rsqrtf(1.0f + BN_EPS); b1 = p1[c + 1];
                } else {
                    b0 = p0[c]; b1 = p0[c + 1]; s0 = s1 = 1.0f;
                }
#pragma unroll
                for (int mt = 0; mt < 4; mt++) {
                    int row = wm * 64 + mt * 16 + qr;
#pragma unroll
                    for (int half = 0; half < 2; half++) {
                        int pix = pix0 + row + half * 8;
                        float v0, v1;
                        if (MODE == 0) {
                            v0 = silu(fmaf(acc[mt][nt][half * 2 + 0], s0, b0));
                            v1 = silu(fmaf(acc[mt][nt][half * 2 + 1], s1, b1));
                        } else {
                            v0 = acc[mt][nt][half * 2 + 0] + b0;
                            v1 = acc[mt][nt][half * 2 + 1] + b1;
                        }
                        *(float2*)&outf[(size_t)pix * C2 + c] = make_float2(v0, v1);
                        if (MODE == 0) {
                            *(uint32_t*)&outhi[(size_t)pix * C2 + c] = pack_pair(v0, v1, false);
                            *(uint32_t*)&outlo[(size_t)pix * C2 + c] = pack_pair(v0, v1, true);
                        }
                    }
                }
            }
#pragma unroll
            for (int mt = 0; mt < 4; mt++)
#pragma unroll
                for (int nt = 0; nt < 4; nt++)
#pragma unroll
                    for (int q = 0; q < 4; q++) acc[mt][nt][q] = 0.0f;
        }
    }
}

// ---------------------------------------------------------------------------
// Fused: depthwise 3x3 + LN + GELU + offset/mask heads
// ---------------------------------------------------------------------------
__global__ __launch_bounds__(256) void dw_ln_gelu_offmask_k(
    const float* __restrict__ y2,
    const float* __restrict__ dww, const float* __restrict__ dwb,
    const float* __restrict__ lg,  const float* __restrict__ lb,
    const float* __restrict__ offw, const float* __restrict__ offb,
    const float* __restrict__ mskw, const float* __restrict__ mskb,
    float* __restrict__ om)
{
    const int pix = blockIdx.x;
    const int n = pix >> 12, hw = pix & 4095, h = hw >> 6, w = hw & 63;
    const int c = threadIdx.x;

    float v = dwb[c];
#pragma unroll
    for (int kh = 0; kh < 3; kh++)
#pragma unroll
        for (int kw = 0; kw < 3; kw++) {
            int hh = h + kh - 1, wk = w + kw - 1;
            if ((unsigned)hh < 64u && (unsigned)wk < 64u)
                v = fmaf(y2[(((size_t)n * HW) + hh * 64 + wk) * C2 + c],
                         dww[c * 9 + kh * 3 + kw], v);
        }

    __shared__ float s1[256];
    __shared__ float s2[256];
    __shared__ float logits[32];
    s1[c] = v; s2[c] = v * v;
    __syncthreads();
#pragma unroll
    for (int off = 128; off > 32; off >>= 1) {
        if (c < off) { s1[c] += s1[c + off]; s2[c] += s2[c + off]; }
        __syncthreads();
    }
    if (c < 32) {
        float a1 = s1[c] + s1[c + 32];
        float a2 = s2[c] + s2[c + 32];
#pragma unroll
        for (int o = 16; o > 0; o >>= 1) {
            a1 += __shfl_down_sync(0xffffffffu, a1, o);
            a2 += __shfl_down_sync(0xffffffffu, a2, o);
        }
        if (c == 0) { s1[0] = a1; s2[0] = a2; }
    }
    __syncthreads();
    float mean = s1[0] * (1.0f / 256.0f);
    float var  = s2[0] * (1.0f / 256.0f) - mean * mean;

    float t = fmaf((v - mean) * rsqrtf(var + LN_EPS), lg[c], lb[c]);
    float gelu = 0.5f * t * (1.0f + erff(t * 0.70710678118654752f));

    __syncthreads();
    s1[c] = gelu;
    __syncthreads();

    const int lane = c & 31, wp = c >> 5;
#pragma unroll
    for (int j0 = 0; j0 < 32; j0 += 8) {
        int j = j0 + wp;
        if (j < 27) {
            const float* wrow = (j < 18) ? (offw + (size_t)j * C2)
                                         : (mskw + (size_t)(j - 18) * C2);
            float s = 0.0f;
#pragma unroll
            for (int tci = lane; tci < C2; tci += 32) s = fmaf(s1[tci], wrow[tci], s);
#pragma unroll
            for (int o = 16; o > 0; o >>= 1) s += __shfl_down_sync(0xffffffffu, s, o);
            if (lane == 0) logits[j] = s + ((j < 18) ? offb[j] : mskb[j - 18]);
        }
    }
    __syncthreads();

    if (c < 18) om[(size_t)pix * 27 + c] = logits[c];
    if (c == 0) {
        float mx = -1e30f;
#pragma unroll
        for (int q = 0; q < 9; q++) mx = fmaxf(mx, logits[18 + q]);
        float e[9], sum = 0.0f;
#pragma unroll
        for (int q = 0; q < 9; q++) { e[q] = expf(logits[18 + q] - mx); sum += e[q]; }
        float inv = 1.0f / sum;
#pragma unroll
        for (int q = 0; q < 9; q++) om[(size_t)pix * 27 + 18 + q] = e[q] * inv;
    }
}

// ---------------------------------------------------------------------------
// DCNv3 core -> split hi/lo bf16
// ---------------------------------------------------------------------------
__global__ __launch_bounds__(256) void dcnv3_k(
    const float* __restrict__ xproj, const float* __restrict__ om,
    bf16* __restrict__ chi, bf16* __restrict__ clo)
{
    const int pix = blockIdx.x;
    const int n = pix >> 12, hw = pix & 4095, h = hw >> 6, w = hw & 63;
    const int c = threadIdx.x;

    __shared__ float o[32];
    if (c < 27) o[c] = om[(size_t)pix * 27 + c];
    __syncthreads();

    const float* base = xproj + (size_t)n * HW * C2;
    float acc = 0.0f;

#pragma unroll
    for (int p = 0; p < PP; p++) {
        float px = (float)(w + (p / 3)) + o[2 * p];
        float py = (float)(h + (p % 3)) + o[2 * p + 1];
        float x0f = floorf(px), y0f = floorf(py);
        float fx = px - x0f, fy = py - y0f;
        int x0 = (int)x0f, y0 = (int)y0f;
        float mk = o[18 + p];
        float s = 0.0f;
#pragma unroll
        for (int dy = 0; dy < 2; dy++)
#pragma unroll
            for (int dx = 0; dx < 2; dx++) {
                int xi = x0 + dx, yi = y0 + dy;
                if (xi >= 1 && xi <= 64 && yi >= 1 && yi <= 64) {
                    float wgt = (dx ? fx : 1.0f - fx) * (dy ? fy : 1.0f - fy);
                    s = fmaf(wgt, base[((size_t)(yi - 1) * 64 + (xi - 1)) * C2 + c], s);
                }
            }
        acc = fmaf(mk, s, acc);
    }
    bf16 hb, lb2; split_bf(acc, hb, lb2);
    chi[(size_t)pix * C2 + c] = hb;
    clo[(size_t)pix * C2 + c] = lb2;
}

// ---------------------------------------------------------------------------
// NHWC->NCHW + BN2 + SiLU + residual
// ---------------------------------------------------------------------------
__global__ __launch_bounds__(256) void bn2_res_transpose_k(
    const float* __restrict__ o, const float* __restrict__ xres,
    const float* __restrict__ g, const float* __restrict__ b,
    float* __restrict__ out)
{
    __shared__ float t[32][33];
    const int n = blockIdx.z, hw0 = blockIdx.x * 32, c0 = blockIdx.y * 32;
    const int tx = threadIdx.x & 31, ty = threadIdx.x >> 5;
#pragma unroll
    for (int i = ty; i < 32; i += 8)
        t[i][tx] = o[((size_t)n * HW + hw0 + i) * C2 + c0 + tx];
    __syncthreads();
#pragma unroll
    for (int i = ty; i < 32; i += 8) {
        int c = c0 + i, hw = hw0 + tx;
        float v = t[tx][i];
        float s = g[c] * rsqrtf(1.0f + BN_EPS);
        v = silu(fmaf(v, s, b[c]));
        size_t idx = ((size_t)n * C2 + c) * HW + hw;
        out[idx] = xres[idx] + v;
    }
}

// ---------------------------------------------------------------------------
// Launch
// ---------------------------------------------------------------------------
extern "C" void kernel_launch(void* const* d_in, const int* in_sizes, int n_in,
                              void* d_out, int out_size) {
    const float* x     = (const float*)d_in[0];
    const float* cv1_w = (const float*)d_in[1];
    const float* cv1_g = (const float*)d_in[2];
    const float* cv1_b = (const float*)d_in[3];
    const float* pw_w  = (const float*)d_in[4];
    const float* pw_g  = (const float*)d_in[5];
    const float* pw_b  = (const float*)d_in[6];
    const float* dw_w  = (const float*)d_in[7];
    const float* dw_b  = (const float*)d_in[8];
    const float* ln_g  = (const float*)d_in[9];
    const float* ln_b  = (const float*)d_in[10];
    const float* off_w = (const float*)d_in[11];
    const float* off_b = (const float*)d_in[12];
    const float* msk_w = (const float*)d_in[13];
    const float* msk_b = (const float*)d_in[14];
    const float* inp_w = (const float*)d_in[15];
    const float* inp_b = (const float*)d_in[16];
    const float* out_w = (const float*)d_in[17];
    const float* out_b = (const float*)d_in[18];
    const float* bn2_g = (const float*)d_in[19];
    const float* bn2_b = (const float*)d_in[20];

    float* sc = nullptr;
    cudaGetSymbolAddress((void**)&sc, g_scratch);
    bf16* xhi  = (bf16*)(sc + OFF_XHI);
    bf16* xlo  = (bf16*)(sc + OFF_XLO);
    bf16* y1hi = (bf16*)(sc + OFF_Y1HI);
    bf16* y1lo = (bf16*)(sc + OFF_Y1LO);
    float* y2f = sc + OFF_Y2F;
    bf16* y2hi = (bf16*)(sc + OFF_Y2HI);
    bf16* y2lo = (bf16*)(sc + OFF_Y2LO);
    float* xproj = sc + OFF_XPROJ;
    float* om    = sc + OFF_OM;
    bf16* chi  = (bf16*)(sc + OFF_CHI);
    bf16* clo  = (bf16*)(sc + OFF_CLO);
    float* onh = sc + OFF_ONH;
    bf16* wt9h = (bf16*)(sc + OFF_WT9H);
    bf16* wt9l = (bf16*)(sc + OFF_WT9L);
    bf16* pwh  = (bf16*)(sc + OFF_PWH);
    bf16* pwl  = (bf16*)(sc + OFF_PWL);
    bf16* inh  = (bf16*)(sc + OFF_INH);
    bf16* inl  = (bf16*)(sc + OFF_INL);
    bf16* ouh  = (bf16*)(sc + OFF_OUH);
    bf16* oul  = (bf16*)(sc + OFF_OUL);
    float* outp = (float*)d_out;

    cudaFuncSetAttribute(mma_conv_k, cudaFuncAttributeMaxDynamicSharedMemorySize, SMEM_PIPE_BYTES);
    cudaFuncSetAttribute(mma_gemm_k<128, 0>, cudaFuncAttributeMaxDynamicSharedMemorySize, SMEM_PIPE_BYTES);
    cudaFuncSetAttribute(mma_gemm_k<256, 1>, cudaFuncAttributeMaxDynamicSharedMemorySize, SMEM_PIPE_BYTES);

    // 0) preprocessing
    prep_x_k<<<dim3(HW / 32, C1 / 32, NB), 256>>>(x, xhi, xlo);
    prep_w_k<<<(9 * CM * C1 + C2 * CM + 2 * C2 * C2 + 255) / 256, 256>>>(
        cv1_w, pw_w, inp_w, out_w, wt9h, wt9l, pwh, pwl, inh, inl, ouh, oul);

    // 1) cv1 (mma, pipelined) -> y1 hi/lo (NHWC bf16)
    mma_conv_k<<<NPIX / 128, 256, SMEM_PIPE_BYTES>>>(
        xhi, xlo, wt9h, wt9l, cv1_g, cv1_b, y1hi, y1lo);

    // 2) pw (mma, pipelined) -> y2 f32 + hi/lo
    mma_gemm_k<128, 0><<<NPIX / 128, 256, SMEM_PIPE_BYTES>>>(
        y1hi, y1lo, pwh, pwl, pw_g, pw_b, y2f, y2hi, y2lo);

    // 3) fused dw + LN + GELU + heads -> om
    dw_ln_gelu_offmask_k<<<NPIX, 256>>>(y2f, dw_w, dw_b, ln_g, ln_b,
                                        off_w, off_b, msk_w, msk_b, om);

    // 4) input_proj (mma, pipelined) -> xproj f32
    mma_gemm_k<256, 1><<<NPIX / 128, 256, SMEM_PIPE_BYTES>>>(
        y2hi, y2lo, inh, inl, inp_b, nullptr, xproj, nullptr, nullptr);

    // 5) DCNv3 core -> hi/lo
    dcnv3_k<<<NPIX, 256>>>(xproj, om, chi, clo);

    // 6) output_proj (mma, pipelined) -> onh f32
    mma_gemm_k<256, 1><<<NPIX / 128, 256, SMEM_PIPE_BYTES>>>(
        chi, clo, ouh, oul, out_b, nullptr, onh, nullptr, nullptr);

    // 7) BN2 + SiLU + residual + transpose -> d_out
    bn2_res_transpose_k<<<dim3(HW / 32, C2 / 32, NB), 256>>>(onh, x, bn2_g, bn2_b, outp);
}

// round 7
// speedup vs baseline: 3.7282x; 1.0515x over previous
#include <cuda_runtime.h>
#include <cuda_fp16.h>
#include <math.h>
#include <stdint.h>

// ---------------------------------------------------------------------------
// Problem constants
// ---------------------------------------------------------------------------
#define NB   4
#define C1   256
#define CM   128
#define C2   256
#define HW   4096
#define NPIX (NB*HW)
#define PP   9
#define BN_EPS 1e-5f
#define LN_EPS 1e-6f

typedef __half hlf;

// ---------------------------------------------------------------------------
// Scratch (offsets in floats)
// ---------------------------------------------------------------------------
#define OFF_XHI   0                         // NPIX*C1 fp16
#define OFF_XLO   (OFF_XHI  + NPIX*C1/2)
#define OFF_Y1HI  (OFF_XLO  + NPIX*C1/2)    // NPIX*CM fp16
#define OFF_Y1LO  (OFF_Y1HI + NPIX*CM/2)
#define OFF_Y2F   (OFF_Y1LO + NPIX*CM/2)    // NPIX*C2 f32
#define OFF_Y2HI  (OFF_Y2F  + NPIX*C2)
#define OFF_Y2LO  (OFF_Y2HI + NPIX*C2/2)
#define OFF_XPROJ (OFF_Y2LO + NPIX*C2/2)    // f32
#define OFF_OM    (OFF_XPROJ+ NPIX*C2)      // NPIX*27 f32
#define OFF_CHI   (OFF_OM   + NPIX*27)
#define OFF_CLO   (OFF_CHI  + NPIX*C2/2)
#define OFF_ONH   (OFF_CLO  + NPIX*C2/2)    // f32
#define OFF_WT9H  (OFF_ONH  + NPIX*C2)      // 9*128*256 fp16, [tap][co][ci]
#define OFF_PWH   (OFF_WT9H + 9*CM*C1/2)    // 256*128 fp16
#define OFF_PWL   (OFF_PWH  + C2*CM/2)
#define OFF_INH   (OFF_PWL  + C2*CM/2)      // 256*256 fp16
#define OFF_INL   (OFF_INH  + C2*C2/2)
#define OFF_OUH   (OFF_INL  + C2*C2/2)
#define OFF_OUL   (OFF_OUH  + C2*C2/2)
#define SCRATCH_FLOATS (OFF_OUL + C2*C2/2)

__device__ __align__(16) float g_scratch[SCRATCH_FLOATS];

__device__ __forceinline__ float silu(float v) { return v / (1.0f + expf(-v)); }

__device__ __forceinline__ void split_h(float v, hlf& h, hlf& l) {
    h = __float2half_rn(v);
    l = __float2half_rn(v - __half2float(h));
}
__device__ __forceinline__ uint32_t pack_pair(float a, float b, bool lo) {
    hlf ha, la, hb, lbv;
    split_h(a, ha, la); split_h(b, hb, lbv);
    if (!lo) return ((uint32_t)*(uint16_t*)&hb << 16) | *(uint16_t*)&ha;
    else     return ((uint32_t)*(uint16_t*)&lbv << 16) | *(uint16_t*)&la;
}

// ---------------------------------------------------------------------------
// mma.sync m16n8k16 fp16 + cp.async (portable sm_80 PTX)
// ---------------------------------------------------------------------------
__device__ __forceinline__ void mma16816(float* d, const uint32_t* a, const uint32_t* b) {
    asm volatile("mma.sync.aligned.m16n8k16.row.col.f32.f16.f16.f32 "
        "{%0,%1,%2,%3}, {%4,%5,%6,%7}, {%8,%9}, {%0,%1,%2,%3};"
        : "+f"(d[0]), "+f"(d[1]), "+f"(d[2]), "+f"(d[3])
        : "r"(a[0]), "r"(a[1]), "r"(a[2]), "r"(a[3]), "r"(b[0]), "r"(b[1]));
}
__device__ __forceinline__ void cp16(uint32_t dst, const void* src) {
    asm volatile("cp.async.cg.shared.global [%0], [%1], 16;" :: "r"(dst), "l"(src));
}
__device__ __forceinline__ void cp16z(uint32_t dst, const void* src, int srcsize) {
    asm volatile("cp.async.cg.shared.global [%0], [%1], 16, %2;"
                 :: "r"(dst), "l"(src), "r"(srcsize));
}
#define CP_COMMIT() asm volatile("cp.async.commit_group;" ::: "memory")
#define CP_WAIT1()  asm volatile("cp.async.wait_group 1;" ::: "memory")

// SMEM row: 32 fp16 = 16 words, padded to 20 (bank-conflict-free)
#define TS 20
#define AW  (64 * TS)            // A tile: 64 rows
#define BW  (128 * TS)           // B tile: 128 rows
// conv stage: AHi | ALo | BHi                 = 2*AW + BW   = 5120 w = 20480 B
// gemm stage: AHi | ALo | BHi | BLo           = 2*AW + 2*BW = 7680 w = 30720 B
#define CONV_STW (2*AW + BW)
#define GEMM_STW (2*AW + 2*BW)
#define CONV_SMEM (2 * CONV_STW * 4)
#define GEMM_SMEM (2 * GEMM_STW * 4)

// ---------------------------------------------------------------------------
// prep_x: NCHW f32 -> NHWC fp16 hi/lo
// ---------------------------------------------------------------------------
__global__ __launch_bounds__(256) void prep_x_k(
    const float* __restrict__ x, hlf* __restrict__ xhi, hlf* __restrict__ xlo)
{
    __shared__ float t[32][33];
    const int n = blockIdx.z, hw0 = blockIdx.x * 32, c0 = blockIdx.y * 32;
    const int tx = threadIdx.x & 31, ty = threadIdx.x >> 5;
#pragma unroll
    for (int i = ty; i < 32; i += 8)
        t[i][tx] = x[((size_t)n * C1 + c0 + i) * HW + hw0 + tx];
    __syncthreads();
#pragma unroll
    for (int i = ty; i < 32; i += 8) {
        float v = t[tx][i];
        hlf h, l; split_h(v, h, l);
        size_t idx = ((size_t)n * HW + hw0 + i) * C1 + c0 + tx;
        xhi[idx] = h; xlo[idx] = l;
    }
}

// ---------------------------------------------------------------------------
// prep_w: split weights to fp16; cv1 -> [tap][co][ci] (hi only)
// ---------------------------------------------------------------------------
__global__ __launch_bounds__(256) void prep_w_k(
    const float* __restrict__ cv1w, const float* __restrict__ pww,
    const float* __restrict__ inpw, const float* __restrict__ outw,
    hlf* __restrict__ wt9h,
    hlf* __restrict__ pwh,  hlf* __restrict__ pwl,
    hlf* __restrict__ inh,  hlf* __restrict__ inl,
    hlf* __restrict__ ouh,  hlf* __restrict__ oul)
{
    int idx = blockIdx.x * 256 + threadIdx.x;
    const int N1 = 9 * CM * C1;
    if (idx < N1) {
        int tap = idx / (CM * C1);
        int rem = idx - tap * CM * C1;
        int co = rem >> 8, ci = rem & 255;
        wt9h[idx] = __float2half_rn(cv1w[(size_t)co * (C1 * 9) + ci * 9 + tap]);
        return;
    }
    idx -= N1;
    if (idx < C2 * CM) {
        hlf h, l; split_h(pww[idx], h, l);
        pwh[idx] = h; pwl[idx] = l; return;
    }
    idx -= C2 * CM;
    if (idx < C2 * C2) {
        hlf h, l; split_h(inpw[idx], h, l);
        inh[idx] = h; inl[idx] = l; return;
    }
    idx -= C2 * C2;
    if (idx < C2 * C2) {
        hlf h, l; split_h(outw[idx], h, l);
        ouh[idx] = h; oul[idx] = l;
    }
}

// ---------------------------------------------------------------------------
// Inner MMA: A tile 64x32 (hi/lo), B tile 128x32 (hi [+lo]). Warp grid 2x4.
// TERMS=2: h*h + lA*h.  TERMS=3: + hA*lB.
// ---------------------------------------------------------------------------
template<int TERMS>
__device__ __forceinline__ void mma_step(
    const uint32_t* __restrict__ st, int wm, int wn, int qr, int qc, float acc[2][4][4])
{
    const uint32_t* AsHi = st;
    const uint32_t* AsLo = st + AW;
    const uint32_t* BsHi = st + 2 * AW;
    const uint32_t* BsLo = st + 2 * AW + BW;
#pragma unroll
    for (int ks = 0; ks < 2; ks++) {
        const int k8 = ks * 8;
        uint32_t ahi[2][4], alo[2][4], bhi[4][2], blo[4][2];
#pragma unroll
        for (int mt = 0; mt < 2; mt++) {
            int br = wm * 32 + mt * 16 + qr;
            ahi[mt][0] = AsHi[br * TS + k8 + qc];
            ahi[mt][1] = AsHi[(br + 8) * TS + k8 + qc];
            ahi[mt][2] = AsHi[br * TS + k8 + 4 + qc];
            ahi[mt][3] = AsHi[(br + 8) * TS + k8 + 4 + qc];
            alo[mt][0] = AsLo[br * TS + k8 + qc];
            alo[mt][1] = AsLo[(br + 8) * TS + k8 + qc];
            alo[mt][2] = AsLo[br * TS + k8 + 4 + qc];
            alo[mt][3] = AsLo[(br + 8) * TS + k8 + 4 + qc];
        }
#pragma unroll
        for (int nt = 0; nt < 4; nt++) {
            int bn_ = wn * 32 + nt * 8 + qr;
            bhi[nt][0] = BsHi[bn_ * TS + k8 + qc];
            bhi[nt][1] = BsHi[bn_ * TS + k8 + 4 + qc];
            if (TERMS == 3) {
                blo[nt][0] = BsLo[bn_ * TS + k8 + qc];
                blo[nt][1] = BsLo[bn_ * TS + k8 + 4 + qc];
            }
        }
#pragma unroll
        for (int mt = 0; mt < 2; mt++)
#pragma unroll
            for (int nt = 0; nt < 4; nt++) {
                mma16816(acc[mt][nt], ahi[mt], bhi[nt]);
                mma16816(acc[mt][nt], alo[mt], bhi[nt]);
                if (TERMS == 3) mma16816(acc[mt][nt], ahi[mt], blo[nt]);
            }
    }
}

// ---------------------------------------------------------------------------
// mma_conv: cv1 3x3 (256->128) + BN + SiLU. Block = 64 pixels (one image row)
// x 128 co. 2-term fp16 split (== fp16-quantized weights). 2-stage cp.async.
// ---------------------------------------------------------------------------
__global__ __launch_bounds__(256, 2) void mma_conv_k(
    const hlf* __restrict__ xhi, const hlf* __restrict__ xlo,
    const hlf* __restrict__ wth,
    const float* __restrict__ g, const float* __restrict__ b,
    hlf* __restrict__ y1hi, hlf* __restrict__ y1lo)
{
    extern __shared__ __align__(16) uint32_t dsm[];
    const uint32_t sbase = (uint32_t)__cvta_generic_to_shared(dsm);

    const int tid = threadIdx.x, wid = tid >> 5, lane = tid & 31;
    const int wm = wid >> 2, wn = wid & 3, qr = lane >> 2, qc = lane & 3;
    const int pix0 = blockIdx.x * 64;
    const int n = pix0 >> 12, hb = (pix0 & 4095) >> 6;   // one image row per block
    const int r0 = tid >> 2, ch0 = tid & 3;

    float acc[2][4][4];
#pragma unroll
    for (int mt = 0; mt < 2; mt++)
#pragma unroll
        for (int nt = 0; nt < 4; nt++)
#pragma unroll
            for (int q = 0; q < 4; q++) acc[mt][nt][q] = 0.0f;

    const int TOT = 72;
    auto stage = [&](int it) {
        const int tap = it / 8, kc = it & 7;
        const int dh = tap / 3 - 1, dw = tap % 3 - 1;
        const uint32_t sb = sbase + (uint32_t)(it & 1) * (CONV_STW * 4);
        // A: 64 rows (pixels), hi+lo
        {
            int hh = hb + dh, ww = r0 + dw;
            bool val = ((unsigned)hh < 64u) && ((unsigned)ww < 64u);
            size_t u4 = val ? ((size_t)(n * HW + hh * 64 + ww) * 32 + kc * 4 + ch0) : 0;
            int sz = val ? 16 : 0;
            uint32_t rowoff = (uint32_t)(r0 * TS + ch0 * 4) * 4;
            cp16z(sb + rowoff,          (const char*)xhi + u4 * 16, sz);
            cp16z(sb + AW * 4 + rowoff, (const char*)xlo + u4 * 16, sz);
        }
        // B: 128 rows (co), hi only
#pragma unroll
        for (int i = 0; i < 2; i++) {
            int r = r0 + i * 64;
            size_t w4 = (size_t)(tap * CM + r) * 32 + kc * 4 + ch0;
            uint32_t rowoff = (uint32_t)(r * TS + ch0 * 4) * 4;
            cp16(sb + 2 * AW * 4 + rowoff, (const char*)wth + w4 * 16);
        }
    };

    stage(0); CP_COMMIT();
    for (int it = 0; it < TOT; it++) {
        if (it + 1 < TOT) stage(it + 1);
        CP_COMMIT();
        CP_WAIT1();
        __syncthreads();
        mma_step<2>(dsm + (it & 1) * CONV_STW, wm, wn, qr, qc, acc);
        __syncthreads();
    }

    // ---- epilogue: BN + SiLU -> split hi/lo, NHWC [pix][128] ----
#pragma unroll
    for (int nt = 0; nt < 4; nt++) {
        int c = wn * 32 + nt * 8 + qc * 2;
        float s0 = g[c] * rsqrtf(1.0f + BN_EPS),     b0 = b[c];
        float s1 = g[c + 1] * rsqrtf(1.0f + BN_EPS), b1 = b[c + 1];
#pragma unroll
        for (int mt = 0; mt < 2; mt++) {
            int row = wm * 32 + mt * 16 + qr;
#pragma unroll
            for (int half = 0; half < 2; half++) {
                int pix = pix0 + row + half * 8;
                float v0 = silu(fmaf(acc[mt][nt][half * 2 + 0], s0, b0));
                float v1 = silu(fmaf(acc[mt][nt][half * 2 + 1], s1, b1));
                *(uint32_t*)&y1hi[(size_t)pix * CM + c] = pack_pair(v0, v1, false);
                *(uint32_t*)&y1lo[(size_t)pix * CM + c] = pack_pair(v0, v1, true);
            }
        }
    }
}

// ---------------------------------------------------------------------------
// mma_gemm: C[M,256] = A[M,K] @ W[256,K]^T, 3-term fp16 split, 2-stage pipe.
// Block = 64 pixels x 128 N (grid.y = n-half).
// MODE 0: BN+SiLU -> f32 + hi/lo split.  MODE 1: +bias -> f32.
// ---------------------------------------------------------------------------
template<int K, int MODE>
__global__ __launch_bounds__(256, 2) void mma_gemm_k(
    const hlf* __restrict__ Ahi, const hlf* __restrict__ Alo,
    const hlf* __restrict__ Whi, const hlf* __restrict__ Wlo,
    const float* __restrict__ p0, const float* __restrict__ p1,
    float* __restrict__ outf, hlf* __restrict__ outhi, hlf* __restrict__ outlo)
{
    extern __shared__ __align__(16) uint32_t dsm[];
    const uint32_t sbase = (uint32_t)__cvta_generic_to_shared(dsm);

    const int tid = threadIdx.x, wid = tid >> 5, lane = tid & 31;
    const int wm = wid >> 2, wn = wid & 3, qr = lane >> 2, qc = lane & 3;
    const int pix0 = blockIdx.x * 64;
    const int nh = blockIdx.y;
    const int r0 = tid >> 2, ch0 = tid & 3;

    constexpr int TOT = K / 32;

    float acc[2][4][4];
#pragma unroll
    for (int mt = 0; mt < 2; mt++)
#pragma unroll
        for (int nt = 0; nt < 4; nt++)
#pragma unroll
            for (int q = 0; q < 4; q++) acc[mt][nt][q] = 0.0f;

    auto stage = [&](int it) {
        const int kc = it;
        const uint32_t sb = sbase + (uint32_t)(it & 1) * (GEMM_STW * 4);
        {
            size_t a4 = (size_t)(pix0 + r0) * (K / 8) + kc * 4 + ch0;
            uint32_t rowoff = (uint32_t)(r0 * TS + ch0 * 4) * 4;
            cp16(sb + rowoff,          (const char*)Ahi + a4 * 16);
            cp16(sb + AW * 4 + rowoff, (const char*)Alo + a4 * 16);
        }
#pragma unroll
        for (int i = 0; i < 2; i++) {
            int r = r0 + i * 64;
            size_t b4 = (size_t)(nh * 128 + r) * (K / 8) + kc * 4 + ch0;
            uint32_t rowoff = (uint32_t)(r * TS + ch0 * 4) * 4;
            cp16(sb + 2 * AW * 4 + rowoff,            (const char*)Whi + b4 * 16);
            cp16(sb + (2 * AW + BW) * 4 + rowoff,     (const char*)Wlo + b4 * 16);
        }
    };

    stage(0); CP_COMMIT();
    for (int it = 0; it < TOT; it++) {
        if (it + 1 < TOT) stage(it + 1);
        CP_COMMIT();
        CP_WAIT1();
        __syncthreads();
        mma_step<3>(dsm + (it & 1) * GEMM_STW, wm, wn, qr, qc, acc);
        __syncthreads();
    }

    // ---- epilogue ----
#pragma unroll
    for (int nt = 0; nt < 4; nt++) {
        int c = nh * 128 + wn * 32 + nt * 8 + qc * 2;
        float s0, b0, s1, b1;
        if (MODE == 0) {
            s0 = p0[c] * rsqrtf(1.0f + BN_EPS);     b0 = p1[c];
            s1 = p0[c + 1] * rsqrtf(1.0f + BN_EPS); b1 = p1[c + 1];
        } else {
            b0 = p0[c]; b1 = p0[c + 1]; s0 = s1 = 1.0f;
        }
#pragma unroll
        for (int mt = 0; mt < 2; mt++) {
            int row = wm * 32 + mt * 16 + qr;
#pragma unroll
            for (int half = 0; half < 2; half++) {
                int pix = pix0 + row + half * 8;
                float v0, v1;
                if (MODE == 0) {
                    v0 = silu(fmaf(acc[mt][nt][half * 2 + 0], s0, b0));
                    v1 = silu(fmaf(acc[mt][nt][half * 2 + 1], s1, b1));
                } else {
                    v0 = acc[mt][nt][half * 2 + 0] + b0;
                    v1 = acc[mt][nt][half * 2 + 1] + b1;
                }
                *(float2*)&outf[(size_t)pix * C2 + c] = make_float2(v0, v1);
                if (MODE == 0) {
                    *(uint32_t*)&outhi[(size_t)pix * C2 + c] = pack_pair(v0, v1, false);
                    *(uint32_t*)&outlo[(size_t)pix * C2 + c] = pack_pair(v0, v1, true);
                }
            }
        }
    }
}

// ---------------------------------------------------------------------------
// Fused: depthwise 3x3 + LN + GELU + offset/mask heads
// ---------------------------------------------------------------------------
__global__ __launch_bounds__(256) void dw_ln_gelu_offmask_k(
    const float* __restrict__ y2,
    const float* __restrict__ dww, const float* __restrict__ dwb,
    const float* __restrict__ lg,  const float* __restrict__ lb,
    const float* __restrict__ offw, const float* __restrict__ offb,
    const float* __restrict__ mskw, const float* __restrict__ mskb,
    float* __restrict__ om)
{
    const int pix = blockIdx.x;
    const int n = pix >> 12, hw = pix & 4095, h = hw >> 6, w = hw & 63;
    const int c = threadIdx.x;

    float v = dwb[c];
#pragma unroll
    for (int kh = 0; kh < 3; kh++)
#pragma unroll
        for (int kw = 0; kw < 3; kw++) {
            int hh = h + kh - 1, wk = w + kw - 1;
            if ((unsigned)hh < 64u && (unsigned)wk < 64u)
                v = fmaf(y2[(((size_t)n * HW) + hh * 64 + wk) * C2 + c],
                         dww[c * 9 + kh * 3 + kw], v);
        }

    __shared__ float s1[256];
    __shared__ float s2[256];
    __shared__ float logits[32];
    s1[c] = v; s2[c] = v * v;
    __syncthreads();
#pragma unroll
    for (int off = 128; off > 32; off >>= 1) {
        if (c < off) { s1[c] += s1[c + off]; s2[c] += s2[c + off]; }
        __syncthreads();
    }
    if (c < 32) {
        float a1 = s1[c] + s1[c + 32];
        float a2 = s2[c] + s2[c + 32];
#pragma unroll
        for (int o = 16; o > 0; o >>= 1) {
            a1 += __shfl_down_sync(0xffffffffu, a1, o);
            a2 += __shfl_down_sync(0xffffffffu, a2, o);
        }
        if (c == 0) { s1[0] = a1; s2[0] = a2; }
    }
    __syncthreads();
    float mean = s1[0] * (1.0f / 256.0f);
    float var  = s2[0] * (1.0f / 256.0f) - mean * mean;

    float t = fmaf((v - mean) * rsqrtf(var + LN_EPS), lg[c], lb[c]);
    float gelu = 0.5f * t * (1.0f + erff(t * 0.70710678118654752f));

    __syncthreads();
    s1[c] = gelu;
    __syncthreads();

    const int lane = c & 31, wp = c >> 5;
#pragma unroll
    for (int j0 = 0; j0 < 32; j0 += 8) {
        int j = j0 + wp;
        if (j < 27) {
            const float* wrow = (j < 18) ? (offw + (size_t)j * C2)
                                         : (mskw + (size_t)(j - 18) * C2);
            float s = 0.0f;
#pragma unroll
            for (int tci = lane; tci < C2; tci += 32) s = fmaf(s1[tci], wrow[tci], s);
#pragma unroll
            for (int o = 16; o > 0; o >>= 1) s += __shfl_down_sync(0xffffffffu, s, o);
            if (lane == 0) logits[j] = s + ((j < 18) ? offb[j] : mskb[j - 18]);
        }
    }
    __syncthreads();

    if (c < 18) om[(size_t)pix * 27 + c] = logits[c];
    if (c == 0) {
        float mx = -1e30f;
#pragma unroll
        for (int q = 0; q < 9; q++) mx = fmaxf(mx, logits[18 + q]);
        float e[9], sum = 0.0f;
#pragma unroll
        for (int q = 0; q < 9; q++) { e[q] = expf(logits[18 + q] - mx); sum += e[q]; }
        float inv = 1.0f / sum;
#pragma unroll
        for (int q = 0; q < 9; q++) om[(size_t)pix * 27 + 18 + q] = e[q] * inv;
    }
}

// ---------------------------------------------------------------------------
// DCNv3 core -> split hi/lo fp16
// ---------------------------------------------------------------------------
__global__ __launch_bounds__(256) void dcnv3_k(
    const float* __restrict__ xproj, const float* __restrict__ om,
    hlf* __restrict__ chi, hlf* __restrict__ clo)
{
    const int pix = blockIdx.x;
    const int n = pix >> 12, hw = pix & 4095, h = hw >> 6, w = hw & 63;
    const int c = threadIdx.x;

    __shared__ float o[32];
    if (c < 27) o[c] = om[(size_t)pix * 27 + c];
    __syncthreads();

    const float* base = xproj + (size_t)n * HW * C2;
    float acc = 0.0f;

#pragma unroll
    for (int p = 0; p < PP; p++) {
        float px = (float)(w + (p / 3)) + o[2 * p];
        float py = (float)(h + (p % 3)) + o[2 * p + 1];
        float x0f = floorf(px), y0f = floorf(py);
        float fx = px - x0f, fy = py - y0f;
        int x0 = (int)x0f, y0 = (int)y0f;
        float mk = o[18 + p];
        float s = 0.0f;
#pragma unroll
        for (int dy = 0; dy < 2; dy++)
#pragma unroll
            for (int dx = 0; dx < 2; dx++) {
                int xi = x0 + dx, yi = y0 + dy;
                if (xi >= 1 && xi <= 64 && yi >= 1 && yi <= 64) {
                    float wgt = (dx ? fx : 1.0f - fx) * (dy ? fy : 1.0f - fy);
                    s = fmaf(wgt, base[((size_t)(yi - 1) * 64 + (xi - 1)) * C2 + c], s);
                }
            }
        acc = fmaf(mk, s, acc);
    }
    hlf hb, lb2; split_h(acc, hb, lb2);
    chi[(size_t)pix * C2 + c] = hb;
    clo[(size_t)pix * C2 + c] = lb2;
}

// ---------------------------------------------------------------------------
// NHWC->NCHW + BN2 + SiLU + residual
// ---------------------------------------------------------------------------
__global__ __launch_bounds__(256) void bn2_res_transpose_k(
    const float* __restrict__ o, const float* __restrict__ xres,
    const float* __restrict__ g, const float* __restrict__ b,
    float* __restrict__ out)
{
    __shared__ float t[32][33];
    const int n = blockIdx.z, hw0 = blockIdx.x * 32, c0 = blockIdx.y * 32;
    const int tx = threadIdx.x & 31, ty = threadIdx.x >> 5;
#pragma unroll
    for (int i = ty; i < 32; i += 8)
        t[i][tx] = o[((size_t)n * HW + hw0 + i) * C2 + c0 + tx];
    __syncthreads();
#pragma unroll
    for (int i = ty; i < 32; i += 8) {
        int c = c0 + i, hw = hw0 + tx;
        float v = t[tx][i];
        float s = g[c] * rsqrtf(1.0f + BN_EPS);
        v = silu(fmaf(v, s, b[c]));
        size_t idx = ((size_t)n * C2 + c) * HW + hw;
        out[idx] = xres[idx] + v;
    }
}

// ---------------------------------------------------------------------------
// Launch
// ---------------------------------------------------------------------------
extern "C" void kernel_launch(void* const* d_in, const int* in_sizes, int n_in,
                              void* d_out, int out_size) {
    const float* x     = (const float*)d_in[0];
    const float* cv1_w = (const float*)d_in[1];
    const float* cv1_g = (const float*)d_in[2];
    const float* cv1_b = (const float*)d_in[3];
    const float* pw_w  = (const float*)d_in[4];
    const float* pw_g  = (const float*)d_in[5];
    const float* pw_b  = (const float*)d_in[6];
    const float* dw_w  = (const float*)d_in[7];
    const float* dw_b  = (const float*)d_in[8];
    const float* ln_g  = (const float*)d_in[9];
    const float* ln_b  = (const float*)d_in[10];
    const float* off_w = (const float*)d_in[11];
    const float* off_b = (const float*)d_in[12];
    const float* msk_w = (const float*)d_in[13];
    const float* msk_b = (const float*)d_in[14];
    const float* inp_w = (const float*)d_in[15];
    const float* inp_b = (const float*)d_in[16];
    const float* out_w = (const float*)d_in[17];
    const float* out_b = (const float*)d_in[18];
    const float* bn2_g = (const float*)d_in[19];
    const float* bn2_b = (const float*)d_in[20];

    float* sc = nullptr;
    cudaGetSymbolAddress((void**)&sc, g_scratch);
    hlf* xhi  = (hlf*)(sc + OFF_XHI);
    hlf* xlo  = (hlf*)(sc + OFF_XLO);
    hlf* y1hi = (hlf*)(sc + OFF_Y1HI);
    hlf* y1lo = (hlf*)(sc + OFF_Y1LO);
    float* y2f = sc + OFF_Y2F;
    hlf* y2hi = (hlf*)(sc + OFF_Y2HI);
    hlf* y2lo = (hlf*)(sc + OFF_Y2LO);
    float* xproj = sc + OFF_XPROJ;
    float* om    = sc + OFF_OM;
    hlf* chi  = (hlf*)(sc + OFF_CHI);
    hlf* clo  = (hlf*)(sc + OFF_CLO);
    float* onh = sc + OFF_ONH;
    hlf* wt9h = (hlf*)(sc + OFF_WT9H);
    hlf* pwh  = (hlf*)(sc + OFF_PWH);
    hlf* pwl  = (hlf*)(sc + OFF_PWL);
    hlf* inh  = (hlf*)(sc + OFF_INH);
    hlf* inl  = (hlf*)(sc + OFF_INL);
    hlf* ouh  = (hlf*)(sc + OFF_OUH);
    hlf* oul  = (hlf*)(sc + OFF_OUL);
    float* outp = (float*)d_out;

    cudaFuncSetAttribute(mma_conv_k, cudaFuncAttributeMaxDynamicSharedMemorySize, CONV_SMEM);
    cudaFuncSetAttribute(mma_gemm_k<128, 0>, cudaFuncAttributeMaxDynamicSharedMemorySize, GEMM_SMEM);
    cudaFuncSetAttribute(mma_gemm_k<256, 1>, cudaFuncAttributeMaxDynamicSharedMemorySize, GEMM_SMEM);

    // 0) preprocessing
    prep_x_k<<<dim3(HW / 32, C1 / 32, NB), 256>>>(x, xhi, xlo);
    prep_w_k<<<(9 * CM * C1 + C2 * CM + 2 * C2 * C2 + 255) / 256, 256>>>(
        cv1_w, pw_w, inp_w, out_w, wt9h, pwh, pwl, inh, inl, ouh, oul);

    // 1) cv1 (mma, 2-term fp16) -> y1 hi/lo
    mma_conv_k<<<NPIX / 64, 256, CONV_SMEM>>>(
        xhi, xlo, wt9h, cv1_g, cv1_b, y1hi, y1lo);

    // 2) pw (mma) -> y2 f32 + hi/lo
    mma_gemm_k<128, 0><<<dim3(NPIX / 64, 2), 256, GEMM_SMEM>>>(
        y1hi, y1lo, pwh, pwl, pw_g, pw_b, y2f, y2hi, y2lo);

    // 3) fused dw + LN + GELU + heads -> om
    dw_ln_gelu_offmask_k<<<NPIX, 256>>>(y2f, dw_w, dw_b, ln_g, ln_b,
                                        off_w, off_b, msk_w, msk_b, om);

    // 4) input_proj (mma) -> xproj f32
    mma_gemm_k<256, 1><<<dim3(NPIX / 64, 2), 256, GEMM_SMEM>>>(
        y2hi, y2lo, inh, inl, inp_b, nullptr, xproj, nullptr, nullptr);

    // 5) DCNv3 core -> hi/lo
    dcnv3_k<<<NPIX, 256>>>(xproj, om, chi, clo);

    // 6) output_proj (mma) -> onh f32
    mma_gemm_k<256, 1><<<dim3(NPIX / 64, 2), 256, GEMM_SMEM>>>(
        chi, clo, ouh, oul, out_b, nullptr, onh, nullptr, nullptr);

    // 7) BN2 + SiLU + residual + transpose -> d_out
    bn2_res_transpose_k<<<dim3(HW / 32, C2 / 32, NB), 256>>>(onh, x, bn2_g, bn2_b, outp);
}

// round 8
// speedup vs baseline: 4.0772x; 1.0936x over previous
#include <cuda_runtime.h>
#include <cuda_fp16.h>
#include <math.h>
#include <stdint.h>

// ---------------------------------------------------------------------------
// Problem constants
// ---------------------------------------------------------------------------
#define NB   4
#define C1   256
#define CM   128
#define C2   256
#define HW   4096
#define NPIX (NB*HW)
#define PP   9
#define BN_EPS 1e-5f
#define LN_EPS 1e-6f

typedef __half hlf;

// ---------------------------------------------------------------------------
// Scratch (offsets in floats)
// ---------------------------------------------------------------------------
#define OFF_XHI   0
#define OFF_XLO   (OFF_XHI  + NPIX*C1/2)
#define OFF_Y1HI  (OFF_XLO  + NPIX*C1/2)
#define OFF_Y1LO  (OFF_Y1HI + NPIX*CM/2)
#define OFF_Y2F   (OFF_Y1LO + NPIX*CM/2)
#define OFF_Y2HI  (OFF_Y2F  + NPIX*C2)
#define OFF_Y2LO  (OFF_Y2HI + NPIX*C2/2)
#define OFF_X1HI  (OFF_Y2LO + NPIX*C2/2)
#define OFF_X1LO  (OFF_X1HI + NPIX*C2/2)
#define OFF_XPROJ (OFF_X1LO + NPIX*C2/2)
#define OFF_OM    (OFF_XPROJ+ NPIX*C2)
#define OFF_CHI   (OFF_OM   + NPIX*27)
#define OFF_CLO   (OFF_CHI  + NPIX*C2/2)
#define OFF_ONH   (OFF_CLO  + NPIX*C2/2)
#define OFF_WT9H  (OFF_ONH  + NPIX*C2)
#define OFF_PWH   (OFF_WT9H + 9*CM*C1/2)
#define OFF_PWL   (OFF_PWH  + C2*CM/2)
#define OFF_INH   (OFF_PWL  + C2*CM/2)
#define OFF_INL   (OFF_INH  + C2*C2/2)
#define OFF_OUH   (OFF_INL  + C2*C2/2)
#define OFF_OUL   (OFF_OUH  + C2*C2/2)
#define OFF_HWH   (OFF_OUL  + C2*C2/2)      // 32*256 fp16 head weights
#define OFF_HWL   (OFF_HWH  + 32*C2/2)
#define OFF_HB    (OFF_HWL  + 32*C2/2)      // 32 f32 head bias
#define SCRATCH_FLOATS (OFF_HB + 32)

__device__ __align__(16) float g_scratch[SCRATCH_FLOATS];

__device__ __forceinline__ float silu(float v) { return v / (1.0f + expf(-v)); }

__device__ __forceinline__ void split_h(float v, hlf& h, hlf& l) {
    h = __float2half_rn(v);
    l = __float2half_rn(v - __half2float(h));
}
__device__ __forceinline__ uint32_t pack_pair(float a, float b, bool lo) {
    hlf ha, la, hb, lbv;
    split_h(a, ha, la); split_h(b, hb, lbv);
    if (!lo) return ((uint32_t)*(uint16_t*)&hb << 16) | *(uint16_t*)&ha;
    else     return ((uint32_t)*(uint16_t*)&lbv << 16) | *(uint16_t*)&la;
}

// ---------------------------------------------------------------------------
// mma.sync + ldmatrix + cp.async (portable sm_80 PTX)
// ---------------------------------------------------------------------------
__device__ __forceinline__ void mma16816(float* d, const uint32_t* a, const uint32_t* b) {
    asm volatile("mma.sync.aligned.m16n8k16.row.col.f32.f16.f16.f32 "
        "{%0,%1,%2,%3}, {%4,%5,%6,%7}, {%8,%9}, {%0,%1,%2,%3};"
        : "+f"(d[0]), "+f"(d[1]), "+f"(d[2]), "+f"(d[3])
        : "r"(a[0]), "r"(a[1]), "r"(a[2]), "r"(a[3]), "r"(b[0]), "r"(b[1]));
}
__device__ __forceinline__ void ldm4(uint32_t* r, uint32_t addr) {
    asm volatile("ldmatrix.sync.aligned.m8n8.x4.shared.b16 {%0,%1,%2,%3}, [%4];"
        : "=r"(r[0]), "=r"(r[1]), "=r"(r[2]), "=r"(r[3]) : "r"(addr));
}
__device__ __forceinline__ void cp16(uint32_t dst, const void* src) {
    asm volatile("cp.async.cg.shared.global [%0], [%1], 16;" :: "r"(dst), "l"(src));
}
__device__ __forceinline__ void cp16z(uint32_t dst, const void* src, int srcsize) {
    asm volatile("cp.async.cg.shared.global [%0], [%1], 16, %2;"
                 :: "r"(dst), "l"(src), "r"(srcsize));
}
#define CP_COMMIT() asm volatile("cp.async.commit_group;" ::: "memory")
#define CP_WAIT1()  asm volatile("cp.async.wait_group 1;" ::: "memory")

// SMEM row: 32 fp16 = 16 words, padded to 20 (conflict-free for ldmatrix)
#define TS 20
#define AW  (64 * TS)
#define BW  (128 * TS)
#define CONV_STW (2*AW + BW)
#define GEMM_STW (2*AW + 2*BW)
#define CONV_SMEM (2 * CONV_STW * 4)
#define GEMM_SMEM (2 * GEMM_STW * 4)

// ---------------------------------------------------------------------------
// prep_x: NCHW f32 -> NHWC fp16 hi/lo
// ---------------------------------------------------------------------------
__global__ __launch_bounds__(256) void prep_x_k(
    const float* __restrict__ x, hlf* __restrict__ xhi, hlf* __restrict__ xlo)
{
    __shared__ float t[32][33];
    const int n = blockIdx.z, hw0 = blockIdx.x * 32, c0 = blockIdx.y * 32;
    const int tx = threadIdx.x & 31, ty = threadIdx.x >> 5;
#pragma unroll
    for (int i = ty; i < 32; i += 8)
        t[i][tx] = x[((size_t)n * C1 + c0 + i) * HW + hw0 + tx];
    __syncthreads();
#pragma unroll
    for (int i = ty; i < 32; i += 8) {
        float v = t[tx][i];
        hlf h, l; split_h(v, h, l);
        size_t idx = ((size_t)n * HW + hw0 + i) * C1 + c0 + tx;
        xhi[idx] = h; xlo[idx] = l;
    }
}

// ---------------------------------------------------------------------------
// prep_w: split weights to fp16; cv1 -> [tap][co][ci] (hi only); head pack
// ---------------------------------------------------------------------------
__global__ __launch_bounds__(256) void prep_w_k(
    const float* __restrict__ cv1w, const float* __restrict__ pww,
    const float* __restrict__ inpw, const float* __restrict__ outw,
    const float* __restrict__ offw, const float* __restrict__ mskw,
    const float* __restrict__ offb, const float* __restrict__ mskb,
    hlf* __restrict__ wt9h,
    hlf* __restrict__ pwh,  hlf* __restrict__ pwl,
    hlf* __restrict__ inh,  hlf* __restrict__ inl,
    hlf* __restrict__ ouh,  hlf* __restrict__ oul,
    hlf* __restrict__ hwh,  hlf* __restrict__ hwl, float* __restrict__ hb)
{
    int idx = blockIdx.x * 256 + threadIdx.x;
    const int N1 = 9 * CM * C1;
    if (idx < N1) {
        int tap = idx / (CM * C1);
        int rem = idx - tap * CM * C1;
        int co = rem >> 8, ci = rem & 255;
        wt9h[idx] = __float2half_rn(cv1w[(size_t)co * (C1 * 9) + ci * 9 + tap]);
        return;
    }
    idx -= N1;
    if (idx < C2 * CM) {
        hlf h, l; split_h(pww[idx], h, l);
        pwh[idx] = h; pwl[idx] = l; return;
    }
    idx -= C2 * CM;
    if (idx < C2 * C2) {
        hlf h, l; split_h(inpw[idx], h, l);
        inh[idx] = h; inl[idx] = l; return;
    }
    idx -= C2 * C2;
    if (idx < C2 * C2) {
        hlf h, l; split_h(outw[idx], h, l);
        ouh[idx] = h; oul[idx] = l; return;
    }
    idx -= C2 * C2;
    if (idx < 32 * C2) {
        int j = idx >> 8, k = idx & 255;
        float v = (j < 18) ? offw[j * C2 + k] : ((j < 27) ? mskw[(j - 18) * C2 + k] : 0.0f);
        hlf h, l; split_h(v, h, l);
        hwh[idx] = h; hwl[idx] = l; return;
    }
    idx -= 32 * C2;
    if (idx < 32)
        hb[idx] = (idx < 18) ? offb[idx] : ((idx < 27) ? mskb[idx - 18] : 0.0f);
}

// ---------------------------------------------------------------------------
// Inner MMA via ldmatrix: A tile 64x32 (hi/lo), B tile 128x32 (hi [+lo]).
// Warp grid 2x4: wm m-half, wn 32-n slice.
// ---------------------------------------------------------------------------
template<int TERMS>
__device__ __forceinline__ void mma_step(
    uint32_t sb, int wm, int wn, int lane, float acc[2][4][4])
{
    const int arow = (lane & 7) + ((lane >> 3) & 1) * 8;
    const int akt  = (lane >> 4) & 1;
    const int brow = (lane & 7) + ((lane >> 4) & 1) * 8;
    const int bkt  = (lane >> 3) & 1;
    const uint32_t aHi = sb;
    const uint32_t aLo = sb + AW * 4;
    const uint32_t bHi = sb + 2 * AW * 4;
    const uint32_t bLo = sb + (2 * AW + BW) * 4;
#pragma unroll
    for (int ks = 0; ks < 2; ks++) {
        uint32_t ahi[2][4], alo[2][4], bhi[2][4], blo[2][4];
#pragma unroll
        for (int mt = 0; mt < 2; mt++) {
            uint32_t off = (uint32_t)(((wm * 32 + mt * 16 + arow) * TS + ks * 8 + akt * 4) * 4);
            ldm4(ahi[mt], aHi + off);
            ldm4(alo[mt], aLo + off);
        }
#pragma unroll
        for (int np = 0; np < 2; np++) {
            uint32_t off = (uint32_t)(((wn * 32 + np * 16 + brow) * TS + ks * 8 + bkt * 4) * 4);
            ldm4(bhi[np], bHi + off);
            if (TERMS == 3) ldm4(blo[np], bLo + off);
        }
#pragma unroll
        for (int mt = 0; mt < 2; mt++)
#pragma unroll
            for (int nt = 0; nt < 4; nt++) {
                const uint32_t* bh = &bhi[nt >> 1][(nt & 1) * 2];
                mma16816(acc[mt][nt], ahi[mt], bh);
                mma16816(acc[mt][nt], alo[mt], bh);
                if (TERMS == 3) mma16816(acc[mt][nt], ahi[mt], &blo[nt >> 1][(nt & 1) * 2]);
            }
    }
}

// ---------------------------------------------------------------------------
// mma_conv: cv1 3x3 (256->128) + BN + SiLU. 2-term fp16 (fp16 weights).
// ---------------------------------------------------------------------------
__global__ __launch_bounds__(256, 2) void mma_conv_k(
    const hlf* __restrict__ xhi, const hlf* __restrict__ xlo,
    const hlf* __restrict__ wth,
    const float* __restrict__ g, const float* __restrict__ b,
    hlf* __restrict__ y1hi, hlf* __restrict__ y1lo)
{
    extern __shared__ __align__(16) uint32_t dsm[];
    const uint32_t sbase = (uint32_t)__cvta_generic_to_shared(dsm);

    const int tid = threadIdx.x, wid = tid >> 5, lane = tid & 31;
    const int wm = wid >> 2, wn = wid & 3, qr = lane >> 2, qc = lane & 3;
    const int pix0 = blockIdx.x * 64;
    const int n = pix0 >> 12, hb2 = (pix0 & 4095) >> 6;
    const int r0 = tid >> 2, ch0 = tid & 3;

    float acc[2][4][4];
#pragma unroll
    for (int mt = 0; mt < 2; mt++)
#pragma unroll
        for (int nt = 0; nt < 4; nt++)
#pragma unroll
            for (int q = 0; q < 4; q++) acc[mt][nt][q] = 0.0f;

    const int TOT = 72;
    auto stage = [&](int it) {
        const int tap = it / 8, kc = it & 7;
        const int dh = tap / 3 - 1, dw = tap % 3 - 1;
        const uint32_t sb = sbase + (uint32_t)(it & 1) * (CONV_STW * 4);
        {
            int hh = hb2 + dh, ww = r0 + dw;
            bool val = ((unsigned)hh < 64u) && ((unsigned)ww < 64u);
            size_t u4 = val ? ((size_t)(n * HW + hh * 64 + ww) * 32 + kc * 4 + ch0) : 0;
            int sz = val ? 16 : 0;
            uint32_t rowoff = (uint32_t)(r0 * TS + ch0 * 4) * 4;
            cp16z(sb + rowoff,          (const char*)xhi + u4 * 16, sz);
            cp16z(sb + AW * 4 + rowoff, (const char*)xlo + u4 * 16, sz);
        }
#pragma unroll
        for (int i = 0; i < 2; i++) {
            int r = r0 + i * 64;
            size_t w4 = (size_t)(tap * CM + r) * 32 + kc * 4 + ch0;
            uint32_t rowoff = (uint32_t)(r * TS + ch0 * 4) * 4;
            cp16(sb + 2 * AW * 4 + rowoff, (const char*)wth + w4 * 16);
        }
    };

    stage(0); CP_COMMIT();
    for (int it = 0; it < TOT; it++) {
        if (it + 1 < TOT) stage(it + 1);
        CP_COMMIT();
        CP_WAIT1();
        __syncthreads();
        mma_step<2>(sbase + (uint32_t)(it & 1) * (CONV_STW * 4), wm, wn, lane, acc);
        __syncthreads();
    }

#pragma unroll
    for (int nt = 0; nt < 4; nt++) {
        int c = wn * 32 + nt * 8 + qc * 2;
        float s0 = g[c] * rsqrtf(1.0f + BN_EPS),     b0 = b[c];
        float s1 = g[c + 1] * rsqrtf(1.0f + BN_EPS), b1 = b[c + 1];
#pragma unroll
        for (int mt = 0; mt < 2; mt++) {
            int row = wm * 32 + mt * 16 + qr;
#pragma unroll
            for (int half = 0; half < 2; half++) {
                int pix = pix0 + row + half * 8;
                float v0 = silu(fmaf(acc[mt][nt][half * 2 + 0], s0, b0));
                float v1 = silu(fmaf(acc[mt][nt][half * 2 + 1], s1, b1));
                *(uint32_t*)&y1hi[(size_t)pix * CM + c] = pack_pair(v0, v1, false);
                *(uint32_t*)&y1lo[(size_t)pix * CM + c] = pack_pair(v0, v1, true);
            }
        }
    }
}

// ---------------------------------------------------------------------------
// mma_gemm: C[M,256] = A[M,K] @ W[256,K]^T, 3-term fp16, 2-stage pipe.
// ---------------------------------------------------------------------------
template<int K, int MODE>
__global__ __launch_bounds__(256, 2) void mma_gemm_k(
    const hlf* __restrict__ Ahi, const hlf* __restrict__ Alo,
    const hlf* __restrict__ Whi, const hlf* __restrict__ Wlo,
    const float* __restrict__ p0, const float* __restrict__ p1,
    float* __restrict__ outf, hlf* __restrict__ outhi, hlf* __restrict__ outlo)
{
    extern __shared__ __align__(16) uint32_t dsm[];
    const uint32_t sbase = (uint32_t)__cvta_generic_to_shared(dsm);

    const int tid = threadIdx.x, wid = tid >> 5, lane = tid & 31;
    const int wm = wid >> 2, wn = wid & 3, qr = lane >> 2, qc = lane & 3;
    const int pix0 = blockIdx.x * 64;
    const int nh = blockIdx.y;
    const int r0 = tid >> 2, ch0 = tid & 3;

    constexpr int TOT = K / 32;

    float acc[2][4][4];
#pragma unroll
    for (int mt = 0; mt < 2; mt++)
#pragma unroll
        for (int nt = 0; nt < 4; nt++)
#pragma unroll
            for (int q = 0; q < 4; q++) acc[mt][nt][q] = 0.0f;

    auto stage = [&](int it) {
        const int kc = it;
        const uint32_t sb = sbase + (uint32_t)(it & 1) * (GEMM_STW * 4);
        {
            size_t a4 = (size_t)(pix0 + r0) * (K / 8) + kc * 4 + ch0;
            uint32_t rowoff = (uint32_t)(r0 * TS + ch0 * 4) * 4;
            cp16(sb + rowoff,          (const char*)Ahi + a4 * 16);
            cp16(sb + AW * 4 + rowoff, (const char*)Alo + a4 * 16);
        }
#pragma unroll
        for (int i = 0; i < 2; i++) {
            int r = r0 + i * 64;
            size_t b4 = (size_t)(nh * 128 + r) * (K / 8) + kc * 4 + ch0;
            uint32_t rowoff = (uint32_t)(r * TS + ch0 * 4) * 4;
            cp16(sb + 2 * AW * 4 + rowoff,        (const char*)Whi + b4 * 16);
            cp16(sb + (2 * AW + BW) * 4 + rowoff, (const char*)Wlo + b4 * 16);
        }
    };

    stage(0); CP_COMMIT();
    for (int it = 0; it < TOT; it++) {
        if (it + 1 < TOT) stage(it + 1);
        CP_COMMIT();
        CP_WAIT1();
        __syncthreads();
        mma_step<3>(sbase + (uint32_t)(it & 1) * (GEMM_STW * 4), wm, wn, lane, acc);
        __syncthreads();
    }

#pragma unroll
    for (int nt = 0; nt < 4; nt++) {
        int c = nh * 128 + wn * 32 + nt * 8 + qc * 2;
        float s0, b0, s1, b1;
        if (MODE == 0) {
            s0 = p0[c] * rsqrtf(1.0f + BN_EPS);     b0 = p1[c];
            s1 = p0[c + 1] * rsqrtf(1.0f + BN_EPS); b1 = p1[c + 1];
        } else {
            b0 = p0[c]; b1 = p0[c + 1]; s0 = s1 = 1.0f;
        }
#pragma unroll
        for (int mt = 0; mt < 2; mt++) {
            int row = wm * 32 + mt * 16 + qr;
#pragma unroll
            for (int half = 0; half < 2; half++) {
                int pix = pix0 + row + half * 8;
                float v0, v1;
                if (MODE == 0) {
                    v0 = silu(fmaf(acc[mt][nt][half * 2 + 0], s0, b0));
                    v1 = silu(fmaf(acc[mt][nt][half * 2 + 1], s1, b1));
                } else {
                    v0 = acc[mt][nt][half * 2 + 0] + b0;
                    v1 = acc[mt][nt][half * 2 + 1] + b1;
                }
                *(float2*)&outf[(size_t)pix * C2 + c] = make_float2(v0, v1);
                if (MODE == 0) {
                    *(uint32_t*)&outhi[(size_t)pix * C2 + c] = pack_pair(v0, v1, false);
                    *(uint32_t*)&outlo[(size_t)pix * C2 + c] = pack_pair(v0, v1, true);
                }
            }
        }
    }
}

// ---------------------------------------------------------------------------
// mma_head: om[M,27] = x1[M,256] @ HW[32,256]^T + hb (3-term fp16).
// Block = 128 pixels, 8 warps x (16 px, 32 n). B resident in SMEM.
// ---------------------------------------------------------------------------
#define BS2 132
#define HEAD_SMEM ((2*128*TS + 2*32*BS2) * 4)
__global__ __launch_bounds__(256) void mma_head_k(
    const hlf* __restrict__ x1hi, const hlf* __restrict__ x1lo,
    const hlf* __restrict__ hwh,  const hlf* __restrict__ hwl,
    const float* __restrict__ hb, float* __restrict__ om)
{
    extern __shared__ __align__(16) uint32_t dsm[];
    const uint32_t sbase = (uint32_t)__cvta_generic_to_shared(dsm);
    const uint32_t AHI = 0, ALO = 128 * TS, BHI = 2 * 128 * TS, BLO = BHI + 32 * BS2;

    const int tid = threadIdx.x, wid = tid >> 5, lane = tid & 31;
    const int pix0 = blockIdx.x * 128;

    // stage B (both arrays) once
    for (int i = tid; i < 2048; i += 256) {
        int arr = i >> 10, j = i & 1023;
        int row = j >> 5, ch = j & 31;
        const uint4 v = ((const uint4*)(arr ? hwl : hwh))[row * 32 + ch];
        *(uint4*)&dsm[(arr ? BLO : BHI) + row * BS2 + ch * 4] = v;
    }

    float acc[4][4];
#pragma unroll
    for (int nt = 0; nt < 4; nt++)
#pragma unroll
        for (int q = 0; q < 4; q++) acc[nt][q] = 0.0f;

    const int arow = (lane & 7) + ((lane >> 3) & 1) * 8;
    const int akt  = (lane >> 4) & 1;
    const int brow = (lane & 7) + ((lane >> 4) & 1) * 8;
    const int bkt  = (lane >> 3) & 1;

    for (int kc = 0; kc < 8; kc++) {
        __syncthreads();
        // stage A chunk (128 px x 32 k halves, hi+lo)
        for (int i = tid; i < 1024; i += 256) {
            int arr = i >> 9, j = i & 511;
            int row = j >> 2, ch = j & 3;
            const uint4 v = ((const uint4*)(arr ? x1lo : x1hi))[(size_t)(pix0 + row) * 32 + kc * 4 + ch];
            *(uint4*)&dsm[(arr ? ALO : AHI) + row * TS + ch * 4] = v;
        }
        __syncthreads();
#pragma unroll
        for (int ks = 0; ks < 2; ks++) {
            uint32_t ahi[4], alo[4], bhi[2][4], blo[2][4];
            uint32_t aoff = (uint32_t)(((wid * 16 + arow) * TS + ks * 8 + akt * 4) * 4);
            ldm4(ahi, sbase + AHI * 4 + aoff);
            ldm4(alo, sbase + ALO * 4 + aoff);
#pragma unroll
            for (int np = 0; np < 2; np++) {
                uint32_t boff = (uint32_t)(((np * 16 + brow) * BS2 + kc * 16 + ks * 8 + bkt * 4) * 4);
                ldm4(bhi[np], sbase + BHI * 4 + boff);
                ldm4(blo[np], sbase + BLO * 4 + boff);
            }
#pragma unroll
            for (int nt = 0; nt < 4; nt++) {
                const uint32_t* bh = &bhi[nt >> 1][(nt & 1) * 2];
                mma16816(acc[nt], ahi, bh);
                mma16816(acc[nt], alo, bh);
                mma16816(acc[nt], ahi, &blo[nt >> 1][(nt & 1) * 2]);
            }
        }
    }

    // epilogue: logits (bias added), only cols < 27 stored
#pragma unroll
    for (int nt = 0; nt < 4; nt++) {
        int c = nt * 8 + (lane & 3) * 2;
        int r0p = pix0 + wid * 16 + (lane >> 2);
#pragma unroll
        for (int half = 0; half < 2; half++) {
            int pix = r0p + half * 8;
            float v0 = acc[nt][half * 2 + 0] + hb[c];
            float v1 = acc[nt][half * 2 + 1] + hb[c + 1];
            if (c < 27)     om[(size_t)pix * 27 + c]     = v0;
            if (c + 1 < 27) om[(size_t)pix * 27 + c + 1] = v1;
        }
    }
}

// ---------------------------------------------------------------------------
// Fused: depthwise 3x3 + LN + GELU -> x1 hi/lo
// ---------------------------------------------------------------------------
__global__ __launch_bounds__(256) void dw_ln_gelu_k(
    const float* __restrict__ y2,
    const float* __restrict__ dww, const float* __restrict__ dwb,
    const float* __restrict__ lg,  const float* __restrict__ lb,
    hlf* __restrict__ x1hi, hlf* __restrict__ x1lo)
{
    const int pix = blockIdx.x;
    const int n = pix >> 12, hw = pix & 4095, h = hw >> 6, w = hw & 63;
    const int c = threadIdx.x;

    float v = dwb[c];
#pragma unroll
    for (int kh = 0; kh < 3; kh++)
#pragma unroll
        for (int kw = 0; kw < 3; kw++) {
            int hh = h + kh - 1, wk = w + kw - 1;
            if ((unsigned)hh < 64u && (unsigned)wk < 64u)
                v = fmaf(y2[(((size_t)n * HW) + hh * 64 + wk) * C2 + c],
                         dww[c * 9 + kh * 3 + kw], v);
        }

    __shared__ float s1[256];
    __shared__ float s2[256];
    s1[c] = v; s2[c] = v * v;
    __syncthreads();
#pragma unroll
    for (int off = 128; off > 32; off >>= 1) {
        if (c < off) { s1[c] += s1[c + off]; s2[c] += s2[c + off]; }
        __syncthreads();
    }
    if (c < 32) {
        float a1 = s1[c] + s1[c + 32];
        float a2 = s2[c] + s2[c + 32];
#pragma unroll
        for (int o = 16; o > 0; o >>= 1) {
            a1 += __shfl_down_sync(0xffffffffu, a1, o);
            a2 += __shfl_down_sync(0xffffffffu, a2, o);
        }
        if (c == 0) { s1[0] = a1; s2[0] = a2; }
    }
    __syncthreads();
    float mean = s1[0] * (1.0f / 256.0f);
    float var  = s2[0] * (1.0f / 256.0f) - mean * mean;

    float t = fmaf((v - mean) * rsqrtf(var + LN_EPS), lg[c], lb[c]);
    float gelu = 0.5f * t * (1.0f + erff(t * 0.70710678118654752f));

    hlf hh2, ll2; split_h(gelu, hh2, ll2);
    x1hi[(size_t)pix * C2 + c] = hh2;
    x1lo[(size_t)pix * C2 + c] = ll2;
}

// ---------------------------------------------------------------------------
// DCNv3 core (mask softmax in-kernel) -> split hi/lo fp16
// ---------------------------------------------------------------------------
__global__ __launch_bounds__(256) void dcnv3_k(
    const float* __restrict__ xproj, const float* __restrict__ om,
    hlf* __restrict__ chi, hlf* __restrict__ clo)
{
    const int pix = blockIdx.x;
    const int n = pix >> 12, hw = pix & 4095, h = hw >> 6, w = hw & 63;
    const int c = threadIdx.x;

    __shared__ float o[32];
    if (c < 27) o[c] = om[(size_t)pix * 27 + c];
    __syncthreads();
    if (c == 0) {
        float mx = -1e30f;
#pragma unroll
        for (int q = 0; q < 9; q++) mx = fmaxf(mx, o[18 + q]);
        float e[9], sum = 0.0f;
#pragma unroll
        for (int q = 0; q < 9; q++) { e[q] = expf(o[18 + q] - mx); sum += e[q]; }
        float inv = 1.0f / sum;
#pragma unroll
        for (int q = 0; q < 9; q++) o[18 + q] = e[q] * inv;
    }
    __syncthreads();

    const float* base = xproj + (size_t)n * HW * C2;
    float acc = 0.0f;

#pragma unroll
    for (int p = 0; p < PP; p++) {
        float px = (float)(w + (p / 3)) + o[2 * p];
        float py = (float)(h + (p % 3)) + o[2 * p + 1];
        float x0f = floorf(px), y0f = floorf(py);
        float fx = px - x0f, fy = py - y0f;
        int x0 = (int)x0f, y0 = (int)y0f;
        float mk = o[18 + p];
        float s = 0.0f;
#pragma unroll
        for (int dy = 0; dy < 2; dy++)
#pragma unroll
            for (int dx = 0; dx < 2; dx++) {
                int xi = x0 + dx, yi = y0 + dy;
                if (xi >= 1 && xi <= 64 && yi >= 1 && yi <= 64) {
                    float wgt = (dx ? fx : 1.0f - fx) * (dy ? fy : 1.0f - fy);
                    s = fmaf(wgt, base[((size_t)(yi - 1) * 64 + (xi - 1)) * C2 + c], s);
                }
            }
        acc = fmaf(mk, s, acc);
    }
    hlf hb2, lb2; split_h(acc, hb2, lb2);
    chi[(size_t)pix * C2 + c] = hb2;
    clo[(size_t)pix * C2 + c] = lb2;
}

// ---------------------------------------------------------------------------
// NHWC->NCHW + BN2 + SiLU + residual
// ---------------------------------------------------------------------------
__global__ __launch_bounds__(256) void bn2_res_transpose_k(
    const float* __restrict__ o, const float* __restrict__ xres,
    const float* __restrict__ g, const float* __restrict__ b,
    float* __restrict__ out)
{
    __shared__ float t[32][33];
    const int n = blockIdx.z, hw0 = blockIdx.x * 32, c0 = blockIdx.y * 32;
    const int tx = threadIdx.x & 31, ty = threadIdx.x >> 5;
#pragma unroll
    for (int i = ty; i < 32; i += 8)
        t[i][tx] = o[((size_t)n * HW + hw0 + i) * C2 + c0 + tx];
    __syncthreads();
#pragma unroll
    for (int i = ty; i < 32; i += 8) {
        int c = c0 + i, hw = hw0 + tx;
        float v = t[tx][i];
        float s = g[c] * rsqrtf(1.0f + BN_EPS);
        v = silu(fmaf(v, s, b[c]));
        size_t idx = ((size_t)n * C2 + c) * HW + hw;
        out[idx] = xres[idx] + v;
    }
}

// ---------------------------------------------------------------------------
// Launch
// ---------------------------------------------------------------------------
extern "C" void kernel_launch(void* const* d_in, const int* in_sizes, int n_in,
                              void* d_out, int out_size) {
    const float* x     = (const float*)d_in[0];
    const float* cv1_w = (const float*)d_in[1];
    const float* cv1_g = (const float*)d_in[2];
    const float* cv1_b = (const float*)d_in[3];
    const float* pw_w  = (const float*)d_in[4];
    const float* pw_g  = (const float*)d_in[5];
    const float* pw_b  = (const float*)d_in[6];
    const float* dw_w  = (const float*)d_in[7];
    const float* dw_b  = (const float*)d_in[8];
    const float* ln_g  = (const float*)d_in[9];
    const float* ln_b  = (const float*)d_in[10];
    const float* off_w = (const float*)d_in[11];
    const float* off_b = (const float*)d_in[12];
    const float* msk_w = (const float*)d_in[13];
    const float* msk_b = (const float*)d_in[14];
    const float* inp_w = (const float*)d_in[15];
    const float* inp_b = (const float*)d_in[16];
    const float* out_w = (const float*)d_in[17];
    const float* out_b = (const float*)d_in[18];
    const float* bn2_g = (const float*)d_in[19];
    const float* bn2_b = (const float*)d_in[20];

    float* sc = nullptr;
    cudaGetSymbolAddress((void**)&sc, g_scratch);
    hlf* xhi  = (hlf*)(sc + OFF_XHI);
    hlf* xlo  = (hlf*)(sc + OFF_XLO);
    hlf* y1hi = (hlf*)(sc + OFF_Y1HI);
    hlf* y1lo = (hlf*)(sc + OFF_Y1LO);
    float* y2f = sc + OFF_Y2F;
    hlf* y2hi = (hlf*)(sc + OFF_Y2HI);
    hlf* y2lo = (hlf*)(sc + OFF_Y2LO);
    hlf* x1hi = (hlf*)(sc + OFF_X1HI);
    hlf* x1lo = (hlf*)(sc + OFF_X1LO);
    float* xproj = sc + OFF_XPROJ;
    float* om    = sc + OFF_OM;
    hlf* chi  = (hlf*)(sc + OFF_CHI);
    hlf* clo  = (hlf*)(sc + OFF_CLO);
    float* onh = sc + OFF_ONH;
    hlf* wt9h = (hlf*)(sc + OFF_WT9H);
    hlf* pwh  = (hlf*)(sc + OFF_PWH);
    hlf* pwl  = (hlf*)(sc + OFF_PWL);
    hlf* inh  = (hlf*)(sc + OFF_INH);
    hlf* inl  = (hlf*)(sc + OFF_INL);
    hlf* ouh  = (hlf*)(sc + OFF_OUH);
    hlf* oul  = (hlf*)(sc + OFF_OUL);
    hlf* hwh  = (hlf*)(sc + OFF_HWH);
    hlf* hwl  = (hlf*)(sc + OFF_HWL);
    float* hb = sc + OFF_HB;
    float* outp = (float*)d_out;

    cudaFuncSetAttribute(mma_conv_k, cudaFuncAttributeMaxDynamicSharedMemorySize, CONV_SMEM);
    cudaFuncSetAttribute(mma_gemm_k<128, 0>, cudaFuncAttributeMaxDynamicSharedMemorySize, GEMM_SMEM);
    cudaFuncSetAttribute(mma_gemm_k<256, 1>, cudaFuncAttributeMaxDynamicSharedMemorySize, GEMM_SMEM);
    cudaFuncSetAttribute(mma_head_k, cudaFuncAttributeMaxDynamicSharedMemorySize, HEAD_SMEM);

    // 0) preprocessing
    prep_x_k<<<dim3(HW / 32, C1 / 32, NB), 256>>>(x, xhi, xlo);
    int prep_tot = 9 * CM * C1 + C2 * CM + 2 * C2 * C2 + 32 * C2 + 32;
    prep_w_k<<<(prep_tot + 255) / 256, 256>>>(
        cv1_w, pw_w, inp_w, out_w, off_w, msk_w, off_b, msk_b,
        wt9h, pwh, pwl, inh, inl, ouh, oul, hwh, hwl, hb);

    // 1) cv1 -> y1 hi/lo
    mma_conv_k<<<NPIX / 64, 256, CONV_SMEM>>>(
        xhi, xlo, wt9h, cv1_g, cv1_b, y1hi, y1lo);

    // 2) pw -> y2 f32 + hi/lo
    mma_gemm_k<128, 0><<<dim3(NPIX / 64, 2), 256, GEMM_SMEM>>>(
        y1hi, y1lo, pwh, pwl, pw_g, pw_b, y2f, y2hi, y2lo);

    // 3) dw + LN + GELU -> x1 hi/lo
    dw_ln_gelu_k<<<NPIX, 256>>>(y2f, dw_w, dw_b, ln_g, ln_b, x1hi, x1lo);

    // 4) offset/mask heads -> om (logits)
    mma_head_k<<<NPIX / 128, 256, HEAD_SMEM>>>(x1hi, x1lo, hwh, hwl, hb, om);

    // 5) input_proj -> xproj f32
    mma_gemm_k<256, 1><<<dim3(NPIX / 64, 2), 256, GEMM_SMEM>>>(
        y2hi, y2lo, inh, inl, inp_b, nullptr, xproj, nullptr, nullptr);

    // 6) DCNv3 core (softmax inside) -> hi/lo
    dcnv3_k<<<NPIX, 256>>>(xproj, om, chi, clo);

    // 7) output_proj -> onh f32
    mma_gemm_k<256, 1><<<dim3(NPIX / 64, 2), 256, GEMM_SMEM>>>(
        chi, clo, ouh, oul, out_b, nullptr, onh, nullptr, nullptr);

    // 8) BN2 + SiLU + residual + transpose -> d_out
    bn2_res_transpose_k<<<dim3(HW / 32, C2 / 32, NB), 256>>>(onh, x, bn2_g, bn2_b, outp);
}

// round 9
// speedup vs baseline: 4.5548x; 1.1171x over previous
#include <cuda_runtime.h>
#include <cuda_fp16.h>
#include <math.h>
#include <stdint.h>

// ---------------------------------------------------------------------------
// Problem constants
// ---------------------------------------------------------------------------
#define NB   4
#define C1   256
#define CM   128
#define C2   256
#define HW   4096
#define NPIX (NB*HW)
#define PP   9
#define BN_EPS 1e-5f
#define LN_EPS 1e-6f

typedef __half hlf;

// ---------------------------------------------------------------------------
// Scratch (offsets in floats)
// ---------------------------------------------------------------------------
#define OFF_XHI   0                          // NPIX*C1 fp16 (conv A, 1-term)
#define OFF_Y1HI  (OFF_XHI  + NPIX*C1/2)     // NPIX*CM fp16 hi/lo (pw A)
#define OFF_Y1LO  (OFF_Y1HI + NPIX*CM/2)
#define OFF_Y2F   (OFF_Y1LO + NPIX*CM/2)     // f32
#define OFF_Y2HI  (OFF_Y2F  + NPIX*C2)
#define OFF_Y2LO  (OFF_Y2HI + NPIX*C2/2)
#define OFF_X1HI  (OFF_Y2LO + NPIX*C2/2)
#define OFF_X1LO  (OFF_X1HI + NPIX*C2/2)
#define OFF_XPROJ (OFF_X1LO + NPIX*C2/2)
#define OFF_OM    (OFF_XPROJ+ NPIX*C2)
#define OFF_CHI   (OFF_OM   + NPIX*27)
#define OFF_CLO   (OFF_CHI  + NPIX*C2/2)
#define OFF_ONH   (OFF_CLO  + NPIX*C2/2)
#define OFF_WT9H  (OFF_ONH  + NPIX*C2)       // 9*128*256 fp16 [tap][co][ci]
#define OFF_PWH   (OFF_WT9H + 9*CM*C1/2)
#define OFF_INH   (OFF_PWH  + C2*CM/2)
#define OFF_OUH   (OFF_INH  + C2*C2/2)
#define OFF_HWH   (OFF_OUH  + C2*C2/2)       // 32*256 fp16 head weights
#define OFF_HB    (OFF_HWH  + 32*C2/2)       // 32 f32 head bias
#define SCRATCH_FLOATS (OFF_HB + 32)

__device__ __align__(16) float g_scratch[SCRATCH_FLOATS];

__device__ __forceinline__ float silu(float v) { return v / (1.0f + expf(-v)); }

__device__ __forceinline__ void split_h(float v, hlf& h, hlf& l) {
    h = __float2half_rn(v);
    l = __float2half_rn(v - __half2float(h));
}
__device__ __forceinline__ uint32_t pack_pair(float a, float b, bool lo) {
    hlf ha, la, hb, lbv;
    split_h(a, ha, la); split_h(b, hb, lbv);
    if (!lo) return ((uint32_t)*(uint16_t*)&hb << 16) | *(uint16_t*)&ha;
    else     return ((uint32_t)*(uint16_t*)&lbv << 16) | *(uint16_t*)&la;
}

// ---------------------------------------------------------------------------
// mma.sync + ldmatrix + cp.async (portable sm_80 PTX)
// ---------------------------------------------------------------------------
__device__ __forceinline__ void mma16816(float* d, const uint32_t* a, const uint32_t* b) {
    asm volatile("mma.sync.aligned.m16n8k16.row.col.f32.f16.f16.f32 "
        "{%0,%1,%2,%3}, {%4,%5,%6,%7}, {%8,%9}, {%0,%1,%2,%3};"
        : "+f"(d[0]), "+f"(d[1]), "+f"(d[2]), "+f"(d[3])
        : "r"(a[0]), "r"(a[1]), "r"(a[2]), "r"(a[3]), "r"(b[0]), "r"(b[1]));
}
__device__ __forceinline__ void ldm4(uint32_t* r, uint32_t addr) {
    asm volatile("ldmatrix.sync.aligned.m8n8.x4.shared.b16 {%0,%1,%2,%3}, [%4];"
        : "=r"(r[0]), "=r"(r[1]), "=r"(r[2]), "=r"(r[3]) : "r"(addr));
}
__device__ __forceinline__ void cp16(uint32_t dst, const void* src) {
    asm volatile("cp.async.cg.shared.global [%0], [%1], 16;" :: "r"(dst), "l"(src));
}
__device__ __forceinline__ void cp16z(uint32_t dst, const void* src, int srcsize) {
    asm volatile("cp.async.cg.shared.global [%0], [%1], 16, %2;"
                 :: "r"(dst), "l"(src), "r"(srcsize));
}
#define CP_COMMIT() asm volatile("cp.async.commit_group;" ::: "memory")
#define CP_WAIT1()  asm volatile("cp.async.wait_group 1;" ::: "memory")

// SMEM row: 32 fp16 = 16 words, padded to 20 (conflict-free for ldmatrix)
#define TS 20
#define AW  (64 * TS)
#define BW  (128 * TS)
#define CONV_STW (AW + BW)        // A hi | B hi
#define GEMM_STW (2*AW + BW)      // A hi | A lo | B hi
#define CONV_SMEM (2 * CONV_STW * 4)
#define GEMM_SMEM (2 * GEMM_STW * 4)

// ---------------------------------------------------------------------------
// prep_x: NCHW f32 -> NHWC fp16 (single precision term for conv)
// ---------------------------------------------------------------------------
__global__ __launch_bounds__(256) void prep_x_k(
    const float* __restrict__ x, hlf* __restrict__ xhi)
{
    __shared__ float t[32][33];
    const int n = blockIdx.z, hw0 = blockIdx.x * 32, c0 = blockIdx.y * 32;
    const int tx = threadIdx.x & 31, ty = threadIdx.x >> 5;
#pragma unroll
    for (int i = ty; i < 32; i += 8)
        t[i][tx] = x[((size_t)n * C1 + c0 + i) * HW + hw0 + tx];
    __syncthreads();
#pragma unroll
    for (int i = ty; i < 32; i += 8) {
        size_t idx = ((size_t)n * HW + hw0 + i) * C1 + c0 + tx;
        xhi[idx] = __float2half_rn(t[tx][i]);
    }
}

// ---------------------------------------------------------------------------
// prep_w: all weights -> fp16 (hi only); cv1 -> [tap][co][ci]; head pack
// ---------------------------------------------------------------------------
__global__ __launch_bounds__(256) void prep_w_k(
    const float* __restrict__ cv1w, const float* __restrict__ pww,
    const float* __restrict__ inpw, const float* __restrict__ outw,
    const float* __restrict__ offw, const float* __restrict__ mskw,
    const float* __restrict__ offb, const float* __restrict__ mskb,
    hlf* __restrict__ wt9h, hlf* __restrict__ pwh,
    hlf* __restrict__ inh,  hlf* __restrict__ ouh,
    hlf* __restrict__ hwh,  float* __restrict__ hb)
{
    int idx = blockIdx.x * 256 + threadIdx.x;
    const int N1 = 9 * CM * C1;
    if (idx < N1) {
        int tap = idx / (CM * C1);
        int rem = idx - tap * CM * C1;
        int co = rem >> 8, ci = rem & 255;
        wt9h[idx] = __float2half_rn(cv1w[(size_t)co * (C1 * 9) + ci * 9 + tap]);
        return;
    }
    idx -= N1;
    if (idx < C2 * CM) { pwh[idx] = __float2half_rn(pww[idx]); return; }
    idx -= C2 * CM;
    if (idx < C2 * C2) { inh[idx] = __float2half_rn(inpw[idx]); return; }
    idx -= C2 * C2;
    if (idx < C2 * C2) { ouh[idx] = __float2half_rn(outw[idx]); return; }
    idx -= C2 * C2;
    if (idx < 32 * C2) {
        int j = idx >> 8, k = idx & 255;
        float v = (j < 18) ? offw[j * C2 + k] : ((j < 27) ? mskw[(j - 18) * C2 + k] : 0.0f);
        hwh[idx] = __float2half_rn(v); return;
    }
    idx -= 32 * C2;
    if (idx < 32)
        hb[idx] = (idx < 18) ? offb[idx] : ((idx < 27) ? mskb[idx - 18] : 0.0f);
}

// ---------------------------------------------------------------------------
// Inner MMA via ldmatrix. A tile 64x32 (ATERMS arrays), B tile 128x32 (hi).
// Warp grid 2x4.
// ---------------------------------------------------------------------------
template<int ATERMS>
__device__ __forceinline__ void mma_step(
    uint32_t aHi, uint32_t aLo, uint32_t bHi,
    int wm, int wn, int lane, float acc[2][4][4])
{
    const int arow = (lane & 7) + ((lane >> 3) & 1) * 8;
    const int akt  = (lane >> 4) & 1;
    const int brow = (lane & 7) + ((lane >> 4) & 1) * 8;
    const int bkt  = (lane >> 3) & 1;
#pragma unroll
    for (int ks = 0; ks < 2; ks++) {
        uint32_t ahi[2][4], alo[2][4], bhi[2][4];
#pragma unroll
        for (int mt = 0; mt < 2; mt++) {
            uint32_t off = (uint32_t)(((wm * 32 + mt * 16 + arow) * TS + ks * 8 + akt * 4) * 4);
            ldm4(ahi[mt], aHi + off);
            if (ATERMS == 2) ldm4(alo[mt], aLo + off);
        }
#pragma unroll
        for (int np = 0; np < 2; np++) {
            uint32_t off = (uint32_t)(((wn * 32 + np * 16 + brow) * TS + ks * 8 + bkt * 4) * 4);
            ldm4(bhi[np], bHi + off);
        }
#pragma unroll
        for (int mt = 0; mt < 2; mt++)
#pragma unroll
            for (int nt = 0; nt < 4; nt++) {
                const uint32_t* bh = &bhi[nt >> 1][(nt & 1) * 2];
                mma16816(acc[mt][nt], ahi[mt], bh);
                if (ATERMS == 2) mma16816(acc[mt][nt], alo[mt], bh);
            }
    }
}

// ---------------------------------------------------------------------------
// mma_conv: cv1 3x3 (256->128) + BN + SiLU. 1-term pure fp16.
// ---------------------------------------------------------------------------
__global__ __launch_bounds__(256, 2) void mma_conv_k(
    const hlf* __restrict__ xhi, const hlf* __restrict__ wth,
    const float* __restrict__ g, const float* __restrict__ b,
    hlf* __restrict__ y1hi, hlf* __restrict__ y1lo)
{
    extern __shared__ __align__(16) uint32_t dsm[];
    const uint32_t sbase = (uint32_t)__cvta_generic_to_shared(dsm);

    const int tid = threadIdx.x, wid = tid >> 5, lane = tid & 31;
    const int wm = wid >> 2, wn = wid & 3, qr = lane >> 2, qc = lane & 3;
    const int pix0 = blockIdx.x * 64;
    const int n = pix0 >> 12, hb2 = (pix0 & 4095) >> 6;
    const int r0 = tid >> 2, ch0 = tid & 3;

    float acc[2][4][4];
#pragma unroll
    for (int mt = 0; mt < 2; mt++)
#pragma unroll
        for (int nt = 0; nt < 4; nt++)
#pragma unroll
            for (int q = 0; q < 4; q++) acc[mt][nt][q] = 0.0f;

    const int TOT = 72;
    auto stage = [&](int it) {
        const int tap = it / 8, kc = it & 7;
        const int dh = tap / 3 - 1, dw = tap % 3 - 1;
        const uint32_t sb = sbase + (uint32_t)(it & 1) * (CONV_STW * 4);
        {
            int hh = hb2 + dh, ww = r0 + dw;
            bool val = ((unsigned)hh < 64u) && ((unsigned)ww < 64u);
            size_t u4 = val ? ((size_t)(n * HW + hh * 64 + ww) * 32 + kc * 4 + ch0) : 0;
            int sz = val ? 16 : 0;
            uint32_t rowoff = (uint32_t)(r0 * TS + ch0 * 4) * 4;
            cp16z(sb + rowoff, (const char*)xhi + u4 * 16, sz);
        }
#pragma unroll
        for (int i = 0; i < 2; i++) {
            int r = r0 + i * 64;
            size_t w4 = (size_t)(tap * CM + r) * 32 + kc * 4 + ch0;
            uint32_t rowoff = (uint32_t)(r * TS + ch0 * 4) * 4;
            cp16(sb + AW * 4 + rowoff, (const char*)wth + w4 * 16);
        }
    };

    stage(0); CP_COMMIT();
    for (int it = 0; it < TOT; it++) {
        if (it + 1 < TOT) stage(it + 1);
        CP_COMMIT();
        CP_WAIT1();
        __syncthreads();
        uint32_t sb = sbase + (uint32_t)(it & 1) * (CONV_STW * 4);
        mma_step<1>(sb, 0, sb + AW * 4, wm, wn, lane, acc);
        __syncthreads();
    }

#pragma unroll
    for (int nt = 0; nt < 4; nt++) {
        int c = wn * 32 + nt * 8 + qc * 2;
        float s0 = g[c] * rsqrtf(1.0f + BN_EPS),     b0 = b[c];
        float s1 = g[c + 1] * rsqrtf(1.0f + BN_EPS), b1 = b[c + 1];
#pragma unroll
        for (int mt = 0; mt < 2; mt++) {
            int row = wm * 32 + mt * 16 + qr;
#pragma unroll
            for (int half = 0; half < 2; half++) {
                int pix = pix0 + row + half * 8;
                float v0 = silu(fmaf(acc[mt][nt][half * 2 + 0], s0, b0));
                float v1 = silu(fmaf(acc[mt][nt][half * 2 + 1], s1, b1));
                *(uint32_t*)&y1hi[(size_t)pix * CM + c] = pack_pair(v0, v1, false);
                *(uint32_t*)&y1lo[(size_t)pix * CM + c] = pack_pair(v0, v1, true);
            }
        }
    }
}

// ---------------------------------------------------------------------------
// mma_gemm: C[M,256] = (Ahi+Alo)[M,K] @ Wfp16[256,K]^T, 2-term, 2-stage pipe.
// MODE 0: BN+SiLU -> f32 + hi/lo split.  MODE 1: +bias -> f32.
// ---------------------------------------------------------------------------
template<int K, int MODE>
__global__ __launch_bounds__(256, 2) void mma_gemm_k(
    const hlf* __restrict__ Ahi, const hlf* __restrict__ Alo,
    const hlf* __restrict__ Whi,
    const float* __restrict__ p0, const float* __restrict__ p1,
    float* __restrict__ outf, hlf* __restrict__ outhi, hlf* __restrict__ outlo)
{
    extern __shared__ __align__(16) uint32_t dsm[];
    const uint32_t sbase = (uint32_t)__cvta_generic_to_shared(dsm);

    const int tid = threadIdx.x, wid = tid >> 5, lane = tid & 31;
    const int wm = wid >> 2, wn = wid & 3, qr = lane >> 2, qc = lane & 3;
    const int pix0 = blockIdx.x * 64;
    const int nh = blockIdx.y;
    const int r0 = tid >> 2, ch0 = tid & 3;

    constexpr int TOT = K / 32;

    float acc[2][4][4];
#pragma unroll
    for (int mt = 0; mt < 2; mt++)
#pragma unroll
        for (int nt = 0; nt < 4; nt++)
#pragma unroll
            for (int q = 0; q < 4; q++) acc[mt][nt][q] = 0.0f;

    auto stage = [&](int it) {
        const int kc = it;
        const uint32_t sb = sbase + (uint32_t)(it & 1) * (GEMM_STW * 4);
        {
            size_t a4 = (size_t)(pix0 + r0) * (K / 8) + kc * 4 + ch0;
            uint32_t rowoff = (uint32_t)(r0 * TS + ch0 * 4) * 4;
            cp16(sb + rowoff,          (const char*)Ahi + a4 * 16);
            cp16(sb + AW * 4 + rowoff, (const char*)Alo + a4 * 16);
        }
#pragma unroll
        for (int i = 0; i < 2; i++) {
            int r = r0 + i * 64;
            size_t b4 = (size_t)(nh * 128 + r) * (K / 8) + kc * 4 + ch0;
            uint32_t rowoff = (uint32_t)(r * TS + ch0 * 4) * 4;
            cp16(sb + 2 * AW * 4 + rowoff, (const char*)Whi + b4 * 16);
        }
    };

    stage(0); CP_COMMIT();
    for (int it = 0; it < TOT; it++) {
        if (it + 1 < TOT) stage(it + 1);
        CP_COMMIT();
        CP_WAIT1();
        __syncthreads();
        uint32_t sb = sbase + (uint32_t)(it & 1) * (GEMM_STW * 4);
        mma_step<2>(sb, sb + AW * 4, sb + 2 * AW * 4, wm, wn, lane, acc);
        __syncthreads();
    }

#pragma unroll
    for (int nt = 0; nt < 4; nt++) {
        int c = nh * 128 + wn * 32 + nt * 8 + qc * 2;
        float s0, b0, s1, b1;
        if (MODE == 0) {
            s0 = p0[c] * rsqrtf(1.0f + BN_EPS);     b0 = p1[c];
            s1 = p0[c + 1] * rsqrtf(1.0f + BN_EPS); b1 = p1[c + 1];
        } else {
            b0 = p0[c]; b1 = p0[c + 1]; s0 = s1 = 1.0f;
        }
#pragma unroll
        for (int mt = 0; mt < 2; mt++) {
            int row = wm * 32 + mt * 16 + qr;
#pragma unroll
            for (int half = 0; half < 2; half++) {
                int pix = pix0 + row + half * 8;
                float v0, v1;
                if (MODE == 0) {
                    v0 = silu(fmaf(acc[mt][nt][half * 2 + 0], s0, b0));
                    v1 = silu(fmaf(acc[mt][nt][half * 2 + 1], s1, b1));
                } else {
                    v0 = acc[mt][nt][half * 2 + 0] + b0;
                    v1 = acc[mt][nt][half * 2 + 1] + b1;
                }
                *(float2*)&outf[(size_t)pix * C2 + c] = make_float2(v0, v1);
                if (MODE == 0) {
                    *(uint32_t*)&outhi[(size_t)pix * C2 + c] = pack_pair(v0, v1, false);
                    *(uint32_t*)&outlo[(size_t)pix * C2 + c] = pack_pair(v0, v1, true);
                }
            }
        }
    }
}

// ---------------------------------------------------------------------------
// mma_head: om[M,27] = (x1hi+x1lo)[M,256] @ HW16[32,256]^T + hb (2-term).
// Block = 128 pixels, 8 warps x (16 px, 32 n). B resident in SMEM.
// ---------------------------------------------------------------------------
#define BS2 132
#define HEAD_SMEM ((2*128*TS + 32*BS2) * 4)
__global__ __launch_bounds__(256) void mma_head_k(
    const hlf* __restrict__ x1hi, const hlf* __restrict__ x1lo,
    const hlf* __restrict__ hwh,
    const float* __restrict__ hb, float* __restrict__ om)
{
    extern __shared__ __align__(16) uint32_t dsm[];
    const uint32_t sbase = (uint32_t)__cvta_generic_to_shared(dsm);
    const uint32_t AHI = 0, ALO = 128 * TS, BHI = 2 * 128 * TS;

    const int tid = threadIdx.x, wid = tid >> 5, lane = tid & 31;
    const int pix0 = blockIdx.x * 128;

    // stage B once
    for (int i = tid; i < 1024; i += 256) {
        int row = i >> 5, ch = i & 31;
        *(uint4*)&dsm[BHI + row * BS2 + ch * 4] = ((const uint4*)hwh)[row * 32 + ch];
    }

    float acc[4][4];
#pragma unroll
    for (int nt = 0; nt < 4; nt++)
#pragma unroll
        for (int q = 0; q < 4; q++) acc[nt][q] = 0.0f;

    const int arow = (lane & 7) + ((lane >> 3) & 1) * 8;
    const int akt  = (lane >> 4) & 1;
    const int brow = (lane & 7) + ((lane >> 4) & 1) * 8;
    const int bkt  = (lane >> 3) & 1;

    for (int kc = 0; kc < 8; kc++) {
        __syncthreads();
        for (int i = tid; i < 1024; i += 256) {
            int arr = i >> 9, j = i & 511;
            int row = j >> 2, ch = j & 3;
            const uint4 v = ((const uint4*)(arr ? x1lo : x1hi))[(size_t)(pix0 + row) * 32 + kc * 4 + ch];
            *(uint4*)&dsm[(arr ? ALO : AHI) + row * TS + ch * 4] = v;
        }
        __syncthreads();
#pragma unroll
        for (int ks = 0; ks < 2; ks++) {
            uint32_t ahi[4], alo[4], bhi[2][4];
            uint32_t aoff = (uint32_t)(((wid * 16 + arow) * TS + ks * 8 + akt * 4) * 4);
            ldm4(ahi, sbase + AHI * 4 + aoff);
            ldm4(alo, sbase + ALO * 4 + aoff);
#pragma unroll
            for (int np = 0; np < 2; np++) {
                uint32_t boff = (uint32_t)(((np * 16 + brow) * BS2 + kc * 16 + ks * 8 + bkt * 4) * 4);
                ldm4(bhi[np], sbase + BHI * 4 + boff);
            }
#pragma unroll
            for (int nt = 0; nt < 4; nt++) {
                const uint32_t* bh = &bhi[nt >> 1][(nt & 1) * 2];
                mma16816(acc[nt], ahi, bh);
                mma16816(acc[nt], alo, bh);
            }
        }
    }

#pragma unroll
    for (int nt = 0; nt < 4; nt++) {
        int c = nt * 8 + (lane & 3) * 2;
        int r0p = pix0 + wid * 16 + (lane >> 2);
#pragma unroll
        for (int half = 0; half < 2; half++) {
            int pix = r0p + half * 8;
            float v0 = acc[nt][half * 2 + 0] + hb[c];
            float v1 = acc[nt][half * 2 + 1] + hb[c + 1];
            if (c < 27)     om[(size_t)pix * 27 + c]     = v0;
            if (c + 1 < 27) om[(size_t)pix * 27 + c + 1] = v1;
        }
    }
}

// ---------------------------------------------------------------------------
// Fused: depthwise 3x3 + LN + GELU -> x1 hi/lo
// ---------------------------------------------------------------------------
__global__ __launch_bounds__(256) void dw_ln_gelu_k(
    const float* __restrict__ y2,
    const float* __restrict__ dww, const float* __restrict__ dwb,
    const float* __restrict__ lg,  const float* __restrict__ lb,
    hlf* __restrict__ x1hi, hlf* __restrict__ x1lo)
{
    const int pix = blockIdx.x;
    const int n = pix >> 12, hw = pix & 4095, h = hw >> 6, w = hw & 63;
    const int c = threadIdx.x;

    float v = dwb[c];
#pragma unroll
    for (int kh = 0; kh < 3; kh++)
#pragma unroll
        for (int kw = 0; kw < 3; kw++) {
            int hh = h + kh - 1, wk = w + kw - 1;
            if ((unsigned)hh < 64u && (unsigned)wk < 64u)
                v = fmaf(y2[(((size_t)n * HW) + hh * 64 + wk) * C2 + c],
                         dww[c * 9 + kh * 3 + kw], v);
        }

    __shared__ float s1[256];
    __shared__ float s2[256];
    s1[c] = v; s2[c] = v * v;
    __syncthreads();
#pragma unroll
    for (int off = 128; off > 32; off >>= 1) {
        if (c < off) { s1[c] += s1[c + off]; s2[c] += s2[c + off]; }
        __syncthreads();
    }
    if (c < 32) {
        float a1 = s1[c] + s1[c + 32];
        float a2 = s2[c] + s2[c + 32];
#pragma unroll
        for (int o = 16; o > 0; o >>= 1) {
            a1 += __shfl_down_sync(0xffffffffu, a1, o);
            a2 += __shfl_down_sync(0xffffffffu, a2, o);
        }
        if (c == 0) { s1[0] = a1; s2[0] = a2; }
    }
    __syncthreads();
    float mean = s1[0] * (1.0f / 256.0f);
    float var  = s2[0] * (1.0f / 256.0f) - mean * mean;

    float t = fmaf((v - mean) * rsqrtf(var + LN_EPS), lg[c], lb[c]);
    float gelu = 0.5f * t * (1.0f + erff(t * 0.70710678118654752f));

    hlf hh2, ll2; split_h(gelu, hh2, ll2);
    x1hi[(size_t)pix * C2 + c] = hh2;
    x1lo[(size_t)pix * C2 + c] = ll2;
}

// ---------------------------------------------------------------------------
// DCNv3 core (mask softmax in-kernel) -> split hi/lo fp16
// ---------------------------------------------------------------------------
__global__ __launch_bounds__(256) void dcnv3_k(
    const float* __restrict__ xproj, const float* __restrict__ om,
    hlf* __restrict__ chi, hlf* __restrict__ clo)
{
    const int pix = blockIdx.x;
    const int n = pix >> 12, hw = pix & 4095, h = hw >> 6, w = hw & 63;
    const int c = threadIdx.x;

    __shared__ float o[32];
    if (c < 27) o[c] = om[(size_t)pix * 27 + c];
    __syncthreads();
    if (c == 0) {
        float mx = -1e30f;
#pragma unroll
        for (int q = 0; q < 9; q++) mx = fmaxf(mx, o[18 + q]);
        float e[9], sum = 0.0f;
#pragma unroll
        for (int q = 0; q < 9; q++) { e[q] = expf(o[18 + q] - mx); sum += e[q]; }
        float inv = 1.0f / sum;
#pragma unroll
        for (int q = 0; q < 9; q++) o[18 + q] = e[q] * inv;
    }
    __syncthreads();

    const float* base = xproj + (size_t)n * HW * C2;
    float acc = 0.0f;

#pragma unroll
    for (int p = 0; p < PP; p++) {
        float px = (float)(w + (p / 3)) + o[2 * p];
        float py = (float)(h + (p % 3)) + o[2 * p + 1];
        float x0f = floorf(px), y0f = floorf(py);
        float fx = px - x0f, fy = py - y0f;
        int x0 = (int)x0f, y0 = (int)y0f;
        float mk = o[18 + p];
        float s = 0.0f;
#pragma unroll
        for (int dy = 0; dy < 2; dy++)
#pragma unroll
            for (int dx = 0; dx < 2; dx++) {
                int xi = x0 + dx, yi = y0 + dy;
                if (xi >= 1 && xi <= 64 && yi >= 1 && yi <= 64) {
                    float wgt = (dx ? fx : 1.0f - fx) * (dy ? fy : 1.0f - fy);
                    s = fmaf(wgt, base[((size_t)(yi - 1) * 64 + (xi - 1)) * C2 + c], s);
                }
            }
        acc = fmaf(mk, s, acc);
    }
    hlf hb2, lb2; split_h(acc, hb2, lb2);
    chi[(size_t)pix * C2 + c] = hb2;
    clo[(size_t)pix * C2 + c] = lb2;
}

// ---------------------------------------------------------------------------
// NHWC->NCHW + BN2 + SiLU + residual
// ---------------------------------------------------------------------------
__global__ __launch_bounds__(256) void bn2_res_transpose_k(
    const float* __restrict__ o, const float* __restrict__ xres,
    const float* __restrict__ g, const float* __restrict__ b,
    float* __restrict__ out)
{
    __shared__ float t[32][33];
    const int n = blockIdx.z, hw0 = blockIdx.x * 32, c0 = blockIdx.y * 32;
    const int tx = threadIdx.x & 31, ty = threadIdx.x >> 5;
#pragma unroll
    for (int i = ty; i < 32; i += 8)
        t[i][tx] = o[((size_t)n * HW + hw0 + i) * C2 + c0 + tx];
    __syncthreads();
#pragma unroll
    for (int i = ty; i < 32; i += 8) {
        int c = c0 + i, hw = hw0 + tx;
        float v = t[tx][i];
        float s = g[c] * rsqrtf(1.0f + BN_EPS);
        v = silu(fmaf(v, s, b[c]));
        size_t idx = ((size_t)n * C2 + c) * HW + hw;
        out[idx] = xres[idx] + v;
    }
}

// ---------------------------------------------------------------------------
// Launch
// ---------------------------------------------------------------------------
extern "C" void kernel_launch(void* const* d_in, const int* in_sizes, int n_in,
                              void* d_out, int out_size) {
    const float* x     = (const float*)d_in[0];
    const float* cv1_w = (const float*)d_in[1];
    const float* cv1_g = (const float*)d_in[2];
    const float* cv1_b = (const float*)d_in[3];
    const float* pw_w  = (const float*)d_in[4];
    const float* pw_g  = (const float*)d_in[5];
    const float* pw_b  = (const float*)d_in[6];
    const float* dw_w  = (const float*)d_in[7];
    const float* dw_b  = (const float*)d_in[8];
    const float* ln_g  = (const float*)d_in[9];
    const float* ln_b  = (const float*)d_in[10];
    const float* off_w = (const float*)d_in[11];
    const float* off_b = (const float*)d_in[12];
    const float* msk_w = (const float*)d_in[13];
    const float* msk_b = (const float*)d_in[14];
    const float* inp_w = (const float*)d_in[15];
    const float* inp_b = (const float*)d_in[16];
    const float* out_w = (const float*)d_in[17];
    const float* out_b = (const float*)d_in[18];
    const float* bn2_g = (const float*)d_in[19];
    const float* bn2_b = (const float*)d_in[20];

    float* sc = nullptr;
    cudaGetSymbolAddress((void**)&sc, g_scratch);
    hlf* xhi  = (hlf*)(sc + OFF_XHI);
    hlf* y1hi = (hlf*)(sc + OFF_Y1HI);
    hlf* y1lo = (hlf*)(sc + OFF_Y1LO);
    float* y2f = sc + OFF_Y2F;
    hlf* y2hi = (hlf*)(sc + OFF_Y2HI);
    hlf* y2lo = (hlf*)(sc + OFF_Y2LO);
    hlf* x1hi = (hlf*)(sc + OFF_X1HI);
    hlf* x1lo = (hlf*)(sc + OFF_X1LO);
    float* xproj = sc + OFF_XPROJ;
    float* om    = sc + OFF_OM;
    hlf* chi  = (hlf*)(sc + OFF_CHI);
    hlf* clo  = (hlf*)(sc + OFF_CLO);
    float* onh = sc + OFF_ONH;
    hlf* wt9h = (hlf*)(sc + OFF_WT9H);
    hlf* pwh  = (hlf*)(sc + OFF_PWH);
    hlf* inh  = (hlf*)(sc + OFF_INH);
    hlf* ouh  = (hlf*)(sc + OFF_OUH);
    hlf* hwh  = (hlf*)(sc + OFF_HWH);
    float* hb = sc + OFF_HB;
    float* outp = (float*)d_out;

    cudaFuncSetAttribute(mma_conv_k, cudaFuncAttributeMaxDynamicSharedMemorySize, CONV_SMEM);
    cudaFuncSetAttribute(mma_gemm_k<128, 0>, cudaFuncAttributeMaxDynamicSharedMemorySize, GEMM_SMEM);
    cudaFuncSetAttribute(mma_gemm_k<256, 1>, cudaFuncAttributeMaxDynamicSharedMemorySize, GEMM_SMEM);
    cudaFuncSetAttribute(mma_head_k, cudaFuncAttributeMaxDynamicSharedMemorySize, HEAD_SMEM);

    // 0) preprocessing
    prep_x_k<<<dim3(HW / 32, C1 / 32, NB), 256>>>(x, xhi);
    int prep_tot = 9 * CM * C1 + C2 * CM + 2 * C2 * C2 + 32 * C2 + 32;
    prep_w_k<<<(prep_tot + 255) / 256, 256>>>(
        cv1_w, pw_w, inp_w, out_w, off_w, msk_w, off_b, msk_b,
        wt9h, pwh, inh, ouh, hwh, hb);

    // 1) cv1 (1-term fp16) -> y1 hi/lo
    mma_conv_k<<<NPIX / 64, 256, CONV_SMEM>>>(
        xhi, wt9h, cv1_g, cv1_b, y1hi, y1lo);

    // 2) pw (2-term) -> y2 f32 + hi/lo
    mma_gemm_k<128, 0><<<dim3(NPIX / 64, 2), 256, GEMM_SMEM>>>(
        y1hi, y1lo, pwh, pw_g, pw_b, y2f, y2hi, y2lo);

    // 3) dw + LN + GELU -> x1 hi/lo
    dw_ln_gelu_k<<<NPIX, 256>>>(y2f, dw_w, dw_b, ln_g, ln_b, x1hi, x1lo);

    // 4) offset/mask heads -> om (logits)
    mma_head_k<<<NPIX / 128, 256, HEAD_SMEM>>>(x1hi, x1lo, hwh, hb, om);

    // 5) input_proj (2-term) -> xproj f32
    mma_gemm_k<256, 1><<<dim3(NPIX / 64, 2), 256, GEMM_SMEM>>>(
        y2hi, y2lo, inh, inp_b, nullptr, xproj, nullptr, nullptr);

    // 6) DCNv3 core (softmax inside) -> hi/lo
    dcnv3_k<<<NPIX, 256>>>(xproj, om, chi, clo);

    // 7) output_proj (2-term) -> onh f32
    mma_gemm_k<256, 1><<<dim3(NPIX / 64, 2), 256, GEMM_SMEM>>>(
        chi, clo, ouh, out_b, nullptr, onh, nullptr, nullptr);

    // 8) BN2 + SiLU + residual + transpose -> d_out
    bn2_res_transpose_k<<<dim3(HW / 32, C2 / 32, NB), 256>>>(onh, x, bn2_g, bn2_b, outp);
}

// round 10
// speedup vs baseline: 4.7490x; 1.0426x over previous
#include <cuda_runtime.h>
#include <cuda_fp16.h>
#include <math.h>
#include <stdint.h>

// ---------------------------------------------------------------------------
// Problem constants
// ---------------------------------------------------------------------------
#define NB   4
#define C1   256
#define CM   128
#define C2   256
#define HW   4096
#define NPIX (NB*HW)
#define PP   9
#define BN_EPS 1e-5f
#define LN_EPS 1e-6f

typedef __half hlf;

// ---------------------------------------------------------------------------
// Scratch (offsets in floats)
// ---------------------------------------------------------------------------
#define OFF_XHI   0                          // NPIX*C1 fp16
#define OFF_Y1HI  (OFF_XHI  + NPIX*C1/2)     // NPIX*CM fp16 hi/lo
#define OFF_Y1LO  (OFF_Y1HI + NPIX*CM/2)
#define OFF_Y2HI  (OFF_Y1LO + NPIX*CM/2)     // NPIX*C2 fp16 hi/lo
#define OFF_Y2LO  (OFF_Y2HI + NPIX*C2/2)
#define OFF_X1HI  (OFF_Y2LO + NPIX*C2/2)
#define OFF_X1LO  (OFF_X1HI + NPIX*C2/2)
#define OFF_XPROJ (OFF_X1LO + NPIX*C2/2)     // f32
#define OFF_OM    (OFF_XPROJ+ NPIX*C2)
#define OFF_CHI   (OFF_OM   + NPIX*27)       // fp16 (1-term)
#define OFF_ONH   (OFF_CHI  + NPIX*C2/2)     // f32
#define OFF_WT9H  (OFF_ONH  + NPIX*C2)       // 9*128*256 fp16 [tap][co][ci]
#define OFF_PWH   (OFF_WT9H + 9*CM*C1/2)
#define OFF_INH   (OFF_PWH  + C2*CM/2)
#define OFF_OUH   (OFF_INH  + C2*C2/2)
#define OFF_HWH   (OFF_OUH  + C2*C2/2)       // 32*256 fp16 head weights
#define OFF_HB    (OFF_HWH  + 32*C2/2)       // 32 f32 head bias
#define SCRATCH_FLOATS (OFF_HB + 32)

__device__ __align__(16) float g_scratch[SCRATCH_FLOATS];

__device__ __forceinline__ float silu(float v) { return v / (1.0f + expf(-v)); }

__device__ __forceinline__ void split_h(float v, hlf& h, hlf& l) {
    h = __float2half_rn(v);
    l = __float2half_rn(v - __half2float(h));
}
__device__ __forceinline__ uint32_t pack_pair(float a, float b, bool lo) {
    hlf ha, la, hb, lbv;
    split_h(a, ha, la); split_h(b, hb, lbv);
    if (!lo) return ((uint32_t)*(uint16_t*)&hb << 16) | *(uint16_t*)&ha;
    else     return ((uint32_t)*(uint16_t*)&lbv << 16) | *(uint16_t*)&la;
}
__device__ __forceinline__ uint32_t pack_h2(float a, float b) {
    hlf ha = __float2half_rn(a), hb = __float2half_rn(b);
    return ((uint32_t)*(uint16_t*)&hb << 16) | *(uint16_t*)&ha;
}

// ---------------------------------------------------------------------------
// mma.sync + ldmatrix + cp.async (portable sm_80 PTX)
// ---------------------------------------------------------------------------
__device__ __forceinline__ void mma16816(float* d, const uint32_t* a, const uint32_t* b) {
    asm volatile("mma.sync.aligned.m16n8k16.row.col.f32.f16.f16.f32 "
        "{%0,%1,%2,%3}, {%4,%5,%6,%7}, {%8,%9}, {%0,%1,%2,%3};"
        : "+f"(d[0]), "+f"(d[1]), "+f"(d[2]), "+f"(d[3])
        : "r"(a[0]), "r"(a[1]), "r"(a[2]), "r"(a[3]), "r"(b[0]), "r"(b[1]));
}
__device__ __forceinline__ void ldm4(uint32_t* r, uint32_t addr) {
    asm volatile("ldmatrix.sync.aligned.m8n8.x4.shared.b16 {%0,%1,%2,%3}, [%4];"
        : "=r"(r[0]), "=r"(r[1]), "=r"(r[2]), "=r"(r[3]) : "r"(addr));
}
__device__ __forceinline__ void cp16(uint32_t dst, const void* src) {
    asm volatile("cp.async.cg.shared.global [%0], [%1], 16;" :: "r"(dst), "l"(src));
}
__device__ __forceinline__ void cp16z(uint32_t dst, const void* src, int srcsize) {
    asm volatile("cp.async.cg.shared.global [%0], [%1], 16, %2;"
                 :: "r"(dst), "l"(src), "r"(srcsize));
}
#define CP_COMMIT() asm volatile("cp.async.commit_group;" ::: "memory")
#define CP_WAIT1()  asm volatile("cp.async.wait_group 1;" ::: "memory")

// SMEM row: 32 fp16 = 16 words, padded to 20 (conflict-free for ldmatrix)
#define TS 20
#define AW  (64 * TS)
#define BW  (128 * TS)
#define CONV_STW (AW + BW)
#define CONV_SMEM (2 * CONV_STW * 4)
#define GEMM_STW1 (AW + BW)
#define GEMM_STW2 (2*AW + BW)
#define GEMM_SMEM1 (2 * GEMM_STW1 * 4)
#define GEMM_SMEM2 (2 * GEMM_STW2 * 4)

// ---------------------------------------------------------------------------
// prep_x: NCHW f32 -> NHWC fp16
// ---------------------------------------------------------------------------
__global__ __launch_bounds__(256) void prep_x_k(
    const float* __restrict__ x, hlf* __restrict__ xhi)
{
    __shared__ float t[32][33];
    const int n = blockIdx.z, hw0 = blockIdx.x * 32, c0 = blockIdx.y * 32;
    const int tx = threadIdx.x & 31, ty = threadIdx.x >> 5;
#pragma unroll
    for (int i = ty; i < 32; i += 8)
        t[i][tx] = x[((size_t)n * C1 + c0 + i) * HW + hw0 + tx];
    __syncthreads();
#pragma unroll
    for (int i = ty; i < 32; i += 8) {
        size_t idx = ((size_t)n * HW + hw0 + i) * C1 + c0 + tx;
        xhi[idx] = __float2half_rn(t[tx][i]);
    }
}

// ---------------------------------------------------------------------------
// prep_w: all weights -> fp16; cv1 -> [tap][co][ci]; head pack
// ---------------------------------------------------------------------------
__global__ __launch_bounds__(256) void prep_w_k(
    const float* __restrict__ cv1w, const float* __restrict__ pww,
    const float* __restrict__ inpw, const float* __restrict__ outw,
    const float* __restrict__ offw, const float* __restrict__ mskw,
    const float* __restrict__ offb, const float* __restrict__ mskb,
    hlf* __restrict__ wt9h, hlf* __restrict__ pwh,
    hlf* __restrict__ inh,  hlf* __restrict__ ouh,
    hlf* __restrict__ hwh,  float* __restrict__ hb)
{
    int idx = blockIdx.x * 256 + threadIdx.x;
    const int N1 = 9 * CM * C1;
    if (idx < N1) {
        int tap = idx / (CM * C1);
        int rem = idx - tap * CM * C1;
        int co = rem >> 8, ci = rem & 255;
        wt9h[idx] = __float2half_rn(cv1w[(size_t)co * (C1 * 9) + ci * 9 + tap]);
        return;
    }
    idx -= N1;
    if (idx < C2 * CM) { pwh[idx] = __float2half_rn(pww[idx]); return; }
    idx -= C2 * CM;
    if (idx < C2 * C2) { inh[idx] = __float2half_rn(inpw[idx]); return; }
    idx -= C2 * C2;
    if (idx < C2 * C2) { ouh[idx] = __float2half_rn(outw[idx]); return; }
    idx -= C2 * C2;
    if (idx < 32 * C2) {
        int j = idx >> 8, k = idx & 255;
        float v = (j < 18) ? offw[j * C2 + k] : ((j < 27) ? mskw[(j - 18) * C2 + k] : 0.0f);
        hwh[idx] = __float2half_rn(v); return;
    }
    idx -= 32 * C2;
    if (idx < 32)
        hb[idx] = (idx < 18) ? offb[idx] : ((idx < 27) ? mskb[idx - 18] : 0.0f);
}

// ---------------------------------------------------------------------------
// Inner MMA via ldmatrix. A tile 64x32 (ATERMS arrays), B tile 128x32.
// ---------------------------------------------------------------------------
template<int ATERMS>
__device__ __forceinline__ void mma_step(
    uint32_t aHi, uint32_t aLo, uint32_t bHi,
    int wm, int wn, int lane, float acc[2][4][4])
{
    const int arow = (lane & 7) + ((lane >> 3) & 1) * 8;
    const int akt  = (lane >> 4) & 1;
    const int brow = (lane & 7) + ((lane >> 4) & 1) * 8;
    const int bkt  = (lane >> 3) & 1;
#pragma unroll
    for (int ks = 0; ks < 2; ks++) {
        uint32_t ahi[2][4], alo[2][4], bhi[2][4];
#pragma unroll
        for (int mt = 0; mt < 2; mt++) {
            uint32_t off = (uint32_t)(((wm * 32 + mt * 16 + arow) * TS + ks * 8 + akt * 4) * 4);
            ldm4(ahi[mt], aHi + off);
            if (ATERMS == 2) ldm4(alo[mt], aLo + off);
        }
#pragma unroll
        for (int np = 0; np < 2; np++) {
            uint32_t off = (uint32_t)(((wn * 32 + np * 16 + brow) * TS + ks * 8 + bkt * 4) * 4);
            ldm4(bhi[np], bHi + off);
        }
#pragma unroll
        for (int mt = 0; mt < 2; mt++)
#pragma unroll
            for (int nt = 0; nt < 4; nt++) {
                const uint32_t* bh = &bhi[nt >> 1][(nt & 1) * 2];
                mma16816(acc[mt][nt], ahi[mt], bh);
                if (ATERMS == 2) mma16816(acc[mt][nt], alo[mt], bh);
            }
    }
}

// ---------------------------------------------------------------------------
// mma_conv: cv1 3x3 (256->128) + BN + SiLU. 1-term pure fp16.
// ---------------------------------------------------------------------------
__global__ __launch_bounds__(256, 2) void mma_conv_k(
    const hlf* __restrict__ xhi, const hlf* __restrict__ wth,
    const float* __restrict__ g, const float* __restrict__ b,
    hlf* __restrict__ y1hi, hlf* __restrict__ y1lo)
{
    extern __shared__ __align__(16) uint32_t dsm[];
    const uint32_t sbase = (uint32_t)__cvta_generic_to_shared(dsm);

    const int tid = threadIdx.x, wid = tid >> 5, lane = tid & 31;
    const int wm = wid >> 2, wn = wid & 3, qr = lane >> 2, qc = lane & 3;
    const int pix0 = blockIdx.x * 64;
    const int n = pix0 >> 12, hb2 = (pix0 & 4095) >> 6;
    const int r0 = tid >> 2, ch0 = tid & 3;

    float acc[2][4][4];
#pragma unroll
    for (int mt = 0; mt < 2; mt++)
#pragma unroll
        for (int nt = 0; nt < 4; nt++)
#pragma unroll
            for (int q = 0; q < 4; q++) acc[mt][nt][q] = 0.0f;

    const int TOT = 72;
    auto stage = [&](int it) {
        const int tap = it / 8, kc = it & 7;
        const int dh = tap / 3 - 1, dw = tap % 3 - 1;
        const uint32_t sb = sbase + (uint32_t)(it & 1) * (CONV_STW * 4);
        {
            int hh = hb2 + dh, ww = r0 + dw;
            bool val = ((unsigned)hh < 64u) && ((unsigned)ww < 64u);
            size_t u4 = val ? ((size_t)(n * HW + hh * 64 + ww) * 32 + kc * 4 + ch0) : 0;
            int sz = val ? 16 : 0;
            uint32_t rowoff = (uint32_t)(r0 * TS + ch0 * 4) * 4;
            cp16z(sb + rowoff, (const char*)xhi + u4 * 16, sz);
        }
#pragma unroll
        for (int i = 0; i < 2; i++) {
            int r = r0 + i * 64;
            size_t w4 = (size_t)(tap * CM + r) * 32 + kc * 4 + ch0;
            uint32_t rowoff = (uint32_t)(r * TS + ch0 * 4) * 4;
            cp16(sb + AW * 4 + rowoff, (const char*)wth + w4 * 16);
        }
    };

    stage(0); CP_COMMIT();
    for (int it = 0; it < TOT; it++) {
        if (it + 1 < TOT) stage(it + 1);
        CP_COMMIT();
        CP_WAIT1();
        __syncthreads();
        uint32_t sb = sbase + (uint32_t)(it & 1) * (CONV_STW * 4);
        mma_step<1>(sb, 0, sb + AW * 4, wm, wn, lane, acc);
        __syncthreads();
    }

#pragma unroll
    for (int nt = 0; nt < 4; nt++) {
        int c = wn * 32 + nt * 8 + qc * 2;
        float s0 = g[c] * rsqrtf(1.0f + BN_EPS),     b0 = b[c];
        float s1 = g[c + 1] * rsqrtf(1.0f + BN_EPS), b1 = b[c + 1];
#pragma unroll
        for (int mt = 0; mt < 2; mt++) {
            int row = wm * 32 + mt * 16 + qr;
#pragma unroll
            for (int half = 0; half < 2; half++) {
                int pix = pix0 + row + half * 8;
                float v0 = silu(fmaf(acc[mt][nt][half * 2 + 0], s0, b0));
                float v1 = silu(fmaf(acc[mt][nt][half * 2 + 1], s1, b1));
                *(uint32_t*)&y1hi[(size_t)pix * CM + c] = pack_pair(v0, v1, false);
                *(uint32_t*)&y1lo[(size_t)pix * CM + c] = pack_pair(v0, v1, true);
            }
        }
    }
}

// ---------------------------------------------------------------------------
// mma_gemm: C[M,256] = A[M,K] @ Wfp16[256,K]^T.
// ATERMS=2: A = hi+lo (exact split).  ATERMS=1: A = fp16.
// MODE 0: BN+SiLU -> hi/lo fp16 only.  MODE 1: +bias -> f32.
// ---------------------------------------------------------------------------
template<int K, int MODE, int ATERMS>
__global__ __launch_bounds__(256, 2) void mma_gemm_k(
    const hlf* __restrict__ Ahi, const hlf* __restrict__ Alo,
    const hlf* __restrict__ Whi,
    const float* __restrict__ p0, const float* __restrict__ p1,
    float* __restrict__ outf, hlf* __restrict__ outhi, hlf* __restrict__ outlo)
{
    extern __shared__ __align__(16) uint32_t dsm[];
    const uint32_t sbase = (uint32_t)__cvta_generic_to_shared(dsm);
    constexpr int STW = ATERMS * AW + BW;

    const int tid = threadIdx.x, wid = tid >> 5, lane = tid & 31;
    const int wm = wid >> 2, wn = wid & 3, qr = lane >> 2, qc = lane & 3;
    const int pix0 = blockIdx.x * 64;
    const int nh = blockIdx.y;
    const int r0 = tid >> 2, ch0 = tid & 3;

    constexpr int TOT = K / 32;

    float acc[2][4][4];
#pragma unroll
    for (int mt = 0; mt < 2; mt++)
#pragma unroll
        for (int nt = 0; nt < 4; nt++)
#pragma unroll
            for (int q = 0; q < 4; q++) acc[mt][nt][q] = 0.0f;

    auto stage = [&](int it) {
        const int kc = it;
        const uint32_t sb = sbase + (uint32_t)(it & 1) * (STW * 4);
        {
            size_t a4 = (size_t)(pix0 + r0) * (K / 8) + kc * 4 + ch0;
            uint32_t rowoff = (uint32_t)(r0 * TS + ch0 * 4) * 4;
            cp16(sb + rowoff, (const char*)Ahi + a4 * 16);
            if (ATERMS == 2) cp16(sb + AW * 4 + rowoff, (const char*)Alo + a4 * 16);
        }
#pragma unroll
        for (int i = 0; i < 2; i++) {
            int r = r0 + i * 64;
            size_t b4 = (size_t)(nh * 128 + r) * (K / 8) + kc * 4 + ch0;
            uint32_t rowoff = (uint32_t)(r * TS + ch0 * 4) * 4;
            cp16(sb + ATERMS * AW * 4 + rowoff, (const char*)Whi + b4 * 16);
        }
    };

    stage(0); CP_COMMIT();
    for (int it = 0; it < TOT; it++) {
        if (it + 1 < TOT) stage(it + 1);
        CP_COMMIT();
        CP_WAIT1();
        __syncthreads();
        uint32_t sb = sbase + (uint32_t)(it & 1) * (STW * 4);
        mma_step<ATERMS>(sb, sb + AW * 4, sb + ATERMS * AW * 4, wm, wn, lane, acc);
        __syncthreads();
    }

#pragma unroll
    for (int nt = 0; nt < 4; nt++) {
        int c = nh * 128 + wn * 32 + nt * 8 + qc * 2;
        float s0, b0, s1, b1;
        if (MODE == 0) {
            s0 = p0[c] * rsqrtf(1.0f + BN_EPS);     b0 = p1[c];
            s1 = p0[c + 1] * rsqrtf(1.0f + BN_EPS); b1 = p1[c + 1];
        } else {
            b0 = p0[c]; b1 = p0[c + 1]; s0 = s1 = 1.0f;
        }
#pragma unroll
        for (int mt = 0; mt < 2; mt++) {
            int row = wm * 32 + mt * 16 + qr;
#pragma unroll
            for (int half = 0; half < 2; half++) {
                int pix = pix0 + row + half * 8;
                if (MODE == 0) {
                    float v0 = silu(fmaf(acc[mt][nt][half * 2 + 0], s0, b0));
                    float v1 = silu(fmaf(acc[mt][nt][half * 2 + 1], s1, b1));
                    *(uint32_t*)&outhi[(size_t)pix * C2 + c] = pack_pair(v0, v1, false);
                    *(uint32_t*)&outlo[(size_t)pix * C2 + c] = pack_pair(v0, v1, true);
                } else {
                    float v0 = acc[mt][nt][half * 2 + 0] + b0;
                    float v1 = acc[mt][nt][half * 2 + 1] + b1;
                    *(float2*)&outf[(size_t)pix * C2 + c] = make_float2(v0, v1);
                }
            }
        }
    }
}

// ---------------------------------------------------------------------------
// mma_head: om[M,27] = (x1hi+x1lo)[M,256] @ HW16[32,256]^T + hb (2-term).
// ---------------------------------------------------------------------------
#define BS2 132
#define HEAD_SMEM ((2*128*TS + 32*BS2) * 4)
__global__ __launch_bounds__(256) void mma_head_k(
    const hlf* __restrict__ x1hi, const hlf* __restrict__ x1lo,
    const hlf* __restrict__ hwh,
    const float* __restrict__ hb, float* __restrict__ om)
{
    extern __shared__ __align__(16) uint32_t dsm[];
    const uint32_t sbase = (uint32_t)__cvta_generic_to_shared(dsm);
    const uint32_t AHI = 0, ALO = 128 * TS, BHI = 2 * 128 * TS;

    const int tid = threadIdx.x, wid = tid >> 5, lane = tid & 31;
    const int pix0 = blockIdx.x * 128;

    for (int i = tid; i < 1024; i += 256) {
        int row = i >> 5, ch = i & 31;
        *(uint4*)&dsm[BHI + row * BS2 + ch * 4] = ((const uint4*)hwh)[row * 32 + ch];
    }

    float acc[4][4];
#pragma unroll
    for (int nt = 0; nt < 4; nt++)
#pragma unroll
        for (int q = 0; q < 4; q++) acc[nt][q] = 0.0f;

    const int arow = (lane & 7) + ((lane >> 3) & 1) * 8;
    const int akt  = (lane >> 4) & 1;
    const int brow = (lane & 7) + ((lane >> 4) & 1) * 8;
    const int bkt  = (lane >> 3) & 1;

    for (int kc = 0; kc < 8; kc++) {
        __syncthreads();
        for (int i = tid; i < 1024; i += 256) {
            int arr = i >> 9, j = i & 511;
            int row = j >> 2, ch = j & 3;
            const uint4 v = ((const uint4*)(arr ? x1lo : x1hi))[(size_t)(pix0 + row) * 32 + kc * 4 + ch];
            *(uint4*)&dsm[(arr ? ALO : AHI) + row * TS + ch * 4] = v;
        }
        __syncthreads();
#pragma unroll
        for (int ks = 0; ks < 2; ks++) {
            uint32_t ahi[4], alo[4], bhi[2][4];
            uint32_t aoff = (uint32_t)(((wid * 16 + arow) * TS + ks * 8 + akt * 4) * 4);
            ldm4(ahi, sbase + AHI * 4 + aoff);
            ldm4(alo, sbase + ALO * 4 + aoff);
#pragma unroll
            for (int np = 0; np < 2; np++) {
                uint32_t boff = (uint32_t)(((np * 16 + brow) * BS2 + kc * 16 + ks * 8 + bkt * 4) * 4);
                ldm4(bhi[np], sbase + BHI * 4 + boff);
            }
#pragma unroll
            for (int nt = 0; nt < 4; nt++) {
                const uint32_t* bh = &bhi[nt >> 1][(nt & 1) * 2];
                mma16816(acc[nt], ahi, bh);
                mma16816(acc[nt], alo, bh);
            }
        }
    }

#pragma unroll
    for (int nt = 0; nt < 4; nt++) {
        int c = nt * 8 + (lane & 3) * 2;
        int r0p = pix0 + wid * 16 + (lane >> 2);
#pragma unroll
        for (int half = 0; half < 2; half++) {
            int pix = r0p + half * 8;
            float v0 = acc[nt][half * 2 + 0] + hb[c];
            float v1 = acc[nt][half * 2 + 1] + hb[c + 1];
            if (c < 27)     om[(size_t)pix * 27 + c]     = v0;
            if (c + 1 < 27) om[(size_t)pix * 27 + c + 1] = v1;
        }
    }
}

// ---------------------------------------------------------------------------
// Fused: depthwise 3x3 (on fp16 y2hi) + LN + GELU -> x1 hi/lo
// ---------------------------------------------------------------------------
__global__ __launch_bounds__(256) void dw_ln_gelu_k(
    const hlf* __restrict__ y2h,
    const float* __restrict__ dww, const float* __restrict__ dwb,
    const float* __restrict__ lg,  const float* __restrict__ lb,
    hlf* __restrict__ x1hi, hlf* __restrict__ x1lo)
{
    const int pix = blockIdx.x;
    const int n = pix >> 12, hw = pix & 4095, h = hw >> 6, w = hw & 63;
    const int c = threadIdx.x;

    float v = dwb[c];
#pragma unroll
    for (int kh = 0; kh < 3; kh++)
#pragma unroll
        for (int kw = 0; kw < 3; kw++) {
            int hh = h + kh - 1, wk = w + kw - 1;
            if ((unsigned)hh < 64u && (unsigned)wk < 64u)
                v = fmaf(__half2float(y2h[(((size_t)n * HW) + hh * 64 + wk) * C2 + c]),
                         dww[c * 9 + kh * 3 + kw], v);
        }

    __shared__ float s1[256];
    __shared__ float s2[256];
    s1[c] = v; s2[c] = v * v;
    __syncthreads();
#pragma unroll
    for (int off = 128; off > 32; off >>= 1) {
        if (c < off) { s1[c] += s1[c + off]; s2[c] += s2[c + off]; }
        __syncthreads();
    }
    if (c < 32) {
        float a1 = s1[c] + s1[c + 32];
        float a2 = s2[c] + s2[c + 32];
#pragma unroll
        for (int o = 16; o > 0; o >>= 1) {
            a1 += __shfl_down_sync(0xffffffffu, a1, o);
            a2 += __shfl_down_sync(0xffffffffu, a2, o);
        }
        if (c == 0) { s1[0] = a1; s2[0] = a2; }
    }
    __syncthreads();
    float mean = s1[0] * (1.0f / 256.0f);
    float var  = s2[0] * (1.0f / 256.0f) - mean * mean;

    float t = fmaf((v - mean) * rsqrtf(var + LN_EPS), lg[c], lb[c]);
    float gelu = 0.5f * t * (1.0f + erff(t * 0.70710678118654752f));

    hlf hh2, ll2; split_h(gelu, hh2, ll2);
    x1hi[(size_t)pix * C2 + c] = hh2;
    x1lo[(size_t)pix * C2 + c] = ll2;
}

// ---------------------------------------------------------------------------
// DCNv3 core (mask softmax in-kernel) -> fp16 (1-term)
// ---------------------------------------------------------------------------
__global__ __launch_bounds__(256) void dcnv3_k(
    const float* __restrict__ xproj, const float* __restrict__ om,
    hlf* __restrict__ chi)
{
    const int pix = blockIdx.x;
    const int n = pix >> 12, hw = pix & 4095, h = hw >> 6, w = hw & 63;
    const int c = threadIdx.x;

    __shared__ float o[32];
    if (c < 27) o[c] = om[(size_t)pix * 27 + c];
    __syncthreads();
    if (c == 0) {
        float mx = -1e30f;
#pragma unroll
        for (int q = 0; q < 9; q++) mx = fmaxf(mx, o[18 + q]);
        float e[9], sum = 0.0f;
#pragma unroll
        for (int q = 0; q < 9; q++) { e[q] = expf(o[18 + q] - mx); sum += e[q]; }
        float inv = 1.0f / sum;
#pragma unroll
        for (int q = 0; q < 9; q++) o[18 + q] = e[q] * inv;
    }
    __syncthreads();

    const float* base = xproj + (size_t)n * HW * C2;
    float acc = 0.0f;

#pragma unroll
    for (int p = 0; p < PP; p++) {
        float px = (float)(w + (p / 3)) + o[2 * p];
        float py = (float)(h + (p % 3)) + o[2 * p + 1];
        float x0f = floorf(px), y0f = floorf(py);
        float fx = px - x0f, fy = py - y0f;
        int x0 = (int)x0f, y0 = (int)y0f;
        float mk = o[18 + p];
        float s = 0.0f;
#pragma unroll
        for (int dy = 0; dy < 2; dy++)
#pragma unroll
            for (int dx = 0; dx < 2; dx++) {
                int xi = x0 + dx, yi = y0 + dy;
                if (xi >= 1 && xi <= 64 && yi >= 1 && yi <= 64) {
                    float wgt = (dx ? fx : 1.0f - fx) * (dy ? fy : 1.0f - fy);
                    s = fmaf(wgt, base[((size_t)(yi - 1) * 64 + (xi - 1)) * C2 + c], s);
                }
            }
        acc = fmaf(mk, s, acc);
    }
    chi[(size_t)pix * C2 + c] = __float2half_rn(acc);
}

// ---------------------------------------------------------------------------
// NHWC->NCHW + BN2 + SiLU + residual
// ---------------------------------------------------------------------------
__global__ __launch_bounds__(256) void bn2_res_transpose_k(
    const float* __restrict__ o, const float* __restrict__ xres,
    const float* __restrict__ g, const float* __restrict__ b,
    float* __restrict__ out)
{
    __shared__ float t[32][33];
    const int n = blockIdx.z, hw0 = blockIdx.x * 32, c0 = blockIdx.y * 32;
    const int tx = threadIdx.x & 31, ty = threadIdx.x >> 5;
#pragma unroll
    for (int i = ty; i < 32; i += 8)
        t[i][tx] = o[((size_t)n * HW + hw0 + i) * C2 + c0 + tx];
    __syncthreads();
#pragma unroll
    for (int i = ty; i < 32; i += 8) {
        int c = c0 + i, hw = hw0 + tx;
        float v = t[tx][i];
        float s = g[c] * rsqrtf(1.0f + BN_EPS);
        v = silu(fmaf(v, s, b[c]));
        size_t idx = ((size_t)n * C2 + c) * HW + hw;
        out[idx] = xres[idx] + v;
    }
}

// ---------------------------------------------------------------------------
// Launch
// ---------------------------------------------------------------------------
extern "C" void kernel_launch(void* const* d_in, const int* in_sizes, int n_in,
                              void* d_out, int out_size) {
    const float* x     = (const float*)d_in[0];
    const float* cv1_w = (const float*)d_in[1];
    const float* cv1_g = (const float*)d_in[2];
    const float* cv1_b = (const float*)d_in[3];
    const float* pw_w  = (const float*)d_in[4];
    const float* pw_g  = (const float*)d_in[5];
    const float* pw_b  = (const float*)d_in[6];
    const float* dw_w  = (const float*)d_in[7];
    const float* dw_b  = (const float*)d_in[8];
    const float* ln_g  = (const float*)d_in[9];
    const float* ln_b  = (const float*)d_in[10];
    const float* off_w = (const float*)d_in[11];
    const float* off_b = (const float*)d_in[12];
    const float* msk_w = (const float*)d_in[13];
    const float* msk_b = (const float*)d_in[14];
    const float* inp_w = (const float*)d_in[15];
    const float* inp_b = (const float*)d_in[16];
    const float* out_w = (const float*)d_in[17];
    const float* out_b = (const float*)d_in[18];
    const float* bn2_g = (const float*)d_in[19];
    const float* bn2_b = (const float*)d_in[20];

    float* sc = nullptr;
    cudaGetSymbolAddress((void**)&sc, g_scratch);
    hlf* xhi  = (hlf*)(sc + OFF_XHI);
    hlf* y1hi = (hlf*)(sc + OFF_Y1HI);
    hlf* y1lo = (hlf*)(sc + OFF_Y1LO);
    hlf* y2hi = (hlf*)(sc + OFF_Y2HI);
    hlf* y2lo = (hlf*)(sc + OFF_Y2LO);
    hlf* x1hi = (hlf*)(sc + OFF_X1HI);
    hlf* x1lo = (hlf*)(sc + OFF_X1LO);
    float* xproj = sc + OFF_XPROJ;
    float* om    = sc + OFF_OM;
    hlf* chi  = (hlf*)(sc + OFF_CHI);
    float* onh = sc + OFF_ONH;
    hlf* wt9h = (hlf*)(sc + OFF_WT9H);
    hlf* pwh  = (hlf*)(sc + OFF_PWH);
    hlf* inh  = (hlf*)(sc + OFF_INH);
    hlf* ouh  = (hlf*)(sc + OFF_OUH);
    hlf* hwh  = (hlf*)(sc + OFF_HWH);
    float* hb = sc + OFF_HB;
    float* outp = (float*)d_out;

    cudaFuncSetAttribute(mma_conv_k, cudaFuncAttributeMaxDynamicSharedMemorySize, CONV_SMEM);
    cudaFuncSetAttribute(mma_gemm_k<128, 0, 2>, cudaFuncAttributeMaxDynamicSharedMemorySize, GEMM_SMEM2);
    cudaFuncSetAttribute(mma_gemm_k<256, 1, 1>, cudaFuncAttributeMaxDynamicSharedMemorySize, GEMM_SMEM1);
    cudaFuncSetAttribute(mma_head_k, cudaFuncAttributeMaxDynamicSharedMemorySize, HEAD_SMEM);

    // 0) preprocessing
    prep_x_k<<<dim3(HW / 32, C1 / 32, NB), 256>>>(x, xhi);
    int prep_tot = 9 * CM * C1 + C2 * CM + 2 * C2 * C2 + 32 * C2 + 32;
    prep_w_k<<<(prep_tot + 255) / 256, 256>>>(
        cv1_w, pw_w, inp_w, out_w, off_w, msk_w, off_b, msk_b,
        wt9h, pwh, inh, ouh, hwh, hb);

    // 1) cv1 (1-term fp16) -> y1 hi/lo
    mma_conv_k<<<NPIX / 64, 256, CONV_SMEM>>>(
        xhi, wt9h, cv1_g, cv1_b, y1hi, y1lo);

    // 2) pw (2-term) -> y2 hi/lo (no f32)
    mma_gemm_k<128, 0, 2><<<dim3(NPIX / 64, 2), 256, GEMM_SMEM2>>>(
        y1hi, y1lo, pwh, pw_g, pw_b, nullptr, y2hi, y2lo);

    // 3) dw (fp16 input) + LN + GELU -> x1 hi/lo
    dw_ln_gelu_k<<<NPIX, 256>>>(y2hi, dw_w, dw_b, ln_g, ln_b, x1hi, x1lo);

    // 4) offset/mask heads -> om (logits)
    mma_head_k<<<NPIX / 128, 256, HEAD_SMEM>>>(x1hi, x1lo, hwh, hb, om);

    // 5) input_proj (1-term on y2hi) -> xproj f32
    mma_gemm_k<256, 1, 1><<<dim3(NPIX / 64, 2), 256, GEMM_SMEM1>>>(
        y2hi, nullptr, inh, inp_b, nullptr, xproj, nullptr, nullptr);

    // 6) DCNv3 core (softmax inside) -> chi fp16
    dcnv3_k<<<NPIX, 256>>>(xproj, om, chi);

    // 7) output_proj (1-term on chi) -> onh f32
    mma_gemm_k<256, 1, 1><<<dim3(NPIX / 64, 2), 256, GEMM_SMEM1>>>(
        chi, nullptr, ouh, out_b, nullptr, onh, nullptr, nullptr);

    // 8) BN2 + SiLU + residual + transpose -> d_out
    bn2_res_transpose_k<<<dim3(HW / 32, C2 / 32, NB), 256>>>(onh, x, bn2_g, bn2_b, outp);
}

// round 11
// speedup vs baseline: 5.4639x; 1.1505x over previous
#include <cuda_runtime.h>
#include <cuda_fp16.h>
#include <math.h>
#include <stdint.h>

// ---------------------------------------------------------------------------
// Problem constants
// ---------------------------------------------------------------------------
#define NB   4
#define C1   256
#define CM   128
#define C2   256
#define HW   4096
#define NPIX (NB*HW)
#define PP   9
#define BN_EPS 1e-5f
#define LN_EPS 1e-6f

typedef __half hlf;

// ---------------------------------------------------------------------------
// Scratch (offsets in floats)
// ---------------------------------------------------------------------------
#define OFF_XHI   0                          // NPIX*C1 fp16
#define OFF_Y1HI  (OFF_XHI  + NPIX*C1/2)     // NPIX*CM fp16 hi/lo
#define OFF_Y1LO  (OFF_Y1HI + NPIX*CM/2)
#define OFF_Y2HI  (OFF_Y1LO + NPIX*CM/2)     // NPIX*C2 fp16 hi/lo
#define OFF_Y2LO  (OFF_Y2HI + NPIX*C2/2)
#define OFF_X1HI  (OFF_Y2LO + NPIX*C2/2)
#define OFF_X1LO  (OFF_X1HI + NPIX*C2/2)
#define OFF_XPROJ (OFF_X1LO + NPIX*C2/2)     // fp16
#define OFF_OM    (OFF_XPROJ+ NPIX*C2/2)
#define OFF_CHI   (OFF_OM   + NPIX*27)       // fp16
#define OFF_ONH   (OFF_CHI  + NPIX*C2/2)     // f32
#define OFF_WT9H  (OFF_ONH  + NPIX*C2)       // 9*128*256 fp16 [tap][co][ci]
#define OFF_PWH   (OFF_WT9H + 9*CM*C1/2)
#define OFF_INH   (OFF_PWH  + C2*CM/2)
#define OFF_OUH   (OFF_INH  + C2*C2/2)
#define OFF_HWH   (OFF_OUH  + C2*C2/2)       // 32*256 fp16 head weights
#define OFF_HB    (OFF_HWH  + 32*C2/2)       // 32 f32 head bias
#define SCRATCH_FLOATS (OFF_HB + 32)

__device__ __align__(16) float g_scratch[SCRATCH_FLOATS];

__device__ __forceinline__ float silu(float v) { return v / (1.0f + expf(-v)); }

__device__ __forceinline__ void split_h(float v, hlf& h, hlf& l) {
    h = __float2half_rn(v);
    l = __float2half_rn(v - __half2float(h));
}
__device__ __forceinline__ uint32_t pack_pair(float a, float b, bool lo) {
    hlf ha, la, hb, lbv;
    split_h(a, ha, la); split_h(b, hb, lbv);
    if (!lo) return ((uint32_t)*(uint16_t*)&hb << 16) | *(uint16_t*)&ha;
    else     return ((uint32_t)*(uint16_t*)&lbv << 16) | *(uint16_t*)&la;
}
__device__ __forceinline__ uint32_t pack_h2(float a, float b) {
    hlf ha = __float2half_rn(a), hb = __float2half_rn(b);
    return ((uint32_t)*(uint16_t*)&hb << 16) | *(uint16_t*)&ha;
}

// ---------------------------------------------------------------------------
// mma.sync + ldmatrix + cp.async (portable sm_80 PTX)
// ---------------------------------------------------------------------------
__device__ __forceinline__ void mma16816(float* d, const uint32_t* a, const uint32_t* b) {
    asm volatile("mma.sync.aligned.m16n8k16.row.col.f32.f16.f16.f32 "
        "{%0,%1,%2,%3}, {%4,%5,%6,%7}, {%8,%9}, {%0,%1,%2,%3};"
        : "+f"(d[0]), "+f"(d[1]), "+f"(d[2]), "+f"(d[3])
        : "r"(a[0]), "r"(a[1]), "r"(a[2]), "r"(a[3]), "r"(b[0]), "r"(b[1]));
}
__device__ __forceinline__ void ldm4(uint32_t* r, uint32_t addr) {
    asm volatile("ldmatrix.sync.aligned.m8n8.x4.shared.b16 {%0,%1,%2,%3}, [%4];"
        : "=r"(r[0]), "=r"(r[1]), "=r"(r[2]), "=r"(r[3]) : "r"(addr));
}
__device__ __forceinline__ void cp16(uint32_t dst, const void* src) {
    asm volatile("cp.async.cg.shared.global [%0], [%1], 16;" :: "r"(dst), "l"(src));
}
__device__ __forceinline__ void cp16z(uint32_t dst, const void* src, int srcsize) {
    asm volatile("cp.async.cg.shared.global [%0], [%1], 16, %2;"
                 :: "r"(dst), "l"(src), "r"(srcsize));
}
#define CP_COMMIT() asm volatile("cp.async.commit_group;" ::: "memory")
#define CP_WAIT1()  asm volatile("cp.async.wait_group 1;" ::: "memory")

// SMEM row: 32 fp16 = 16 words, padded to 20 (conflict-free for ldmatrix)
#define TS 20
#define AW  (64 * TS)
#define BW  (128 * TS)
#define CONV_STW (AW + BW)
#define CONV_SMEM (2 * CONV_STW * 4)
#define GEMM_STW1 (AW + BW)
#define GEMM_STW2 (2*AW + BW)
#define GEMM_SMEM1 (2 * GEMM_STW1 * 4)
#define GEMM_SMEM2 (2 * GEMM_STW2 * 4)

// ---------------------------------------------------------------------------
// prep_x: NCHW f32 -> NHWC fp16
// ---------------------------------------------------------------------------
__global__ __launch_bounds__(256) void prep_x_k(
    const float* __restrict__ x, hlf* __restrict__ xhi)
{
    __shared__ float t[32][33];
    const int n = blockIdx.z, hw0 = blockIdx.x * 32, c0 = blockIdx.y * 32;
    const int tx = threadIdx.x & 31, ty = threadIdx.x >> 5;
#pragma unroll
    for (int i = ty; i < 32; i += 8)
        t[i][tx] = x[((size_t)n * C1 + c0 + i) * HW + hw0 + tx];
    __syncthreads();
#pragma unroll
    for (int i = ty; i < 32; i += 8) {
        size_t idx = ((size_t)n * HW + hw0 + i) * C1 + c0 + tx;
        xhi[idx] = __float2half_rn(t[tx][i]);
    }
}

// ---------------------------------------------------------------------------
// prep_w: all weights -> fp16; cv1 -> [tap][co][ci]; head pack
// ---------------------------------------------------------------------------
__global__ __launch_bounds__(256) void prep_w_k(
    const float* __restrict__ cv1w, const float* __restrict__ pww,
    const float* __restrict__ inpw, const float* __restrict__ outw,
    const float* __restrict__ offw, const float* __restrict__ mskw,
    const float* __restrict__ offb, const float* __restrict__ mskb,
    hlf* __restrict__ wt9h, hlf* __restrict__ pwh,
    hlf* __restrict__ inh,  hlf* __restrict__ ouh,
    hlf* __restrict__ hwh,  float* __restrict__ hb)
{
    int idx = blockIdx.x * 256 + threadIdx.x;
    const int N1 = 9 * CM * C1;
    if (idx < N1) {
        int tap = idx / (CM * C1);
        int rem = idx - tap * CM * C1;
        int co = rem >> 8, ci = rem & 255;
        wt9h[idx] = __float2half_rn(cv1w[(size_t)co * (C1 * 9) + ci * 9 + tap]);
        return;
    }
    idx -= N1;
    if (idx < C2 * CM) { pwh[idx] = __float2half_rn(pww[idx]); return; }
    idx -= C2 * CM;
    if (idx < C2 * C2) { inh[idx] = __float2half_rn(inpw[idx]); return; }
    idx -= C2 * C2;
    if (idx < C2 * C2) { ouh[idx] = __float2half_rn(outw[idx]); return; }
    idx -= C2 * C2;
    if (idx < 32 * C2) {
        int j = idx >> 8, k = idx & 255;
        float v = (j < 18) ? offw[j * C2 + k] : ((j < 27) ? mskw[(j - 18) * C2 + k] : 0.0f);
        hwh[idx] = __float2half_rn(v); return;
    }
    idx -= 32 * C2;
    if (idx < 32)
        hb[idx] = (idx < 18) ? offb[idx] : ((idx < 27) ? mskb[idx - 18] : 0.0f);
}

// ---------------------------------------------------------------------------
// Inner MMA via ldmatrix. A tile 64x32 (ATERMS arrays), B tile 128x32.
// ---------------------------------------------------------------------------
template<int ATERMS>
__device__ __forceinline__ void mma_step(
    uint32_t aHi, uint32_t aLo, uint32_t bHi,
    int wm, int wn, int lane, float acc[2][4][4])
{
    const int arow = (lane & 7) + ((lane >> 3) & 1) * 8;
    const int akt  = (lane >> 4) & 1;
    const int brow = (lane & 7) + ((lane >> 4) & 1) * 8;
    const int bkt  = (lane >> 3) & 1;
#pragma unroll
    for (int ks = 0; ks < 2; ks++) {
        uint32_t ahi[2][4], alo[2][4], bhi[2][4];
#pragma unroll
        for (int mt = 0; mt < 2; mt++) {
            uint32_t off = (uint32_t)(((wm * 32 + mt * 16 + arow) * TS + ks * 8 + akt * 4) * 4);
            ldm4(ahi[mt], aHi + off);
            if (ATERMS == 2) ldm4(alo[mt], aLo + off);
        }
#pragma unroll
        for (int np = 0; np < 2; np++) {
            uint32_t off = (uint32_t)(((wn * 32 + np * 16 + brow) * TS + ks * 8 + bkt * 4) * 4);
            ldm4(bhi[np], bHi + off);
        }
#pragma unroll
        for (int mt = 0; mt < 2; mt++)
#pragma unroll
            for (int nt = 0; nt < 4; nt++) {
                const uint32_t* bh = &bhi[nt >> 1][(nt & 1) * 2];
                mma16816(acc[mt][nt], ahi[mt], bh);
                if (ATERMS == 2) mma16816(acc[mt][nt], alo[mt], bh);
            }
    }
}

// ---------------------------------------------------------------------------
// mma_conv: cv1 3x3 (256->128) + BN + SiLU. 1-term pure fp16.
// ---------------------------------------------------------------------------
__global__ __launch_bounds__(256, 2) void mma_conv_k(
    const hlf* __restrict__ xhi, const hlf* __restrict__ wth,
    const float* __restrict__ g, const float* __restrict__ b,
    hlf* __restrict__ y1hi, hlf* __restrict__ y1lo)
{
    extern __shared__ __align__(16) uint32_t dsm[];
    const uint32_t sbase = (uint32_t)__cvta_generic_to_shared(dsm);

    const int tid = threadIdx.x, wid = tid >> 5, lane = tid & 31;
    const int wm = wid >> 2, wn = wid & 3, qr = lane >> 2, qc = lane & 3;
    const int pix0 = blockIdx.x * 64;
    const int n = pix0 >> 12, hb2 = (pix0 & 4095) >> 6;
    const int r0 = tid >> 2, ch0 = tid & 3;

    float acc[2][4][4];
#pragma unroll
    for (int mt = 0; mt < 2; mt++)
#pragma unroll
        for (int nt = 0; nt < 4; nt++)
#pragma unroll
            for (int q = 0; q < 4; q++) acc[mt][nt][q] = 0.0f;

    const int TOT = 72;
    auto stage = [&](int it) {
        const int tap = it / 8, kc = it & 7;
        const int dh = tap / 3 - 1, dw = tap % 3 - 1;
        const uint32_t sb = sbase + (uint32_t)(it & 1) * (CONV_STW * 4);
        {
            int hh = hb2 + dh, ww = r0 + dw;
            bool val = ((unsigned)hh < 64u) && ((unsigned)ww < 64u);
            size_t u4 = val ? ((size_t)(n * HW + hh * 64 + ww) * 32 + kc * 4 + ch0) : 0;
            int sz = val ? 16 : 0;
            uint32_t rowoff = (uint32_t)(r0 * TS + ch0 * 4) * 4;
            cp16z(sb + rowoff, (const char*)xhi + u4 * 16, sz);
        }
#pragma unroll
        for (int i = 0; i < 2; i++) {
            int r = r0 + i * 64;
            size_t w4 = (size_t)(tap * CM + r) * 32 + kc * 4 + ch0;
            uint32_t rowoff = (uint32_t)(r * TS + ch0 * 4) * 4;
            cp16(sb + AW * 4 + rowoff, (const char*)wth + w4 * 16);
        }
    };

    stage(0); CP_COMMIT();
    for (int it = 0; it < TOT; it++) {
        if (it + 1 < TOT) stage(it + 1);
        CP_COMMIT();
        CP_WAIT1();
        __syncthreads();
        uint32_t sb = sbase + (uint32_t)(it & 1) * (CONV_STW * 4);
        mma_step<1>(sb, 0, sb + AW * 4, wm, wn, lane, acc);
        __syncthreads();
    }

#pragma unroll
    for (int nt = 0; nt < 4; nt++) {
        int c = wn * 32 + nt * 8 + qc * 2;
        float s0 = g[c] * rsqrtf(1.0f + BN_EPS),     b0 = b[c];
        float s1 = g[c + 1] * rsqrtf(1.0f + BN_EPS), b1 = b[c + 1];
#pragma unroll
        for (int mt = 0; mt < 2; mt++) {
            int row = wm * 32 + mt * 16 + qr;
#pragma unroll
            for (int half = 0; half < 2; half++) {
                int pix = pix0 + row + half * 8;
                float v0 = silu(fmaf(acc[mt][nt][half * 2 + 0], s0, b0));
                float v1 = silu(fmaf(acc[mt][nt][half * 2 + 1], s1, b1));
                *(uint32_t*)&y1hi[(size_t)pix * CM + c] = pack_pair(v0, v1, false);
                *(uint32_t*)&y1lo[(size_t)pix * CM + c] = pack_pair(v0, v1, true);
            }
        }
    }
}

// ---------------------------------------------------------------------------
// mma_gemm: C[M,256] = A[M,K] @ Wfp16[256,K]^T.
// ATERMS=2: A = hi+lo.  ATERMS=1: A = fp16.
// MODE 0: BN+SiLU -> hi/lo fp16. MODE 1: +bias -> f32. MODE 2: +bias -> fp16.
// ---------------------------------------------------------------------------
template<int K, int MODE, int ATERMS>
__global__ __launch_bounds__(256, 2) void mma_gemm_k(
    const hlf* __restrict__ Ahi, const hlf* __restrict__ Alo,
    const hlf* __restrict__ Whi,
    const float* __restrict__ p0, const float* __restrict__ p1,
    float* __restrict__ outf, hlf* __restrict__ outhi, hlf* __restrict__ outlo)
{
    extern __shared__ __align__(16) uint32_t dsm[];
    const uint32_t sbase = (uint32_t)__cvta_generic_to_shared(dsm);
    constexpr int STW = ATERMS * AW + BW;

    const int tid = threadIdx.x, wid = tid >> 5, lane = tid & 31;
    const int wm = wid >> 2, wn = wid & 3, qr = lane >> 2, qc = lane & 3;
    const int pix0 = blockIdx.x * 64;
    const int nh = blockIdx.y;
    const int r0 = tid >> 2, ch0 = tid & 3;

    constexpr int TOT = K / 32;

    float acc[2][4][4];
#pragma unroll
    for (int mt = 0; mt < 2; mt++)
#pragma unroll
        for (int nt = 0; nt < 4; nt++)
#pragma unroll
            for (int q = 0; q < 4; q++) acc[mt][nt][q] = 0.0f;

    auto stage = [&](int it) {
        const int kc = it;
        const uint32_t sb = sbase + (uint32_t)(it & 1) * (STW * 4);
        {
            size_t a4 = (size_t)(pix0 + r0) * (K / 8) + kc * 4 + ch0;
            uint32_t rowoff = (uint32_t)(r0 * TS + ch0 * 4) * 4;
            cp16(sb + rowoff, (const char*)Ahi + a4 * 16);
            if (ATERMS == 2) cp16(sb + AW * 4 + rowoff, (const char*)Alo + a4 * 16);
        }
#pragma unroll
        for (int i = 0; i < 2; i++) {
            int r = r0 + i * 64;
            size_t b4 = (size_t)(nh * 128 + r) * (K / 8) + kc * 4 + ch0;
            uint32_t rowoff = (uint32_t)(r * TS + ch0 * 4) * 4;
            cp16(sb + ATERMS * AW * 4 + rowoff, (const char*)Whi + b4 * 16);
        }
    };

    stage(0); CP_COMMIT();
    for (int it = 0; it < TOT; it++) {
        if (it + 1 < TOT) stage(it + 1);
        CP_COMMIT();
        CP_WAIT1();
        __syncthreads();
        uint32_t sb = sbase + (uint32_t)(it & 1) * (STW * 4);
        mma_step<ATERMS>(sb, sb + AW * 4, sb + ATERMS * AW * 4, wm, wn, lane, acc);
        __syncthreads();
    }

#pragma unroll
    for (int nt = 0; nt < 4; nt++) {
        int c = nh * 128 + wn * 32 + nt * 8 + qc * 2;
        float s0, b0, s1, b1;
        if (MODE == 0) {
            s0 = p0[c] * rsqrtf(1.0f + BN_EPS);     b0 = p1[c];
            s1 = p0[c + 1] * rsqrtf(1.0f + BN_EPS); b1 = p1[c + 1];
        } else {
            b0 = p0[c]; b1 = p0[c + 1]; s0 = s1 = 1.0f;
        }
#pragma unroll
        for (int mt = 0; mt < 2; mt++) {
            int row = wm * 32 + mt * 16 + qr;
#pragma unroll
            for (int half = 0; half < 2; half++) {
                int pix = pix0 + row + half * 8;
                if (MODE == 0) {
                    float v0 = silu(fmaf(acc[mt][nt][half * 2 + 0], s0, b0));
                    float v1 = silu(fmaf(acc[mt][nt][half * 2 + 1], s1, b1));
                    *(uint32_t*)&outhi[(size_t)pix * C2 + c] = pack_pair(v0, v1, false);
                    *(uint32_t*)&outlo[(size_t)pix * C2 + c] = pack_pair(v0, v1, true);
                } else if (MODE == 1) {
                    float v0 = acc[mt][nt][half * 2 + 0] + b0;
                    float v1 = acc[mt][nt][half * 2 + 1] + b1;
                    *(float2*)&outf[(size_t)pix * C2 + c] = make_float2(v0, v1);
                } else {
                    float v0 = acc[mt][nt][half * 2 + 0] + b0;
                    float v1 = acc[mt][nt][half * 2 + 1] + b1;
                    *(uint32_t*)&outhi[(size_t)pix * C2 + c] = pack_h2(v0, v1);
                }
            }
        }
    }
}

// ---------------------------------------------------------------------------
// mma_head: om[M,27] = (x1hi+x1lo)[M,256] @ HW16[32,256]^T + hb (2-term).
// ---------------------------------------------------------------------------
#define BS2 132
#define HEAD_SMEM ((2*128*TS + 32*BS2) * 4)
__global__ __launch_bounds__(256) void mma_head_k(
    const hlf* __restrict__ x1hi, const hlf* __restrict__ x1lo,
    const hlf* __restrict__ hwh,
    const float* __restrict__ hb, float* __restrict__ om)
{
    extern __shared__ __align__(16) uint32_t dsm[];
    const uint32_t sbase = (uint32_t)__cvta_generic_to_shared(dsm);
    const uint32_t AHI = 0, ALO = 128 * TS, BHI = 2 * 128 * TS;

    const int tid = threadIdx.x, wid = tid >> 5, lane = tid & 31;
    const int pix0 = blockIdx.x * 128;

    for (int i = tid; i < 1024; i += 256) {
        int row = i >> 5, ch = i & 31;
        *(uint4*)&dsm[BHI + row * BS2 + ch * 4] = ((const uint4*)hwh)[row * 32 + ch];
    }

    float acc[4][4];
#pragma unroll
    for (int nt = 0; nt < 4; nt++)
#pragma unroll
        for (int q = 0; q < 4; q++) acc[nt][q] = 0.0f;

    const int arow = (lane & 7) + ((lane >> 3) & 1) * 8;
    const int akt  = (lane >> 4) & 1;
    const int brow = (lane & 7) + ((lane >> 4) & 1) * 8;
    const int bkt  = (lane >> 3) & 1;

    for (int kc = 0; kc < 8; kc++) {
        __syncthreads();
        for (int i = tid; i < 1024; i += 256) {
            int arr = i >> 9, j = i & 511;
            int row = j >> 2, ch = j & 3;
            const uint4 v = ((const uint4*)(arr ? x1lo : x1hi))[(size_t)(pix0 + row) * 32 + kc * 4 + ch];
            *(uint4*)&dsm[(arr ? ALO : AHI) + row * TS + ch * 4] = v;
        }
        __syncthreads();
#pragma unroll
        for (int ks = 0; ks < 2; ks++) {
            uint32_t ahi[4], alo[4], bhi[2][4];
            uint32_t aoff = (uint32_t)(((wid * 16 + arow) * TS + ks * 8 + akt * 4) * 4);
            ldm4(ahi, sbase + AHI * 4 + aoff);
            ldm4(alo, sbase + ALO * 4 + aoff);
#pragma unroll
            for (int np = 0; np < 2; np++) {
                uint32_t boff = (uint32_t)(((np * 16 + brow) * BS2 + kc * 16 + ks * 8 + bkt * 4) * 4);
                ldm4(bhi[np], sbase + BHI * 4 + boff);
            }
#pragma unroll
            for (int nt = 0; nt < 4; nt++) {
                const uint32_t* bh = &bhi[nt >> 1][(nt & 1) * 2];
                mma16816(acc[nt], ahi, bh);
                mma16816(acc[nt], alo, bh);
            }
        }
    }

#pragma unroll
    for (int nt = 0; nt < 4; nt++) {
        int c = nt * 8 + (lane & 3) * 2;
        int r0p = pix0 + wid * 16 + (lane >> 2);
#pragma unroll
        for (int half = 0; half < 2; half++) {
            int pix = r0p + half * 8;
            float v0 = acc[nt][half * 2 + 0] + hb[c];
            float v1 = acc[nt][half * 2 + 1] + hb[c + 1];
            if (c < 27)     om[(size_t)pix * 27 + c]     = v0;
            if (c + 1 < 27) om[(size_t)pix * 27 + c + 1] = v1;
        }
    }
}

// ---------------------------------------------------------------------------
// Fused: depthwise 3x3 (fp16 y2hi, half2) + LN + GELU -> x1 hi/lo
// 128 threads, 2 channels per thread.
// ---------------------------------------------------------------------------
__global__ __launch_bounds__(128) void dw_ln_gelu_k(
    const hlf* __restrict__ y2h,
    const float* __restrict__ dww, const float* __restrict__ dwb,
    const float* __restrict__ lg,  const float* __restrict__ lb,
    hlf* __restrict__ x1hi, hlf* __restrict__ x1lo)
{
    const int pix = blockIdx.x;
    const int n = pix >> 12, hw = pix & 4095, h = hw >> 6, w = hw & 63;
    const int t = threadIdx.x;
    const int c = t * 2;

    float v0 = dwb[c], v1 = dwb[c + 1];
#pragma unroll
    for (int kh = 0; kh < 3; kh++)
#pragma unroll
        for (int kw = 0; kw < 3; kw++) {
            int hh = h + kh - 1, wk = w + kw - 1;
            if ((unsigned)hh < 64u && (unsigned)wk < 64u) {
                __half2 y = *(const __half2*)&y2h[(((size_t)n * HW) + hh * 64 + wk) * C2 + c];
                float2 f = __half22float2(y);
                v0 = fmaf(f.x, dww[c * 9 + kh * 3 + kw], v0);
                v1 = fmaf(f.y, dww[(c + 1) * 9 + kh * 3 + kw], v1);
            }
        }

    __shared__ float s1[128];
    __shared__ float s2[128];
    s1[t] = v0 + v1; s2[t] = v0 * v0 + v1 * v1;
    __syncthreads();
    if (t < 64) { s1[t] += s1[t + 64]; s2[t] += s2[t + 64]; }
    __syncthreads();
    if (t < 32) {
        float a1 = s1[t] + s1[t + 32];
        float a2 = s2[t] + s2[t + 32];
#pragma unroll
        for (int o = 16; o > 0; o >>= 1) {
            a1 += __shfl_down_sync(0xffffffffu, a1, o);
            a2 += __shfl_down_sync(0xffffffffu, a2, o);
        }
        if (t == 0) { s1[0] = a1; s2[0] = a2; }
    }
    __syncthreads();
    float mean = s1[0] * (1.0f / 256.0f);
    float var  = s2[0] * (1.0f / 256.0f) - mean * mean;
    float rstd = rsqrtf(var + LN_EPS);

    float t0 = fmaf((v0 - mean) * rstd, lg[c],     lb[c]);
    float t1 = fmaf((v1 - mean) * rstd, lg[c + 1], lb[c + 1]);
    float g0 = 0.5f * t0 * (1.0f + erff(t0 * 0.70710678118654752f));
    float g1 = 0.5f * t1 * (1.0f + erff(t1 * 0.70710678118654752f));

    *(uint32_t*)&x1hi[(size_t)pix * C2 + c] = pack_pair(g0, g1, false);
    *(uint32_t*)&x1lo[(size_t)pix * C2 + c] = pack_pair(g0, g1, true);
}

// ---------------------------------------------------------------------------
// DCNv3 core (mask softmax in-kernel), fp16 xproj, half2 math.
// 128 threads, 2 channels per thread -> chi fp16.
// ---------------------------------------------------------------------------
__global__ __launch_bounds__(128) void dcnv3_k(
    const hlf* __restrict__ xproj, const float* __restrict__ om,
    hlf* __restrict__ chi)
{
    const int pix = blockIdx.x;
    const int n = pix >> 12, hw = pix & 4095, h = hw >> 6, w = hw & 63;
    const int t = threadIdx.x;
    const int c = t * 2;

    __shared__ float o[32];
    if (t < 27) o[t] = om[(size_t)pix * 27 + t];
    __syncthreads();
    if (t == 0) {
        float mx = -1e30f;
#pragma unroll
        for (int q = 0; q < 9; q++) mx = fmaxf(mx, o[18 + q]);
        float e[9], sum = 0.0f;
#pragma unroll
        for (int q = 0; q < 9; q++) { e[q] = expf(o[18 + q] - mx); sum += e[q]; }
        float inv = 1.0f / sum;
#pragma unroll
        for (int q = 0; q < 9; q++) o[18 + q] = e[q] * inv;
    }
    __syncthreads();

    const hlf* base = xproj + (size_t)n * HW * C2 + c;
    float a0 = 0.0f, a1 = 0.0f;

#pragma unroll
    for (int p = 0; p < PP; p++) {
        float px = (float)(w + (p / 3)) + o[2 * p];
        float py = (float)(h + (p % 3)) + o[2 * p + 1];
        float x0f = floorf(px), y0f = floorf(py);
        float fx = px - x0f, fy = py - y0f;
        int x0 = (int)x0f, y0 = (int)y0f;
        float mk = o[18 + p];
        float s0 = 0.0f, s1 = 0.0f;
#pragma unroll
        for (int dy = 0; dy < 2; dy++)
#pragma unroll
            for (int dx = 0; dx < 2; dx++) {
                int xi = x0 + dx, yi = y0 + dy;
                if (xi >= 1 && xi <= 64 && yi >= 1 && yi <= 64) {
                    float wgt = (dx ? fx : 1.0f - fx) * (dy ? fy : 1.0f - fy);
                    __half2 v = *(const __half2*)&base[((size_t)(yi - 1) * 64 + (xi - 1)) * C2];
                    float2 f = __half22float2(v);
                    s0 = fmaf(wgt, f.x, s0);
                    s1 = fmaf(wgt, f.y, s1);
                }
            }
        a0 = fmaf(mk, s0, a0);
        a1 = fmaf(mk, s1, a1);
    }
    *(uint32_t*)&chi[(size_t)pix * C2 + c] = pack_h2(a0, a1);
}

// ---------------------------------------------------------------------------
// NHWC->NCHW + BN2 + SiLU + residual
// ---------------------------------------------------------------------------
__global__ __launch_bounds__(256) void bn2_res_transpose_k(
    const float* __restrict__ o, const float* __restrict__ xres,
    const float* __restrict__ g, const float* __restrict__ b,
    float* __restrict__ out)
{
    __shared__ float t[32][33];
    const int n = blockIdx.z, hw0 = blockIdx.x * 32, c0 = blockIdx.y * 32;
    const int tx = threadIdx.x & 31, ty = threadIdx.x >> 5;
#pragma unroll
    for (int i = ty; i < 32; i += 8)
        t[i][tx] = o[((size_t)n * HW + hw0 + i) * C2 + c0 + tx];
    __syncthreads();
#pragma unroll
    for (int i = ty; i < 32; i += 8) {
        int c = c0 + i, hw = hw0 + tx;
        float v = t[tx][i];
        float s = g[c] * rsqrtf(1.0f + BN_EPS);
        v = silu(fmaf(v, s, b[c]));
        size_t idx = ((size_t)n * C2 + c) * HW + hw;
        out[idx] = xres[idx] + v;
    }
}

// ---------------------------------------------------------------------------
// Launch
// ---------------------------------------------------------------------------
extern "C" void kernel_launch(void* const* d_in, const int* in_sizes, int n_in,
                              void* d_out, int out_size) {
    const float* x     = (const float*)d_in[0];
    const float* cv1_w = (const float*)d_in[1];
    const float* cv1_g = (const float*)d_in[2];
    const float* cv1_b = (const float*)d_in[3];
    const float* pw_w  = (const float*)d_in[4];
    const float* pw_g  = (const float*)d_in[5];
    const float* pw_b  = (const float*)d_in[6];
    const float* dw_w  = (const float*)d_in[7];
    const float* dw_b  = (const float*)d_in[8];
    const float* ln_g  = (const float*)d_in[9];
    const float* ln_b  = (const float*)d_in[10];
    const float* off_w = (const float*)d_in[11];
    const float* off_b = (const float*)d_in[12];
    const float* msk_w = (const float*)d_in[13];
    const float* msk_b = (const float*)d_in[14];
    const float* inp_w = (const float*)d_in[15];
    const float* inp_b = (const float*)d_in[16];
    const float* out_w = (const float*)d_in[17];
    const float* out_b = (const float*)d_in[18];
    const float* bn2_g = (const float*)d_in[19];
    const float* bn2_b = (const float*)d_in[20];

    float* sc = nullptr;
    cudaGetSymbolAddress((void**)&sc, g_scratch);
    hlf* xhi  = (hlf*)(sc + OFF_XHI);
    hlf* y1hi = (hlf*)(sc + OFF_Y1HI);
    hlf* y1lo = (hlf*)(sc + OFF_Y1LO);
    hlf* y2hi = (hlf*)(sc + OFF_Y2HI);
    hlf* y2lo = (hlf*)(sc + OFF_Y2LO);
    hlf* x1hi = (hlf*)(sc + OFF_X1HI);
    hlf* x1lo = (hlf*)(sc + OFF_X1LO);
    hlf* xprojh = (hlf*)(sc + OFF_XPROJ);
    float* om    = sc + OFF_OM;
    hlf* chi  = (hlf*)(sc + OFF_CHI);
    float* onh = sc + OFF_ONH;
    hlf* wt9h = (hlf*)(sc + OFF_WT9H);
    hlf* pwh  = (hlf*)(sc + OFF_PWH);
    hlf* inh  = (hlf*)(sc + OFF_INH);
    hlf* ouh  = (hlf*)(sc + OFF_OUH);
    hlf* hwh  = (hlf*)(sc + OFF_HWH);
    float* hb = sc + OFF_HB;
    float* outp = (float*)d_out;

    cudaFuncSetAttribute(mma_conv_k, cudaFuncAttributeMaxDynamicSharedMemorySize, CONV_SMEM);
    cudaFuncSetAttribute(mma_gemm_k<128, 0, 2>, cudaFuncAttributeMaxDynamicSharedMemorySize, GEMM_SMEM2);
    cudaFuncSetAttribute(mma_gemm_k<256, 2, 1>, cudaFuncAttributeMaxDynamicSharedMemorySize, GEMM_SMEM1);
    cudaFuncSetAttribute(mma_gemm_k<256, 1, 1>, cudaFuncAttributeMaxDynamicSharedMemorySize, GEMM_SMEM1);
    cudaFuncSetAttribute(mma_head_k, cudaFuncAttributeMaxDynamicSharedMemorySize, HEAD_SMEM);

    // 0) preprocessing
    prep_x_k<<<dim3(HW / 32, C1 / 32, NB), 256>>>(x, xhi);
    int prep_tot = 9 * CM * C1 + C2 * CM + 2 * C2 * C2 + 32 * C2 + 32;
    prep_w_k<<<(prep_tot + 255) / 256, 256>>>(
        cv1_w, pw_w, inp_w, out_w, off_w, msk_w, off_b, msk_b,
        wt9h, pwh, inh, ouh, hwh, hb);

    // 1) cv1 (1-term fp16) -> y1 hi/lo
    mma_conv_k<<<NPIX / 64, 256, CONV_SMEM>>>(
        xhi, wt9h, cv1_g, cv1_b, y1hi, y1lo);

    // 2) pw (2-term) -> y2 hi/lo
    mma_gemm_k<128, 0, 2><<<dim3(NPIX / 64, 2), 256, GEMM_SMEM2>>>(
        y1hi, y1lo, pwh, pw_g, pw_b, nullptr, y2hi, y2lo);

    // 3) dw (half2) + LN + GELU -> x1 hi/lo
    dw_ln_gelu_k<<<NPIX, 128>>>(y2hi, dw_w, dw_b, ln_g, ln_b, x1hi, x1lo);

    // 4) offset/mask heads -> om (logits)
    mma_head_k<<<NPIX / 128, 256, HEAD_SMEM>>>(x1hi, x1lo, hwh, hb, om);

    // 5) input_proj (1-term) -> xproj fp16
    mma_gemm_k<256, 2, 1><<<dim3(NPIX / 64, 2), 256, GEMM_SMEM1>>>(
        y2hi, nullptr, inh, inp_b, nullptr, nullptr, xprojh, nullptr);

    // 6) DCNv3 core (half2, softmax inside) -> chi fp16
    dcnv3_k<<<NPIX, 128>>>(xprojh, om, chi);

    // 7) output_proj (1-term) -> onh f32
    mma_gemm_k<256, 1, 1><<<dim3(NPIX / 64, 2), 256, GEMM_SMEM1>>>(
        chi, nullptr, ouh, out_b, nullptr, onh, nullptr, nullptr);

    // 8) BN2 + SiLU + residual + transpose -> d_out
    bn2_res_transpose_k<<<dim3(HW / 32, C2 / 32, NB), 256>>>(onh, x, bn2_g, bn2_b, outp);
}